// round 12
// baseline (speedup 1.0000x reference)
#include <cuda_runtime.h>
#include <cuda_fp16.h>
#include <cstdint>
#include <math.h>

// ---------------- problem dims ----------------
#define B    64
#define PL   128
#define RL   64
#define TDEC 63
#define NT   50
#define NP   20
#define TE   100
#define HID  100
#define GH   512
#define G3   1536
#define G4   2048        // 4 gate-row groups for combined decoder GEMM
#define DE   300
#define VW   32000
#define KE   500
#define KD   1612        // logits input dim [hn,dg,tv,rv]
#define KC   1524        // combined decoder GEMM K = 1012 (cv,dg,tv) + 512 (h)
#define NEGV -1000000000.0f
#define NCH  5           // tv n-chunks (10 triples each)

// ---- fp16 2-term split vocab GEMM: A=[ah|al] (KPA), B=[bh] (KW, deduped) ----
#define KSEG 1612
#define KW   1632        // unique K (1612 padded to 32)
#define KPA  3264        // A row: [ah(1632) | al(1632)]
#define MP   4096
#define SSTRIDE 40       // smem row stride in fp16 (32 data + 8 pad)
#define VTM  256
#define VTN  128
#define VA_HALF (256*SSTRIDE*2)           // 20480 per A half
#define VB_SZ   (128*SSTRIDE*2)           // 10240
#define VSTAGE  (2*VA_HALF + VB_SZ)       // 51200
#define VSMEM   (3*VSTAGE)                // 153600

// ---------------- scratch ----------------
constexpr size_t SZ_TEF = (size_t)B*NT*NP*300;
constexpr size_t SZ_SL  = (size_t)B*NT*NP;
constexpr size_t SZ_SG  = (size_t)B*NT*200;
constexpr size_t SZ_UBG = (size_t)B*NT*100;
constexpr size_t SZ_PIN = (size_t)B*PL*KE;
constexpr size_t SZ_GXE = (size_t)B*PL*G3;
constexpr size_t SZ_PO  = (size_t)B*PL*GH;
constexpr size_t SZ_H   = (size_t)B*GH;
constexpr size_t SZ_RV  = (size_t)TDEC*B*600;
constexpr size_t SZ_Z   = (size_t)TDEC*B*KD;
constexpr size_t SZ_DIN2= (size_t)B*KC;
constexpr size_t SZ_Q   = (size_t)B*300;
constexpr size_t SZ_DA  = (size_t)B*NT;
constexpr size_t SZ_CP  = (size_t)8*B*G4;
constexpr size_t SZ_GHP = (size_t)4*B*G3;      // one ghp buffer
constexpr size_t SZ_GXRV= (size_t)TDEC*B*G3;
constexpr size_t SZ_WCB = (size_t)G4*KC;
constexpr size_t SZ_WRV = (size_t)G3*600;
constexpr size_t SZ_TVP = (size_t)TDEC*B*NCH*300;   // per-step tv partials

constexpr size_t OFF_TEF = 0;
constexpr size_t OFF_SL  = OFF_TEF + SZ_TEF;
constexpr size_t OFF_SG  = OFF_SL  + SZ_SL;
constexpr size_t OFF_UBG = OFF_SG  + SZ_SG;
constexpr size_t OFF_PIN = OFF_UBG + SZ_UBG;
constexpr size_t OFF_GXE = OFF_PIN + SZ_PIN;
constexpr size_t OFF_PO  = OFF_GXE + SZ_GXE;
constexpr size_t OFF_HA  = OFF_PO  + SZ_PO;
constexpr size_t OFF_HB  = OFF_HA  + SZ_H;
constexpr size_t OFF_RV  = OFF_HB  + SZ_H;
constexpr size_t OFF_Z   = OFF_RV  + SZ_RV;
constexpr size_t OFF_DIN2= OFF_Z   + SZ_Z;
constexpr size_t OFF_Q   = OFF_DIN2+ SZ_DIN2;
constexpr size_t OFF_DA  = OFF_Q   + SZ_Q;
constexpr size_t OFF_CP  = OFF_DA  + SZ_DA;
constexpr size_t OFF_GHPA= OFF_CP  + SZ_CP;
constexpr size_t OFF_GHPB= OFF_GHPA+ SZ_GHP;
constexpr size_t OFF_GXRV= OFF_GHPB+ SZ_GHP;
constexpr size_t OFF_WCB = OFF_GXRV+ SZ_GXRV;
constexpr size_t OFF_WRV = OFF_WCB + SZ_WCB;
constexpr size_t OFF_TVP = OFF_WRV + SZ_WRV;
constexpr size_t SZ_TOTAL = OFF_TVP + SZ_TVP;

__device__ float g_buf[SZ_TOTAL];
__device__ __align__(16) __half g_Ws[(size_t)VW * KW];
__device__ __align__(16) __half g_As[(size_t)MP * KPA];
__device__ __align__(16) __half g_tef16[SZ_TEF];

__device__ __forceinline__ float sigmoidf_(float x) { return 1.0f / (1.0f + expf(-x)); }
__device__ __forceinline__ uint32_t smem_u32(const void* p) {
    uint32_t a;
    asm("{ .reg .u64 t; cvta.to.shared.u64 t, %1; cvt.u32.u64 %0, t; }" : "=r"(a) : "l"(p));
    return a;
}

// ---------------- small utility kernels ----------------
__global__ void k_zero(float* p, size_t n) {
    size_t i = (size_t)blockIdx.x*blockDim.x + threadIdx.x;
    if (i < n) p[i] = 0.f;
}

__global__ void k_gather_tef(const float* __restrict__ te, const int* __restrict__ triple,
                             float* __restrict__ tef, __half* __restrict__ tef16) {
    size_t i = (size_t)blockIdx.x*blockDim.x + threadIdx.x;
    size_t total = (size_t)B*NT*NP*3*25;
    if (i >= total) return;
    size_t ent = i / 25; int off = (int)(i % 25) * 4;
    size_t tri = ent / 3; int e = (int)(ent % 3);
    int idx = triple[ent];
    float4 v = *reinterpret_cast<const float4*>(te + (size_t)idx*TE + off);
    size_t dst = tri*300 + e*100 + off;
    *reinterpret_cast<float4*>(tef + dst) = v;
    __half h4[4];
    h4[0] = __float2half(v.x); h4[1] = __float2half(v.y);
    h4[2] = __float2half(v.z); h4[3] = __float2half(v.w);
    *reinterpret_cast<uint2*>(tef16 + dst) = *reinterpret_cast<uint2*>(h4);
}

__global__ void k_gather_rv(const float* __restrict__ we, const float* __restrict__ te,
                            const int* __restrict__ resp, const int* __restrict__ rtrip,
                            float* __restrict__ rv, float* __restrict__ Z) {
    size_t i = (size_t)blockIdx.x*blockDim.x + threadIdx.x;
    size_t total = (size_t)TDEC*B*150;
    if (i >= total) return;
    size_t tb = i / 150; int f = (int)(i % 150);
    int t = (int)(tb / B), b = (int)(tb % B);
    float4 v;
    if (f < 75) {
        int w = resp[b*RL + t];
        v = *reinterpret_cast<const float4*>(we + (size_t)w*DE + f*4);
    } else {
        int f2 = f - 75; int e = f2 / 25; int off = (f2 % 25) * 4;
        int idx = rtrip[((size_t)b*RL + t)*3 + e];
        v = *reinterpret_cast<const float4*>(te + (size_t)idx*TE + off);
    }
    *reinterpret_cast<float4*>(rv + tb*600 + f*4) = v;
    *reinterpret_cast<float4*>(Z + tb*KD + 1012 + f*4) = v;
}

__global__ void k_triple_score(const float* __restrict__ tef, const int* __restrict__ triple,
                               const float* __restrict__ wh_w, const float* __restrict__ wh_b,
                               const float* __restrict__ wr_w, const float* __restrict__ wr_b,
                               const float* __restrict__ wt_w, const float* __restrict__ wt_b,
                               float* __restrict__ sl) {
    int g = blockIdx.x;
    const float* tb = tef + (size_t)g*300;
    __shared__ float e[300];
    __shared__ float red[128];
    int tid = threadIdx.x;
    for (int i = tid; i < 300; i += 128) e[i] = tb[i];
    __syncthreads();
    float contrib = 0.f;
    if (tid < HID) {
        int j = tid;
        float a = wh_b[j] + wt_b[j];
        float r = wr_b[j];
        const float* whr = wh_w + (size_t)j*TE;
        const float* wtr = wt_w + (size_t)j*TE;
        const float* wrr = wr_w + (size_t)j*TE;
        #pragma unroll 4
        for (int k = 0; k < TE; k++) {
            a += e[k]*whr[k] + e[200+k]*wtr[k];
            r += e[100+k]*wrr[k];
        }
        contrib = r * tanhf(a);
    }
    red[tid] = contrib; __syncthreads();
    for (int s = 64; s; s >>= 1) { if (tid < s) red[tid] += red[tid+s]; __syncthreads(); }
    if (tid == 0)
        sl[g] = (triple[(size_t)g*3] == 0) ? NEGV : red[0];
}

__global__ void k_graph_softmax(const float* __restrict__ sl, const float* __restrict__ tef,
                                float* __restrict__ sg) {
    int g = blockIdx.x;
    int tid = threadIdx.x;
    __shared__ float sa[NP];
    if (tid == 0) {
        float m = -1e30f;
        for (int p = 0; p < NP; p++) m = fmaxf(m, sl[(size_t)g*NP + p]);
        float sum = 0.f;
        for (int p = 0; p < NP; p++) { float ev = expf(sl[(size_t)g*NP + p] - m); sa[p] = ev; sum += ev; }
        float inv = 1.f / sum;
        for (int p = 0; p < NP; p++) sa[p] *= inv;
    }
    __syncthreads();
    const float* tb = tef + (size_t)g*NP*300;
    for (int d = tid; d < 200; d += 64) {
        int dd = (d < 100) ? d : d + 100;
        float s = 0.f;
        #pragma unroll
        for (int p = 0; p < NP; p++) s += sa[p]*tb[(size_t)p*300 + dd];
        sg[(size_t)g*200 + d] = s;
    }
}

__global__ void k_ubg(const float* __restrict__ sg, const float* __restrict__ ub_w,
                      const float* __restrict__ ub_b, float* __restrict__ ubg) {
    int g = blockIdx.x;
    int tid = threadIdx.x;
    __shared__ float s[200];
    for (int i = tid; i < 200; i += 128) s[i] = sg[(size_t)g*200 + i];
    __syncthreads();
    if (tid < HID) {
        float acc = ub_b[tid];
        const float* w = ub_w + (size_t)tid*200;
        #pragma unroll 4
        for (int k = 0; k < 200; k++) acc += s[k]*w[k];
        ubg[(size_t)g*HID + tid] = acc;
    }
}

__global__ void k_post_in(const float* __restrict__ we, const float* __restrict__ sg,
                          const int* __restrict__ post, const int* __restrict__ ptrip,
                          float* __restrict__ pin) {
    size_t i = (size_t)blockIdx.x*blockDim.x + threadIdx.x;
    size_t total = (size_t)B*PL*125;
    if (i >= total) return;
    size_t bt = i / 125; int f = (int)(i % 125);
    float4 v;
    if (f < 75) {
        v = *reinterpret_cast<const float4*>(we + (size_t)post[bt]*DE + f*4);
    } else {
        int b = (int)(bt / PL);
        int n = ptrip[bt];
        v = *reinterpret_cast<const float4*>(sg + ((size_t)b*NT + n)*200 + (f-75)*4);
    }
    *reinterpret_cast<float4*>(pin + bt*KE + f*4) = v;
}

__global__ void k_build_wcomb(const float* __restrict__ Wih, const float* __restrict__ Whh,
                              float* __restrict__ Wc) {
    size_t i = (size_t)blockIdx.x*blockDim.x + threadIdx.x;
    if (i >= (size_t)G4*KC) return;
    int c = (int)(i % KC);
    int r = (int)(i / KC);
    float v = 0.f;
    if (r < 1024) {
        v = (c < 1012) ? Wih[(size_t)r*KD + c] : Whh[(size_t)r*GH + (c - 1012)];
    } else if (r < 1536) {
        if (c < 1012) v = Wih[(size_t)r*KD + c];
    } else {
        if (c >= 1012) v = Whh[(size_t)(r - 512)*GH + (c - 1012)];
    }
    Wc[i] = v;
}

__global__ void k_build_wrv(const float* __restrict__ Wih, float* __restrict__ Wrv) {
    size_t i = (size_t)blockIdx.x*blockDim.x + threadIdx.x;
    if (i >= (size_t)G3*600) return;
    int c = (int)(i % 600);
    int r = (int)(i / 600);
    Wrv[i] = Wih[(size_t)r*KD + 1012 + c];
}

__global__ void k_h2din2(const float* __restrict__ h, float* __restrict__ din2) {
    int i = blockIdx.x*blockDim.x + threadIdx.x;
    if (i >= B*GH) return;
    int b = i / GH, j = i % GH;
    din2[(size_t)b*KC + 1012 + j] = h[i];
}

// ---------------- fp32 tiled GEMM (batch prep) ----------------
__global__ void gemm_bias(const float* __restrict__ A, const float* __restrict__ W,
                          const float* __restrict__ bias, float* __restrict__ C,
                          int M, int N, int K) {
    __shared__ float As[16][64];
    __shared__ float Ws[16][64];
    int bm = blockIdx.x * 64, bn = blockIdx.y * 64;
    int tid = threadIdx.x;
    int tx = tid & 15, ty = tid >> 4;
    float acc[4][4] = {};
    int r  = tid >> 2;
    int kk = (tid & 3) * 4;
    for (int k0 = 0; k0 < K; k0 += 16) {
        int gk = k0 + kk;
        float4 va = make_float4(0,0,0,0);
        int gm = bm + r;
        if (gm < M) {
            if (gk + 3 < K) va = *reinterpret_cast<const float4*>(A + (size_t)gm*K + gk);
            else { float t0=0,t1=0,t2=0,t3=0;
                   if (gk+0<K) t0=A[(size_t)gm*K+gk+0]; if (gk+1<K) t1=A[(size_t)gm*K+gk+1];
                   if (gk+2<K) t2=A[(size_t)gm*K+gk+2]; if (gk+3<K) t3=A[(size_t)gm*K+gk+3];
                   va = make_float4(t0,t1,t2,t3); }
        }
        As[kk+0][r]=va.x; As[kk+1][r]=va.y; As[kk+2][r]=va.z; As[kk+3][r]=va.w;
        float4 vw = make_float4(0,0,0,0);
        int gn = bn + r;
        if (gn < N) {
            if (gk + 3 < K) vw = *reinterpret_cast<const float4*>(W + (size_t)gn*K + gk);
            else { float t0=0,t1=0,t2=0,t3=0;
                   if (gk+0<K) t0=W[(size_t)gn*K+gk+0]; if (gk+1<K) t1=W[(size_t)gn*K+gk+1];
                   if (gk+2<K) t2=W[(size_t)gn*K+gk+2]; if (gk+3<K) t3=W[(size_t)gn*K+gk+3];
                   vw = make_float4(t0,t1,t2,t3); }
        }
        Ws[kk+0][r]=vw.x; Ws[kk+1][r]=vw.y; Ws[kk+2][r]=vw.z; Ws[kk+3][r]=vw.w;
        __syncthreads();
        #pragma unroll
        for (int k = 0; k < 16; k++) {
            float4 a = *reinterpret_cast<const float4*>(&As[k][ty*4]);
            float4 b = *reinterpret_cast<const float4*>(&Ws[k][tx*4]);
            acc[0][0]+=a.x*b.x; acc[0][1]+=a.x*b.y; acc[0][2]+=a.x*b.z; acc[0][3]+=a.x*b.w;
            acc[1][0]+=a.y*b.x; acc[1][1]+=a.y*b.y; acc[1][2]+=a.y*b.z; acc[1][3]+=a.y*b.w;
            acc[2][0]+=a.z*b.x; acc[2][1]+=a.z*b.y; acc[2][2]+=a.z*b.z; acc[2][3]+=a.z*b.w;
            acc[3][0]+=a.w*b.x; acc[3][1]+=a.w*b.y; acc[3][2]+=a.w*b.z; acc[3][3]+=a.w*b.w;
        }
        __syncthreads();
    }
    #pragma unroll
    for (int i = 0; i < 4; i++) {
        int gm = bm + ty*4 + i; if (gm >= M) continue;
        #pragma unroll
        for (int j = 0; j < 4; j++) {
            int gn = bn + tx*4 + j; if (gn >= N) continue;
            C[(size_t)gm*N + gn] = acc[i][j] + (bias ? bias[gn] : 0.f);
        }
    }
}

// ---------------- fused encoder step: prev gates (per-slice) + split-K gh GEMM -----
// grid (24 bn, 4 z), 256 thr. Each block recomputes h_t for its K-slice into smem.
__global__ void __launch_bounds__(256) enc_step(
        const float* __restrict__ hin, float* __restrict__ hout,
        const float* __restrict__ ghpIn, float* __restrict__ ghpOut,
        const float* __restrict__ Whh, const float* __restrict__ gxe,
        const float* __restrict__ bhh, float* __restrict__ po,
        const int* __restrict__ post_length, int t) {
    __shared__ float Hs[64*128];
    __shared__ float As[16][64];
    __shared__ float Ws[16][64];
    int z = blockIdx.y;
    int bn = blockIdx.x * 64;
    int tid = threadIdx.x;
    int ks = z * 128;
    if (t > 0) {
        for (int idx = tid; idx < 64*128; idx += 256) {
            int b = idx >> 7, jl = idx & 127;
            int j = ks + jl;
            float ghr = bhh[j], ghz = bhh[GH+j], ghn = bhh[2*GH+j];
            #pragma unroll
            for (int s = 0; s < 4; s++) {
                const float* p = ghpIn + ((size_t)s*B + b)*G3;
                ghr += p[j]; ghz += p[GH+j]; ghn += p[2*GH+j];
            }
            const float* gx = gxe + ((size_t)b*PL + (t-1))*G3;
            float r  = sigmoidf_(gx[j] + ghr);
            float zz = sigmoidf_(gx[GH+j] + ghz);
            float n  = tanhf(gx[2*GH+j] + r*ghn);
            float hold = hin[(size_t)b*GH + j];
            float hn = (1.f - zz)*n + zz*hold;
            bool valid = (t-1) < post_length[b];
            float hv = valid ? hn : hold;
            Hs[idx] = hv;
            if (blockIdx.x == 0) {
                hout[(size_t)b*GH + j] = hv;
                po[((size_t)b*PL + (t-1))*GH + j] = valid ? hn : 0.f;
            }
        }
    } else {
        for (int idx = tid; idx < 64*128; idx += 256) {
            int b = idx >> 7, jl = idx & 127;
            Hs[idx] = hin[(size_t)b*GH + ks + jl];
        }
    }
    __syncthreads();
    int tx = tid & 15, ty = tid >> 4;
    float acc[4][4] = {};
    int r = tid >> 2;
    int kk = (tid & 3) * 4;
    for (int k0 = 0; k0 < 128; k0 += 16) {
        {
            float4 va = *reinterpret_cast<const float4*>(&Hs[r*128 + k0 + kk]);
            As[kk+0][r]=va.x; As[kk+1][r]=va.y; As[kk+2][r]=va.z; As[kk+3][r]=va.w;
        }
        {
            float4 vw = *reinterpret_cast<const float4*>(Whh + (size_t)(bn + r)*GH + ks + k0 + kk);
            Ws[kk+0][r]=vw.x; Ws[kk+1][r]=vw.y; Ws[kk+2][r]=vw.z; Ws[kk+3][r]=vw.w;
        }
        __syncthreads();
        #pragma unroll
        for (int k = 0; k < 16; k++) {
            float4 a = *reinterpret_cast<const float4*>(&As[k][ty*4]);
            float4 b = *reinterpret_cast<const float4*>(&Ws[k][tx*4]);
            acc[0][0]+=a.x*b.x; acc[0][1]+=a.x*b.y; acc[0][2]+=a.x*b.z; acc[0][3]+=a.x*b.w;
            acc[1][0]+=a.y*b.x; acc[1][1]+=a.y*b.y; acc[1][2]+=a.y*b.z; acc[1][3]+=a.y*b.w;
            acc[2][0]+=a.z*b.x; acc[2][1]+=a.z*b.y; acc[2][2]+=a.z*b.z; acc[2][3]+=a.z*b.w;
            acc[3][0]+=a.w*b.x; acc[3][1]+=a.w*b.y; acc[3][2]+=a.w*b.z; acc[3][3]+=a.w*b.w;
        }
        __syncthreads();
    }
    float* Cz = ghpOut + (size_t)z*B*G3;
    #pragma unroll
    for (int i = 0; i < 4; i++) {
        int gm = ty*4 + i;
        #pragma unroll
        for (int j2 = 0; j2 < 4; j2++) {
            int gn = bn + tx*4 + j2;
            Cz[(size_t)gm*G3 + gn] = acc[i][j2];
        }
    }
}

// final encoder gates (step PL-1)
__global__ void enc_gates(const float* __restrict__ gxe, const float* __restrict__ ghp,
                          const float* __restrict__ bhh, float* __restrict__ h,
                          float* __restrict__ po, const int* __restrict__ post_length, int t) {
    int idx = blockIdx.x*blockDim.x + threadIdx.x;
    if (idx >= B*GH) return;
    int b = idx / GH, j = idx % GH;
    const float* gx = gxe + ((size_t)b*PL + t)*G3;
    float ghr = bhh[j], ghz = bhh[GH+j], ghn = bhh[2*GH+j];
    #pragma unroll
    for (int s = 0; s < 4; s++) {
        const float* p = ghp + ((size_t)s*B + b)*G3;
        ghr += p[j]; ghz += p[GH+j]; ghn += p[2*GH+j];
    }
    float r = sigmoidf_(gx[j] + ghr);
    float z = sigmoidf_(gx[GH+j] + ghz);
    float n = tanhf(gx[2*GH+j] + r*ghn);
    float hold = h[idx];
    float hn = (1.f - z)*n + z*hold;
    bool valid = t < post_length[b];
    h[idx] = valid ? hn : hold;
    po[((size_t)b*PL + t)*GH + j] = valid ? hn : 0.f;
}

// ---------------- decoder: prev-gates + attention + misc (one block per b) ---------
__global__ void __launch_bounds__(256) dec_am(
        float* __restrict__ din2, const float* __restrict__ po,
        const float* __restrict__ cp, const float* __restrict__ gxrv_prev,
        const float* __restrict__ bhh,
        const float* __restrict__ wb_w, const float* __restrict__ wb_b,
        const float* __restrict__ wc_w, const float* __restrict__ wc_b,
        const float* __restrict__ vb_w, const float* __restrict__ vb_b,
        const float* __restrict__ ubg, const float* __restrict__ sg,
        float* __restrict__ q, float* __restrict__ da,
        float* __restrict__ Z, int t, int do_gates) {
    int b = blockIdx.x, tid = threadIdx.x;
    int lane = tid & 31, wid = tid >> 5;
    __shared__ float hs[GH];
    __shared__ float sc2[256];
    __shared__ float sc[PL];
    __shared__ float al[PL];
    __shared__ float wbh[HID];
    __shared__ float dls[NT];
    __shared__ float das[NT];
    if (do_gates) {
        #pragma unroll
        for (int jj = 0; jj < 2; jj++) {
            int j = jj*256 + tid;
            float cr = 0.f, cz = 0.f, cxn = 0.f, chn = 0.f;
            #pragma unroll
            for (int z = 0; z < 8; z++) {
                const float* p = cp + ((size_t)z*B + b)*G4;
                cr += p[j]; cz += p[512+j]; cxn += p[1024+j]; chn += p[1536+j];
            }
            const float* gr = gxrv_prev + (size_t)b*G3;
            float r  = sigmoidf_(cr + gr[j] + bhh[j]);
            float zz = sigmoidf_(cz + gr[GH+j] + bhh[GH+j]);
            float n  = tanhf(cxn + gr[2*GH+j] + r*(chn + bhh[2*GH+j]));
            float hold = din2[(size_t)b*KC + 1012 + j];
            float hn = (1.f - zz)*n + zz*hold;
            din2[(size_t)b*KC + 1012 + j] = hn;
            Z[((size_t)(t-1)*B + b)*KD + j] = hn;
            hs[j] = hn;
        }
        __syncthreads();
    } else {
        for (int i = tid; i < GH; i += 256) hs[i] = din2[(size_t)b*KC + 1012 + i];
        __syncthreads();
    }
    {
        int p = tid >> 1, hf = tid & 1;
        const float* row = po + ((size_t)b*PL + p)*GH + hf*256;
        const float* h2 = hs + hf*256;
        float s = 0.f;
        for (int k = 0; k < 256; k += 4) {
            float4 v = *reinterpret_cast<const float4*>(row + k);
            s += v.x*h2[k] + v.y*h2[k+1] + v.z*h2[k+2] + v.w*h2[k+3];
        }
        sc2[tid] = s;
    }
    __syncthreads();
    if (tid < PL) sc[tid] = sc2[2*tid] + sc2[2*tid+1];
    __syncthreads();
    for (int j = tid; j < 400; j += 256) {
        const float* w;
        float acc;
        if (j < 300) { acc = wc_b[j]; w = wc_w + (size_t)j*GH; }
        else         { acc = wb_b[j-300]; w = wb_w + (size_t)(j-300)*GH; }
        for (int k = 0; k < GH; k += 4) {
            float4 v = *reinterpret_cast<const float4*>(w + k);
            acc += v.x*hs[k] + v.y*hs[k+1] + v.z*hs[k+2] + v.w*hs[k+3];
        }
        if (j < 300) q[(size_t)b*300 + j] = acc;
        else wbh[j-300] = acc;
    }
    if (wid == 0) {
        float v0 = sc[lane], v1 = sc[lane+32], v2 = sc[lane+64], v3 = sc[lane+96];
        float m = fmaxf(fmaxf(v0, v1), fmaxf(v2, v3));
        for (int o = 16; o; o >>= 1) m = fmaxf(m, __shfl_xor_sync(0xffffffffu, m, o));
        float e0 = expf(v0-m), e1 = expf(v1-m), e2 = expf(v2-m), e3 = expf(v3-m);
        float s = e0+e1+e2+e3;
        for (int o = 16; o; o >>= 1) s += __shfl_xor_sync(0xffffffffu, s, o);
        float inv = 1.f/s;
        al[lane] = e0*inv; al[lane+32] = e1*inv; al[lane+64] = e2*inv; al[lane+96] = e3*inv;
    }
    __syncthreads();
    for (int d = tid; d < GH; d += 256) {
        float acc = 0.f;
        for (int p = 0; p < PL; p++) acc += al[p]*po[((size_t)b*PL + p)*GH + d];
        din2[(size_t)b*KC + d] = acc;
    }
    if (tid < NT) {
        float s = 0.f;
        const float* u = ubg + ((size_t)b*NT + tid)*HID;
        for (int j = 0; j < HID; j++) s += vb_w[j]*tanhf(wbh[j] + u[j]);
        dls[tid] = s + vb_b[0];
    }
    __syncthreads();
    if (wid == 0) {
        float a0 = (lane < NT) ? dls[lane] : -1e30f;
        float a1 = (lane+32 < NT) ? dls[lane+32] : -1e30f;
        float m = fmaxf(a0, a1);
        for (int o = 16; o; o >>= 1) m = fmaxf(m, __shfl_xor_sync(0xffffffffu, m, o));
        float e0 = (lane < NT) ? expf(a0-m) : 0.f;
        float e1 = (lane+32 < NT) ? expf(a1-m) : 0.f;
        float s = e0 + e1;
        for (int o = 16; o; o >>= 1) s += __shfl_xor_sync(0xffffffffu, s, o);
        float inv = 1.f/s;
        if (lane < NT)    { das[lane] = e0*inv;    da[(size_t)b*NT + lane] = e0*inv; }
        if (lane+32 < NT) { das[lane+32] = e1*inv; da[(size_t)b*NT + lane+32] = e1*inv; }
    }
    __syncthreads();
    float* zrow = Z + ((size_t)t*B + b)*KD;
    for (int d = tid; d < 200; d += 256) {
        float s = 0.f;
        for (int n = 0; n < NT; n++) s += das[n]*sg[((size_t)b*NT + n)*200 + d];
        din2[(size_t)b*KC + 512 + d] = s;
        zrow[512 + d] = s;
    }
}

// ---------------- triple attention: partial over n-chunks, fp16 tef ----------------
__global__ void __launch_bounds__(256) dec_tv_part(
        const __half* __restrict__ tef16, const float* __restrict__ q,
        const float* __restrict__ da, float* __restrict__ tvp_t) {
    int b = blockIdx.x, ch = blockIdx.y;
    int tid = threadIdx.x, lane = tid & 31, wid = tid >> 5;
    __shared__ float qs[300];
    __shared__ float sw[10*NP];
    __shared__ float dal[10];
    for (int i = tid; i < 300; i += 256) qs[i] = q[(size_t)b*300 + i];
    if (tid < 10) dal[tid] = da[(size_t)b*NT + ch*10 + tid];
    __syncthreads();
    const __half* tb = tef16 + ((size_t)b*NT + ch*10)*NP*300;
    #pragma unroll
    for (int it = 0; it < 25; it++) {
        int pair = wid + 8*it;
        const __half* row = tb + (size_t)pair*300;
        float s = 0.f;
        for (int k2 = lane; k2 < 150; k2 += 32) {
            __half2 hv = *reinterpret_cast<const __half2*>(row + 2*k2);
            float2 fv = __half22float2(hv);
            s += fv.x*qs[2*k2] + fv.y*qs[2*k2+1];
        }
        #pragma unroll
        for (int o = 16; o; o >>= 1) s += __shfl_down_sync(0xffffffffu, s, o);
        if (lane == 0) sw[pair] = s;
    }
    __syncthreads();
    for (int n = wid; n < 10; n += 8) {
        float v = (lane < NP) ? sw[n*NP + lane] : -1e30f;
        float m = v;
        for (int o = 16; o; o >>= 1) m = fmaxf(m, __shfl_xor_sync(0xffffffffu, m, o));
        float e = (lane < NP) ? expf(v - m) : 0.f;
        float su = e;
        for (int o = 16; o; o >>= 1) su += __shfl_xor_sync(0xffffffffu, su, o);
        if (lane < NP) sw[n*NP + lane] = e * dal[n] / su;
    }
    __syncthreads();
    for (int d = tid; d < 300; d += 256) {
        float acc = 0.f;
        #pragma unroll 8
        for (int r = 0; r < 200; r++) acc += sw[r]*__half2float(tb[(size_t)r*300 + d]);
        tvp_t[((size_t)b*NCH + ch)*300 + d] = acc;
    }
}

// decoder combined GEMM with inline tv-partial summation for A cols [712,1012)
__global__ void gemm_splitk_tv(const float* __restrict__ A, const float* __restrict__ W,
                               float* __restrict__ Cp, const float* __restrict__ tvp_t,
                               int M, int N, int K, int kchunk) {
    __shared__ float As[16][64];
    __shared__ float Ws[16][64];
    int z = blockIdx.y;
    int ks = z * kchunk;
    int ke = min(K, ks + kchunk);
    int bn = blockIdx.x * 64;
    int tid = threadIdx.x;
    int tx = tid & 15, ty = tid >> 4;
    float acc[4][4] = {};
    int r  = tid >> 2;
    int kk = (tid & 3) * 4;
    for (int k0 = ks; k0 < ke; k0 += 16) {
        int gk = k0 + kk;
        float4 va = make_float4(0,0,0,0);
        if (r < M) {
            if (gk >= 712 && gk < 1012) {
                float tsum[4];
                #pragma unroll
                for (int e = 0; e < 4; e++) {
                    float s = 0.f;
                    #pragma unroll
                    for (int ch = 0; ch < NCH; ch++)
                        s += tvp_t[((size_t)r*NCH + ch)*300 + gk + e - 712];
                    tsum[e] = s;
                }
                va = make_float4(tsum[0], tsum[1], tsum[2], tsum[3]);
            } else if (gk + 3 < ke) {
                va = *reinterpret_cast<const float4*>(A + (size_t)r*K + gk);
            } else {
                float t0=0,t1=0,t2=0,t3=0;
                if (gk+0<ke) t0=A[(size_t)r*K+gk+0]; if (gk+1<ke) t1=A[(size_t)r*K+gk+1];
                if (gk+2<ke) t2=A[(size_t)r*K+gk+2]; if (gk+3<ke) t3=A[(size_t)r*K+gk+3];
                va = make_float4(t0,t1,t2,t3);
            }
        }
        As[kk+0][r]=va.x; As[kk+1][r]=va.y; As[kk+2][r]=va.z; As[kk+3][r]=va.w;
        float4 vw = make_float4(0,0,0,0);
        int gn = bn + r;
        if (gn < N) {
            if (gk + 3 < ke) vw = *reinterpret_cast<const float4*>(W + (size_t)gn*K + gk);
            else { float t0=0,t1=0,t2=0,t3=0;
                   if (gk+0<ke) t0=W[(size_t)gn*K+gk+0]; if (gk+1<ke) t1=W[(size_t)gn*K+gk+1];
                   if (gk+2<ke) t2=W[(size_t)gn*K+gk+2]; if (gk+3<ke) t3=W[(size_t)gn*K+gk+3];
                   vw = make_float4(t0,t1,t2,t3); }
        }
        Ws[kk+0][r]=vw.x; Ws[kk+1][r]=vw.y; Ws[kk+2][r]=vw.z; Ws[kk+3][r]=vw.w;
        __syncthreads();
        #pragma unroll
        for (int k = 0; k < 16; k++) {
            float4 a = *reinterpret_cast<const float4*>(&As[k][ty*4]);
            float4 b = *reinterpret_cast<const float4*>(&Ws[k][tx*4]);
            acc[0][0]+=a.x*b.x; acc[0][1]+=a.x*b.y; acc[0][2]+=a.x*b.z; acc[0][3]+=a.x*b.w;
            acc[1][0]+=a.y*b.x; acc[1][1]+=a.y*b.y; acc[1][2]+=a.y*b.z; acc[1][3]+=a.y*b.w;
            acc[2][0]+=a.z*b.x; acc[2][1]+=a.z*b.y; acc[2][2]+=a.z*b.z; acc[2][3]+=a.z*b.w;
            acc[3][0]+=a.w*b.x; acc[3][1]+=a.w*b.y; acc[3][2]+=a.w*b.z; acc[3][3]+=a.w*b.w;
        }
        __syncthreads();
    }
    float* Cz = Cp + (size_t)z*M*N;
    #pragma unroll
    for (int i = 0; i < 4; i++) {
        int gm = ty*4 + i; if (gm >= M) continue;
        #pragma unroll
        for (int j = 0; j < 4; j++) {
            int gn = bn + tx*4 + j; if (gn >= N) continue;
            Cz[(size_t)gm*N + gn] = acc[i][j];
        }
    }
}

// final gates for last decoder step
__global__ void dec_gates2(const float* __restrict__ cp, const float* __restrict__ gxrv_t,
                           const float* __restrict__ bhh, float* __restrict__ din2,
                           float* __restrict__ Z, int t) {
    int idx = blockIdx.x*blockDim.x + threadIdx.x;
    if (idx >= B*GH) return;
    int b = idx / GH, j = idx % GH;
    float cr = 0.f, cz = 0.f, cxn = 0.f, chn = 0.f;
    #pragma unroll
    for (int z = 0; z < 8; z++) {
        const float* p = cp + ((size_t)z*B + b)*G4;
        cr += p[j]; cz += p[512+j]; cxn += p[1024+j]; chn += p[1536+j];
    }
    const float* gr = gxrv_t + (size_t)b*G3;
    float r  = sigmoidf_(cr + gr[j] + bhh[j]);
    float zz = sigmoidf_(cz + gr[GH+j] + bhh[GH+j]);
    float n  = tanhf(cxn + gr[2*GH+j] + r*(chn + bhh[2*GH+j]));
    float hold = din2[(size_t)b*KC + 1012 + j];
    float hn = (1.f - zz)*n + zz*hold;
    din2[(size_t)b*KC + 1012 + j] = hn;
    Z[((size_t)t*B + b)*KD + j] = hn;
}

// ---------------- fp16 split prep ----------------
// W: [bh] only (deduped), KW cols
__global__ void k_split_W(const float* __restrict__ W, __half* __restrict__ Ws) {
    size_t i = (size_t)blockIdx.x*blockDim.x + threadIdx.x;
    size_t total = (size_t)VW*(KW/8);
    if (i >= total) return;
    int cg = (int)(i % (KW/8));
    size_t r = i / (KW/8);
    int c0 = cg*8;
    __half o[8];
    #pragma unroll
    for (int e = 0; e < 8; e++) {
        int c = c0 + e;
        o[e] = (c < KSEG) ? __float2half(W[r*KSEG + c]) : __float2half(0.f);
    }
    *reinterpret_cast<uint4*>(Ws + r*KW + c0) = *reinterpret_cast<uint4*>(o);
}

// A: [ah(KW) | al(KW)]; tv range sourced by summing tvp partials
__global__ void k_split_Z(const float* __restrict__ Z, const float* __restrict__ tvp,
                          __half* __restrict__ As_) {
    size_t i = (size_t)blockIdx.x*blockDim.x + threadIdx.x;
    size_t total = (size_t)MP*(KPA/8);
    if (i >= total) return;
    int cg = (int)(i % (KPA/8));
    int m = (int)(i / (KPA/8));
    int b = m / TDEC, t = m - b*TDEC;
    int c0 = cg*8;
    __half o[8];
    #pragma unroll
    for (int e = 0; e < 8; e++) {
        int c = c0 + e;
        int lo = (c >= KW);
        int kc = lo ? (c - KW) : c;
        __half v = __float2half(0.f);
        if (b < B && kc < KSEG) {
            float zv;
            if (kc >= 712 && kc < 1012) {
                float s = 0.f;
                #pragma unroll
                for (int ch = 0; ch < NCH; ch++)
                    s += tvp[(size_t)t*B*NCH*300 + ((size_t)b*NCH + ch)*300 + (kc - 712)];
                zv = s;
            } else {
                zv = Z[((size_t)t*B + b)*KD + kc];
            }
            __half hh = __float2half(zv);
            if (lo) v = __float2half(zv - __half2float(hh));
            else v = hh;
        }
        o[e] = v;
    }
    *reinterpret_cast<uint4*>(As_ + (size_t)m*KPA + c0) = *reinterpret_cast<uint4*>(o);
}

// ---------------- mma.sync fp16 vocab GEMM: 256x128 tile, B deduped ----------------
__global__ void __launch_bounds__(256) vocab_mma(
        const __half* __restrict__ Ag, const __half* __restrict__ Wg,
        const float* __restrict__ bout, float* __restrict__ out) {
    extern __shared__ __align__(16) char sraw[];
    const int tid = threadIdx.x;
    const int wid = tid >> 5, lane = tid & 31;
    const int m0 = blockIdx.x * VTM, n0 = blockIdx.y * VTN;
    const int wm = (wid >> 1) * 64, wn = (wid & 1) * 64;
    const int g = lane >> 2, tg = lane & 3;
    const uint32_t sb = smem_u32(sraw);

    float acc[4][8][4];
    #pragma unroll
    for (int i = 0; i < 4; i++)
    #pragma unroll
    for (int j = 0; j < 8; j++) { acc[i][j][0]=0.f; acc[i][j][1]=0.f; acc[i][j][2]=0.f; acc[i][j][3]=0.f; }

    auto load_stage = [&](int s, int k0) {
        uint32_t base = sb + (uint32_t)s*VSTAGE;
        #pragma unroll
        for (int i = 0; i < 10; i++) {
            int c = i*256 + tid;                  // 0..2559: A0 1024, A1 1024, B 512
            uint32_t roff; const __half* src;
            if (c < 1024) {
                int row = c >> 2, ch = c & 3;
                roff = (uint32_t)row*(SSTRIDE*2) + (uint32_t)ch*16u;
                src = Ag + (size_t)(m0+row)*KPA + k0 + ch*8;
            } else if (c < 2048) {
                int cc = c - 1024; int row = cc >> 2, ch = cc & 3;
                roff = VA_HALF + (uint32_t)row*(SSTRIDE*2) + (uint32_t)ch*16u;
                src = Ag + (size_t)(m0+row)*KPA + KW + k0 + ch*8;
            } else {
                int cc = c - 2048; int row = cc >> 2, ch = cc & 3;
                roff = 2*VA_HALF + (uint32_t)row*(SSTRIDE*2) + (uint32_t)ch*16u;
                src = Wg + (size_t)(n0+row)*KW + k0 + ch*8;
            }
            asm volatile("cp.async.cg.shared.global [%0], [%1], 16;" :: "r"(base + roff), "l"(src));
        }
        asm volatile("cp.async.commit_group;" ::: "memory");
    };

    load_stage(0, 0); load_stage(1, 32); load_stage(2, 64);

    const int a_row = lane & 15;
    const int a_k8  = (lane >> 4) << 3;
    const int b_row = lane & 7;
    const int b_k8  = ((lane >> 3) & 1) << 3;
    const int b_ni  = lane >> 4;

    const int NIT = KW/32;                 // 51
    for (int kt = 0; kt < NIT; kt++) {
        if (kt + 3 < NIT) { asm volatile("cp.async.wait_group 2;" ::: "memory"); }
        else              { asm volatile("cp.async.wait_group 0;" ::: "memory"); }
        __syncthreads();
        int s = kt % 3;
        uint32_t baseA0 = sb + (uint32_t)s*VSTAGE;
        uint32_t baseB  = baseA0 + 2*VA_HALF;
        #pragma unroll
        for (int kk = 0; kk < 2; kk++) {
            uint32_t bfr[8][2];
            #pragma unroll
            for (int ni = 0; ni < 8; ni += 2) {
                uint32_t bd = baseB + ((uint32_t)(wn + (ni + b_ni)*8 + b_row)*SSTRIDE
                                       + (uint32_t)(kk*16 + b_k8))*2u;
                asm volatile("ldmatrix.sync.aligned.m8n8.x4.shared.b16 {%0,%1,%2,%3}, [%4];"
                    : "=r"(bfr[ni][0]),"=r"(bfr[ni][1]),"=r"(bfr[ni+1][0]),"=r"(bfr[ni+1][1])
                    : "r"(bd));
            }
            #pragma unroll
            for (int half = 0; half < 2; half++) {
                uint32_t baseA = baseA0 + (uint32_t)half*VA_HALF;
                uint32_t afr[4][4];
                #pragma unroll
                for (int mi = 0; mi < 4; mi++) {
                    uint32_t ad = baseA + ((uint32_t)(wm + mi*16 + a_row)*SSTRIDE
                                           + (uint32_t)(kk*16 + a_k8))*2u;
                    asm volatile("ldmatrix.sync.aligned.m8n8.x4.shared.b16 {%0,%1,%2,%3}, [%4];"
                        : "=r"(afr[mi][0]),"=r"(afr[mi][1]),"=r"(afr[mi][2]),"=r"(afr[mi][3])
                        : "r"(ad));
                }
                #pragma unroll
                for (int mi = 0; mi < 4; mi++)
                #pragma unroll
                for (int ni = 0; ni < 8; ni++) {
                    asm volatile(
                      "mma.sync.aligned.m16n8k16.row.col.f32.f16.f16.f32 "
                      "{%0,%1,%2,%3},{%4,%5,%6,%7},{%8,%9},{%0,%1,%2,%3};"
                      : "+f"(acc[mi][ni][0]), "+f"(acc[mi][ni][1]),
                        "+f"(acc[mi][ni][2]), "+f"(acc[mi][ni][3])
                      : "r"(afr[mi][0]),"r"(afr[mi][1]),"r"(afr[mi][2]),"r"(afr[mi][3]),
                        "r"(bfr[ni][0]),"r"(bfr[ni][1]));
                }
            }
        }
        __syncthreads();
        if (kt + 3 < NIT) load_stage(s, (kt+3)*32);
    }
    __syncthreads();

    float* Ds = (float*)sraw;
    #pragma unroll
    for (int h = 0; h < 2; h++) {
        if ((wid >> 2) == h) {
            int mbase = wm - h*128;
            #pragma unroll
            for (int mi = 0; mi < 4; mi++) {
                int mA = mbase + mi*16 + g;
                #pragma unroll
                for (int ni = 0; ni < 8; ni++) {
                    int nn = wn + ni*8 + tg*2;
                    Ds[mA*129 + nn]         = acc[mi][ni][0];
                    Ds[mA*129 + nn + 1]     = acc[mi][ni][1];
                    Ds[(mA+8)*129 + nn]     = acc[mi][ni][2];
                    Ds[(mA+8)*129 + nn + 1] = acc[mi][ni][3];
                }
            }
        }
        __syncthreads();
        for (int idx = tid; idx < VTN*128; idx += 256) {
            int n = idx >> 7, m = idx & 127;
            int mg = m0 + h*128 + m;
            if (mg < B*TDEC) {
                int bb = mg / TDEC, tt = mg - bb*TDEC;
                int ng = n0 + n;
                out[(size_t)bb*VW*TDEC + (size_t)ng*TDEC + tt] = Ds[m*129 + n] + __ldg(bout + ng);
            }
        }
        __syncthreads();
    }
}

// ---------------- launch ----------------
extern "C" void kernel_launch(void* const* d_in, const int* in_sizes, int n_in,
                              void* d_out, int out_size) {
    const float* word_emb   = (const float*)d_in[0];
    const float* transe_emb = (const float*)d_in[1];
    const float* wh_w = (const float*)d_in[2];  const float* wh_b = (const float*)d_in[3];
    const float* wr_w = (const float*)d_in[4];  const float* wr_b = (const float*)d_in[5];
    const float* wt_w = (const float*)d_in[6];  const float* wt_b = (const float*)d_in[7];
    const float* wb_w = (const float*)d_in[8];  const float* wb_b = (const float*)d_in[9];
    const float* ub_w = (const float*)d_in[10]; const float* ub_b = (const float*)d_in[11];
    const float* vb_w = (const float*)d_in[12]; const float* vb_b = (const float*)d_in[13];
    const float* wc_w = (const float*)d_in[14]; const float* wc_b = (const float*)d_in[15];
    const float* Wih_e = (const float*)d_in[16]; const float* Whh_e = (const float*)d_in[17];
    const float* bih_e = (const float*)d_in[18]; const float* bhh_e = (const float*)d_in[19];
    const float* Wih_d = (const float*)d_in[20]; const float* Whh_d = (const float*)d_in[21];
    const float* bih_d = (const float*)d_in[22]; const float* bhh_d = (const float*)d_in[23];
    const float* out_w = (const float*)d_in[24]; const float* out_b = (const float*)d_in[25];
    const int* post          = (const int*)d_in[26];
    const int* post_length   = (const int*)d_in[27];
    const int* response      = (const int*)d_in[28];
    const int* resp_triple   = (const int*)d_in[29];
    const int* post_triple   = (const int*)d_in[30];
    const int* triple        = (const int*)d_in[31];
    float* out = (float*)d_out;

    void* basep = nullptr; cudaGetSymbolAddress(&basep, g_buf);
    float* base = (float*)basep;
    void* wsp = nullptr; cudaGetSymbolAddress(&wsp, g_Ws);
    void* asp = nullptr; cudaGetSymbolAddress(&asp, g_As);
    void* t16p = nullptr; cudaGetSymbolAddress(&t16p, g_tef16);
    __half* Ws = (__half*)wsp;
    __half* As = (__half*)asp;
    __half* tef16 = (__half*)t16p;

    float* tef  = base + OFF_TEF;
    float* sl   = base + OFF_SL;
    float* sg   = base + OFF_SG;
    float* ubg  = base + OFF_UBG;
    float* pin  = base + OFF_PIN;
    float* gxe  = base + OFF_GXE;
    float* po   = base + OFF_PO;
    float* hA   = base + OFF_HA;
    float* hB   = base + OFF_HB;
    float* rv   = base + OFF_RV;
    float* Z    = base + OFF_Z;
    float* din2 = base + OFF_DIN2;
    float* q    = base + OFF_Q;
    float* da   = base + OFF_DA;
    float* cp   = base + OFF_CP;
    float* ghpA = base + OFF_GHPA;
    float* ghpB = base + OFF_GHPB;
    float* gxrv = base + OFF_GXRV;
    float* Wcb  = base + OFF_WCB;
    float* Wrv  = base + OFF_WRV;
    float* tvp  = base + OFF_TVP;

    cudaFuncSetAttribute(vocab_mma, cudaFuncAttributeMaxDynamicSharedMemorySize, VSMEM);

    // ---- phase A ----
    k_zero<<<(unsigned)((SZ_H + 255)/256), 256>>>(hA, SZ_H);
    {
        size_t n4 = (size_t)B*NT*NP*3*25;
        k_gather_tef<<<(unsigned)((n4 + 255)/256), 256>>>(transe_emb, triple, tef, tef16);
    }
    {
        size_t n4 = (size_t)TDEC*B*150;
        k_gather_rv<<<(unsigned)((n4 + 255)/256), 256>>>(word_emb, transe_emb, response, resp_triple, rv, Z);
    }
    {
        size_t nsp = (size_t)VW*(KW/8);
        k_split_W<<<(unsigned)((nsp + 255)/256), 256>>>(out_w, Ws);
    }
    {
        size_t n = (size_t)G4*KC;
        k_build_wcomb<<<(unsigned)((n + 255)/256), 256>>>(Wih_d, Whh_d, Wcb);
    }
    {
        size_t n = (size_t)G3*600;
        k_build_wrv<<<(unsigned)((n + 255)/256), 256>>>(Wih_d, Wrv);
    }
    k_triple_score<<<B*NT*NP, 128>>>(tef, triple, wh_w, wh_b, wr_w, wr_b, wt_w, wt_b, sl);
    k_graph_softmax<<<B*NT, 64>>>(sl, tef, sg);
    k_ubg<<<B*NT, 128>>>(sg, ub_w, ub_b, ubg);
    {
        size_t n4 = (size_t)B*PL*125;
        k_post_in<<<(unsigned)((n4 + 255)/256), 256>>>(word_emb, sg, post, post_triple, pin);
    }
    gemm_bias<<<dim3((B*PL)/64, G3/64), 256>>>(pin, Wih_e, bih_e, gxe, B*PL, G3, KE);
    gemm_bias<<<dim3((TDEC*B)/64, G3/64), 256>>>(rv, Wrv, bih_d, gxrv, TDEC*B, G3, 600);

    // ---- phase B: encoder (1 launch/step, fused prev-gates, ping-pong h/ghp) ----
    for (int t = 0; t < PL; t++) {
        const float* hin  = ((t-1) & 1) ? hB : hA;      // t=0 -> hA (zeros)
        float* hout       = (t & 1) ? hB : hA;
        const float* gin  = ((t-1) & 1) ? ghpB : ghpA;
        float* gout       = (t & 1) ? ghpB : ghpA;
        if (t == 0) hin = hA;
        enc_step<<<dim3(G3/64, 4), 256>>>(hin, hout, gin, gout, Whh_e, gxe, bhh_e,
                                          po, post_length, t);
    }
    // final gates (t = 127): h_127 in hB (127&1=1), ghp(127) in ghpB
    enc_gates<<<(B*GH)/256, 256>>>(gxe, ghpB, bhh_e, hB, po, post_length, PL-1);
    k_h2din2<<<(B*GH)/256, 256>>>(hB, din2);

    // ---- phase C: decoder (3 launches/step) ----
    for (int t = 0; t < TDEC; t++) {
        const float* gxrv_prev = (t > 0) ? (gxrv + (size_t)(t-1)*B*G3) : gxrv;
        float* tvp_t = tvp + (size_t)t*B*NCH*300;
        dec_am<<<B, 256>>>(din2, po, cp, gxrv_prev, bhh_d,
                           wb_w, wb_b, wc_w, wc_b, vb_w, vb_b,
                           ubg, sg, q, da, Z, t, t > 0 ? 1 : 0);
        dec_tv_part<<<dim3(B, NCH), 256>>>(tef16, q, da, tvp_t);
        gemm_splitk_tv<<<dim3(G4/64, 8), 256>>>(din2, Wcb, cp, tvp_t, B, G4, KC, 192);
    }
    dec_gates2<<<(B*GH)/256, 256>>>(cp, gxrv + (size_t)(TDEC-1)*B*G3, bhh_d, din2, Z, TDEC-1);

    // ---- phase D: split Z + vocab projection ----
    {
        size_t nsp = (size_t)MP*(KPA/8);
        k_split_Z<<<(unsigned)((nsp + 255)/256), 256>>>(Z, tvp, As);
    }
    vocab_mma<<<dim3(MP/VTM, VW/VTN), 256, VSMEM>>>(As, Ws, out_b, out);
}

// round 13
// speedup vs baseline: 1.3503x; 1.3503x over previous
#include <cuda_runtime.h>
#include <cuda_fp16.h>
#include <cstdint>
#include <math.h>

// ---------------- problem dims ----------------
#define B    64
#define PL   128
#define RL   64
#define TDEC 63
#define NT   50
#define NP   20
#define TE   100
#define HID  100
#define GH   512
#define G3   1536
#define G4   2048        // 4 gate-row groups for combined decoder GEMM
#define DE   300
#define VW   32000
#define KE   500
#define KD   1612        // logits input dim [hn,dg,tv,rv]
#define KC   1524        // combined decoder GEMM K = 1012 (cv,dg,tv) + 512 (h)
#define NEGV -1000000000.0f
#define NCH  5           // tv n-chunks (10 triples each)

// ---- fp16 2-term split vocab GEMM: A=[ah|al] (KPA), B=[bh] (KW, deduped) ----
#define KSEG 1612
#define KW   1632        // unique K (1612 padded to 32)
#define KPA  3264        // A row: [ah(1632) | al(1632)]
#define MP   4096
#define SSTRIDE 40       // smem row stride in fp16 (32 data + 8 pad)
#define VTM  256
#define VTN  128
#define VA_HALF (256*SSTRIDE*2)           // 20480 per A half
#define VB_SZ   (128*SSTRIDE*2)           // 10240
#define VSTAGE  (2*VA_HALF + VB_SZ)       // 51200
#define VSMEM   (3*VSTAGE)                // 153600

// ---------------- scratch ----------------
constexpr size_t SZ_TEF = (size_t)B*NT*NP*300;
constexpr size_t SZ_SL  = (size_t)B*NT*NP;
constexpr size_t SZ_SG  = (size_t)B*NT*200;
constexpr size_t SZ_UBG = (size_t)B*NT*100;
constexpr size_t SZ_PIN = (size_t)B*PL*KE;
constexpr size_t SZ_GXE = (size_t)B*PL*G3;
constexpr size_t SZ_PO  = (size_t)B*PL*GH;
constexpr size_t SZ_H   = (size_t)B*GH;
constexpr size_t SZ_RV  = (size_t)TDEC*B*600;
constexpr size_t SZ_Z   = (size_t)TDEC*B*KD;
constexpr size_t SZ_DIN2= (size_t)B*KC;
constexpr size_t SZ_Q   = (size_t)B*300;
constexpr size_t SZ_DA  = (size_t)B*NT;
constexpr size_t SZ_CP  = (size_t)8*B*G4;
constexpr size_t SZ_GHP = (size_t)4*B*G3;
constexpr size_t SZ_GXRV= (size_t)TDEC*B*G3;
constexpr size_t SZ_WCB = (size_t)G4*KC;
constexpr size_t SZ_WRV = (size_t)G3*600;
constexpr size_t SZ_TVP = (size_t)B*NCH*300;

constexpr size_t OFF_TEF = 0;
constexpr size_t OFF_SL  = OFF_TEF + SZ_TEF;
constexpr size_t OFF_SG  = OFF_SL  + SZ_SL;
constexpr size_t OFF_UBG = OFF_SG  + SZ_SG;
constexpr size_t OFF_PIN = OFF_UBG + SZ_UBG;
constexpr size_t OFF_GXE = OFF_PIN + SZ_PIN;
constexpr size_t OFF_PO  = OFF_GXE + SZ_GXE;
constexpr size_t OFF_H   = OFF_PO  + SZ_PO;
constexpr size_t OFF_RV  = OFF_H   + SZ_H;
constexpr size_t OFF_Z   = OFF_RV  + SZ_RV;
constexpr size_t OFF_DIN2= OFF_Z   + SZ_Z;
constexpr size_t OFF_Q   = OFF_DIN2+ SZ_DIN2;
constexpr size_t OFF_DA  = OFF_Q   + SZ_Q;
constexpr size_t OFF_CP  = OFF_DA  + SZ_DA;
constexpr size_t OFF_GHP = OFF_CP  + SZ_CP;
constexpr size_t OFF_GXRV= OFF_GHP + SZ_GHP;
constexpr size_t OFF_WCB = OFF_GXRV+ SZ_GXRV;
constexpr size_t OFF_WRV = OFF_WCB + SZ_WCB;
constexpr size_t OFF_TVP = OFF_WRV + SZ_WRV;
constexpr size_t SZ_TOTAL = OFF_TVP + SZ_TVP;

__device__ float g_buf[SZ_TOTAL];
__device__ __align__(16) __half g_Ws[(size_t)VW * KW];
__device__ __align__(16) __half g_As[(size_t)MP * KPA];
__device__ __align__(16) __half g_tef16[SZ_TEF];

__device__ __forceinline__ float sigmoidf_(float x) { return 1.0f / (1.0f + expf(-x)); }
__device__ __forceinline__ uint32_t smem_u32(const void* p) {
    uint32_t a;
    asm("{ .reg .u64 t; cvta.to.shared.u64 t, %1; cvt.u32.u64 %0, t; }" : "=r"(a) : "l"(p));
    return a;
}

// ---------------- small utility kernels ----------------
__global__ void k_zero(float* p, size_t n) {
    size_t i = (size_t)blockIdx.x*blockDim.x + threadIdx.x;
    if (i < n) p[i] = 0.f;
}

__global__ void k_gather_tef(const float* __restrict__ te, const int* __restrict__ triple,
                             float* __restrict__ tef, __half* __restrict__ tef16) {
    size_t i = (size_t)blockIdx.x*blockDim.x + threadIdx.x;
    size_t total = (size_t)B*NT*NP*3*25;
    if (i >= total) return;
    size_t ent = i / 25; int off = (int)(i % 25) * 4;
    size_t tri = ent / 3; int e = (int)(ent % 3);
    int idx = triple[ent];
    float4 v = *reinterpret_cast<const float4*>(te + (size_t)idx*TE + off);
    size_t dst = tri*300 + e*100 + off;
    *reinterpret_cast<float4*>(tef + dst) = v;
    __half h4[4];
    h4[0] = __float2half(v.x); h4[1] = __float2half(v.y);
    h4[2] = __float2half(v.z); h4[3] = __float2half(v.w);
    *reinterpret_cast<uint2*>(tef16 + dst) = *reinterpret_cast<uint2*>(h4);
}

__global__ void k_gather_rv(const float* __restrict__ we, const float* __restrict__ te,
                            const int* __restrict__ resp, const int* __restrict__ rtrip,
                            float* __restrict__ rv, float* __restrict__ Z) {
    size_t i = (size_t)blockIdx.x*blockDim.x + threadIdx.x;
    size_t total = (size_t)TDEC*B*150;
    if (i >= total) return;
    size_t tb = i / 150; int f = (int)(i % 150);
    int t = (int)(tb / B), b = (int)(tb % B);
    float4 v;
    if (f < 75) {
        int w = resp[b*RL + t];
        v = *reinterpret_cast<const float4*>(we + (size_t)w*DE + f*4);
    } else {
        int f2 = f - 75; int e = f2 / 25; int off = (f2 % 25) * 4;
        int idx = rtrip[((size_t)b*RL + t)*3 + e];
        v = *reinterpret_cast<const float4*>(te + (size_t)idx*TE + off);
    }
    *reinterpret_cast<float4*>(rv + tb*600 + f*4) = v;
    *reinterpret_cast<float4*>(Z + tb*KD + 1012 + f*4) = v;
}

__global__ void k_triple_score(const float* __restrict__ tef, const int* __restrict__ triple,
                               const float* __restrict__ wh_w, const float* __restrict__ wh_b,
                               const float* __restrict__ wr_w, const float* __restrict__ wr_b,
                               const float* __restrict__ wt_w, const float* __restrict__ wt_b,
                               float* __restrict__ sl) {
    int g = blockIdx.x;
    const float* tb = tef + (size_t)g*300;
    __shared__ float e[300];
    __shared__ float red[128];
    int tid = threadIdx.x;
    for (int i = tid; i < 300; i += 128) e[i] = tb[i];
    __syncthreads();
    float contrib = 0.f;
    if (tid < HID) {
        int j = tid;
        float a = wh_b[j] + wt_b[j];
        float r = wr_b[j];
        const float* whr = wh_w + (size_t)j*TE;
        const float* wtr = wt_w + (size_t)j*TE;
        const float* wrr = wr_w + (size_t)j*TE;
        #pragma unroll 4
        for (int k = 0; k < TE; k++) {
            a += e[k]*whr[k] + e[200+k]*wtr[k];
            r += e[100+k]*wrr[k];
        }
        contrib = r * tanhf(a);
    }
    red[tid] = contrib; __syncthreads();
    for (int s = 64; s; s >>= 1) { if (tid < s) red[tid] += red[tid+s]; __syncthreads(); }
    if (tid == 0)
        sl[g] = (triple[(size_t)g*3] == 0) ? NEGV : red[0];
}

__global__ void k_graph_softmax(const float* __restrict__ sl, const float* __restrict__ tef,
                                float* __restrict__ sg) {
    int g = blockIdx.x;
    int tid = threadIdx.x;
    __shared__ float sa[NP];
    if (tid == 0) {
        float m = -1e30f;
        for (int p = 0; p < NP; p++) m = fmaxf(m, sl[(size_t)g*NP + p]);
        float sum = 0.f;
        for (int p = 0; p < NP; p++) { float ev = expf(sl[(size_t)g*NP + p] - m); sa[p] = ev; sum += ev; }
        float inv = 1.f / sum;
        for (int p = 0; p < NP; p++) sa[p] *= inv;
    }
    __syncthreads();
    const float* tb = tef + (size_t)g*NP*300;
    for (int d = tid; d < 200; d += 64) {
        int dd = (d < 100) ? d : d + 100;
        float s = 0.f;
        #pragma unroll
        for (int p = 0; p < NP; p++) s += sa[p]*tb[(size_t)p*300 + dd];
        sg[(size_t)g*200 + d] = s;
    }
}

__global__ void k_ubg(const float* __restrict__ sg, const float* __restrict__ ub_w,
                      const float* __restrict__ ub_b, float* __restrict__ ubg) {
    int g = blockIdx.x;
    int tid = threadIdx.x;
    __shared__ float s[200];
    for (int i = tid; i < 200; i += 128) s[i] = sg[(size_t)g*200 + i];
    __syncthreads();
    if (tid < HID) {
        float acc = ub_b[tid];
        const float* w = ub_w + (size_t)tid*200;
        #pragma unroll 4
        for (int k = 0; k < 200; k++) acc += s[k]*w[k];
        ubg[(size_t)g*HID + tid] = acc;
    }
}

__global__ void k_post_in(const float* __restrict__ we, const float* __restrict__ sg,
                          const int* __restrict__ post, const int* __restrict__ ptrip,
                          float* __restrict__ pin) {
    size_t i = (size_t)blockIdx.x*blockDim.x + threadIdx.x;
    size_t total = (size_t)B*PL*125;
    if (i >= total) return;
    size_t bt = i / 125; int f = (int)(i % 125);
    float4 v;
    if (f < 75) {
        v = *reinterpret_cast<const float4*>(we + (size_t)post[bt]*DE + f*4);
    } else {
        int b = (int)(bt / PL);
        int n = ptrip[bt];
        v = *reinterpret_cast<const float4*>(sg + ((size_t)b*NT + n)*200 + (f-75)*4);
    }
    *reinterpret_cast<float4*>(pin + bt*KE + f*4) = v;
}

__global__ void k_build_wcomb(const float* __restrict__ Wih, const float* __restrict__ Whh,
                              float* __restrict__ Wc) {
    size_t i = (size_t)blockIdx.x*blockDim.x + threadIdx.x;
    if (i >= (size_t)G4*KC) return;
    int c = (int)(i % KC);
    int r = (int)(i / KC);
    float v = 0.f;
    if (r < 1024) {
        v = (c < 1012) ? Wih[(size_t)r*KD + c] : Whh[(size_t)r*GH + (c - 1012)];
    } else if (r < 1536) {
        if (c < 1012) v = Wih[(size_t)r*KD + c];
    } else {
        if (c >= 1012) v = Whh[(size_t)(r - 512)*GH + (c - 1012)];
    }
    Wc[i] = v;
}

__global__ void k_build_wrv(const float* __restrict__ Wih, float* __restrict__ Wrv) {
    size_t i = (size_t)blockIdx.x*blockDim.x + threadIdx.x;
    if (i >= (size_t)G3*600) return;
    int c = (int)(i % 600);
    int r = (int)(i / 600);
    Wrv[i] = Wih[(size_t)r*KD + 1012 + c];
}

__global__ void k_h2din2(const float* __restrict__ h, float* __restrict__ din2) {
    int i = blockIdx.x*blockDim.x + threadIdx.x;
    if (i >= B*GH) return;
    int b = i / GH, j = i % GH;
    din2[(size_t)b*KC + 1012 + j] = h[i];
}

// ---------------- fp32 tiled GEMMs ----------------
__global__ void gemm_bias(const float* __restrict__ A, const float* __restrict__ W,
                          const float* __restrict__ bias, float* __restrict__ C,
                          int M, int N, int K) {
    __shared__ float As[16][64];
    __shared__ float Ws[16][64];
    int bm = blockIdx.x * 64, bn = blockIdx.y * 64;
    int tid = threadIdx.x;
    int tx = tid & 15, ty = tid >> 4;
    float acc[4][4] = {};
    int r  = tid >> 2;
    int kk = (tid & 3) * 4;
    for (int k0 = 0; k0 < K; k0 += 16) {
        int gk = k0 + kk;
        float4 va = make_float4(0,0,0,0);
        int gm = bm + r;
        if (gm < M) {
            if (gk + 3 < K) va = *reinterpret_cast<const float4*>(A + (size_t)gm*K + gk);
            else { float t0=0,t1=0,t2=0,t3=0;
                   if (gk+0<K) t0=A[(size_t)gm*K+gk+0]; if (gk+1<K) t1=A[(size_t)gm*K+gk+1];
                   if (gk+2<K) t2=A[(size_t)gm*K+gk+2]; if (gk+3<K) t3=A[(size_t)gm*K+gk+3];
                   va = make_float4(t0,t1,t2,t3); }
        }
        As[kk+0][r]=va.x; As[kk+1][r]=va.y; As[kk+2][r]=va.z; As[kk+3][r]=va.w;
        float4 vw = make_float4(0,0,0,0);
        int gn = bn + r;
        if (gn < N) {
            if (gk + 3 < K) vw = *reinterpret_cast<const float4*>(W + (size_t)gn*K + gk);
            else { float t0=0,t1=0,t2=0,t3=0;
                   if (gk+0<K) t0=W[(size_t)gn*K+gk+0]; if (gk+1<K) t1=W[(size_t)gn*K+gk+1];
                   if (gk+2<K) t2=W[(size_t)gn*K+gk+2]; if (gk+3<K) t3=W[(size_t)gn*K+gk+3];
                   vw = make_float4(t0,t1,t2,t3); }
        }
        Ws[kk+0][r]=vw.x; Ws[kk+1][r]=vw.y; Ws[kk+2][r]=vw.z; Ws[kk+3][r]=vw.w;
        __syncthreads();
        #pragma unroll
        for (int k = 0; k < 16; k++) {
            float4 a = *reinterpret_cast<const float4*>(&As[k][ty*4]);
            float4 b = *reinterpret_cast<const float4*>(&Ws[k][tx*4]);
            acc[0][0]+=a.x*b.x; acc[0][1]+=a.x*b.y; acc[0][2]+=a.x*b.z; acc[0][3]+=a.x*b.w;
            acc[1][0]+=a.y*b.x; acc[1][1]+=a.y*b.y; acc[1][2]+=a.y*b.z; acc[1][3]+=a.y*b.w;
            acc[2][0]+=a.z*b.x; acc[2][1]+=a.z*b.y; acc[2][2]+=a.z*b.z; acc[2][3]+=a.z*b.w;
            acc[3][0]+=a.w*b.x; acc[3][1]+=a.w*b.y; acc[3][2]+=a.w*b.z; acc[3][3]+=a.w*b.w;
        }
        __syncthreads();
    }
    #pragma unroll
    for (int i = 0; i < 4; i++) {
        int gm = bm + ty*4 + i; if (gm >= M) continue;
        #pragma unroll
        for (int j = 0; j < 4; j++) {
            int gn = bn + tx*4 + j; if (gn >= N) continue;
            C[(size_t)gm*N + gn] = acc[i][j] + (bias ? bias[gn] : 0.f);
        }
    }
}

__global__ void gemm_splitk(const float* __restrict__ A, const float* __restrict__ W,
                            float* __restrict__ Cp, int M, int N, int K, int kchunk) {
    __shared__ float As[16][64];
    __shared__ float Ws[16][64];
    int z = blockIdx.y;
    int ks = z * kchunk;
    int ke = min(K, ks + kchunk);
    int bn = blockIdx.x * 64;
    int tid = threadIdx.x;
    int tx = tid & 15, ty = tid >> 4;
    float acc[4][4] = {};
    int r  = tid >> 2;
    int kk = (tid & 3) * 4;
    for (int k0 = ks; k0 < ke; k0 += 16) {
        int gk = k0 + kk;
        float4 va = make_float4(0,0,0,0);
        if (r < M) {
            if (gk + 3 < ke) va = *reinterpret_cast<const float4*>(A + (size_t)r*K + gk);
            else { float t0=0,t1=0,t2=0,t3=0;
                   if (gk+0<ke) t0=A[(size_t)r*K+gk+0]; if (gk+1<ke) t1=A[(size_t)r*K+gk+1];
                   if (gk+2<ke) t2=A[(size_t)r*K+gk+2]; if (gk+3<ke) t3=A[(size_t)r*K+gk+3];
                   va = make_float4(t0,t1,t2,t3); }
        }
        As[kk+0][r]=va.x; As[kk+1][r]=va.y; As[kk+2][r]=va.z; As[kk+3][r]=va.w;
        float4 vw = make_float4(0,0,0,0);
        int gn = bn + r;
        if (gn < N) {
            if (gk + 3 < ke) vw = *reinterpret_cast<const float4*>(W + (size_t)gn*K + gk);
            else { float t0=0,t1=0,t2=0,t3=0;
                   if (gk+0<ke) t0=W[(size_t)gn*K+gk+0]; if (gk+1<ke) t1=W[(size_t)gn*K+gk+1];
                   if (gk+2<ke) t2=W[(size_t)gn*K+gk+2]; if (gk+3<ke) t3=W[(size_t)gn*K+gk+3];
                   vw = make_float4(t0,t1,t2,t3); }
        }
        Ws[kk+0][r]=vw.x; Ws[kk+1][r]=vw.y; Ws[kk+2][r]=vw.z; Ws[kk+3][r]=vw.w;
        __syncthreads();
        #pragma unroll
        for (int k = 0; k < 16; k++) {
            float4 a = *reinterpret_cast<const float4*>(&As[k][ty*4]);
            float4 b = *reinterpret_cast<const float4*>(&Ws[k][tx*4]);
            acc[0][0]+=a.x*b.x; acc[0][1]+=a.x*b.y; acc[0][2]+=a.x*b.z; acc[0][3]+=a.x*b.w;
            acc[1][0]+=a.y*b.x; acc[1][1]+=a.y*b.y; acc[1][2]+=a.y*b.z; acc[1][3]+=a.y*b.w;
            acc[2][0]+=a.z*b.x; acc[2][1]+=a.z*b.y; acc[2][2]+=a.z*b.z; acc[2][3]+=a.z*b.w;
            acc[3][0]+=a.w*b.x; acc[3][1]+=a.w*b.y; acc[3][2]+=a.w*b.z; acc[3][3]+=a.w*b.w;
        }
        __syncthreads();
    }
    float* Cz = Cp + (size_t)z*M*N;
    #pragma unroll
    for (int i = 0; i < 4; i++) {
        int gm = ty*4 + i; if (gm >= M) continue;
        #pragma unroll
        for (int j = 0; j < 4; j++) {
            int gn = bn + tx*4 + j; if (gn >= N) continue;
            Cz[(size_t)gm*N + gn] = acc[i][j];
        }
    }
}

// ---------------- encoder step gates ----------------
__global__ void enc_gates(const float* __restrict__ gxe, const float* __restrict__ ghp,
                          const float* __restrict__ bhh, float* __restrict__ h,
                          float* __restrict__ po, const int* __restrict__ post_length, int t) {
    int idx = blockIdx.x*blockDim.x + threadIdx.x;
    if (idx >= B*GH) return;
    int b = idx / GH, j = idx % GH;
    const float* gx = gxe + ((size_t)b*PL + t)*G3;
    float ghr = bhh[j], ghz = bhh[GH+j], ghn = bhh[2*GH+j];
    #pragma unroll
    for (int s = 0; s < 4; s++) {
        const float* p = ghp + ((size_t)s*B + b)*G3;
        ghr += p[j]; ghz += p[GH+j]; ghn += p[2*GH+j];
    }
    float r = sigmoidf_(gx[j] + ghr);
    float z = sigmoidf_(gx[GH+j] + ghz);
    float n = tanhf(gx[2*GH+j] + r*ghn);
    float hold = h[idx];
    float hn = (1.f - z)*n + z*hold;
    bool valid = t < post_length[b];
    h[idx] = valid ? hn : hold;
    po[((size_t)b*PL + t)*GH + j] = valid ? hn : 0.f;
}

// ---------------- decoder: prev-gates + attention + misc (one block per b) ---------
__global__ void __launch_bounds__(256) dec_am(
        float* __restrict__ din2, const float* __restrict__ po,
        const float* __restrict__ cp, const float* __restrict__ gxrv_prev,
        const float* __restrict__ bhh,
        const float* __restrict__ wb_w, const float* __restrict__ wb_b,
        const float* __restrict__ wc_w, const float* __restrict__ wc_b,
        const float* __restrict__ vb_w, const float* __restrict__ vb_b,
        const float* __restrict__ ubg, const float* __restrict__ sg,
        float* __restrict__ q, float* __restrict__ da,
        float* __restrict__ Z, int t, int do_gates) {
    int b = blockIdx.x, tid = threadIdx.x;
    int lane = tid & 31, wid = tid >> 5;
    __shared__ float hs[GH];
    __shared__ float sc2[256];
    __shared__ float sc[PL];
    __shared__ float al[PL];
    __shared__ float wbh[HID];
    __shared__ float dls[NT];
    __shared__ float das[NT];
    if (do_gates) {
        #pragma unroll
        for (int jj = 0; jj < 2; jj++) {
            int j = jj*256 + tid;
            float cr = 0.f, cz = 0.f, cxn = 0.f, chn = 0.f;
            #pragma unroll
            for (int z = 0; z < 8; z++) {
                const float* p = cp + ((size_t)z*B + b)*G4;
                cr += p[j]; cz += p[512+j]; cxn += p[1024+j]; chn += p[1536+j];
            }
            const float* gr = gxrv_prev + (size_t)b*G3;
            float r  = sigmoidf_(cr + gr[j] + bhh[j]);
            float zz = sigmoidf_(cz + gr[GH+j] + bhh[GH+j]);
            float n  = tanhf(cxn + gr[2*GH+j] + r*(chn + bhh[2*GH+j]));
            float hold = din2[(size_t)b*KC + 1012 + j];
            float hn = (1.f - zz)*n + zz*hold;
            din2[(size_t)b*KC + 1012 + j] = hn;
            Z[((size_t)(t-1)*B + b)*KD + j] = hn;
            hs[j] = hn;
        }
        __syncthreads();
    } else {
        for (int i = tid; i < GH; i += 256) hs[i] = din2[(size_t)b*KC + 1012 + i];
        __syncthreads();
    }
    {
        int p = tid >> 1, hf = tid & 1;
        const float* row = po + ((size_t)b*PL + p)*GH + hf*256;
        const float* h2 = hs + hf*256;
        float s = 0.f;
        for (int k = 0; k < 256; k += 4) {
            float4 v = *reinterpret_cast<const float4*>(row + k);
            s += v.x*h2[k] + v.y*h2[k+1] + v.z*h2[k+2] + v.w*h2[k+3];
        }
        sc2[tid] = s;
    }
    __syncthreads();
    if (tid < PL) sc[tid] = sc2[2*tid] + sc2[2*tid+1];
    __syncthreads();
    for (int j = tid; j < 400; j += 256) {
        const float* w;
        float acc;
        if (j < 300) { acc = wc_b[j]; w = wc_w + (size_t)j*GH; }
        else         { acc = wb_b[j-300]; w = wb_w + (size_t)(j-300)*GH; }
        for (int k = 0; k < GH; k += 4) {
            float4 v = *reinterpret_cast<const float4*>(w + k);
            acc += v.x*hs[k] + v.y*hs[k+1] + v.z*hs[k+2] + v.w*hs[k+3];
        }
        if (j < 300) q[(size_t)b*300 + j] = acc;
        else wbh[j-300] = acc;
    }
    if (wid == 0) {
        float v0 = sc[lane], v1 = sc[lane+32], v2 = sc[lane+64], v3 = sc[lane+96];
        float m = fmaxf(fmaxf(v0, v1), fmaxf(v2, v3));
        for (int o = 16; o; o >>= 1) m = fmaxf(m, __shfl_xor_sync(0xffffffffu, m, o));
        float e0 = expf(v0-m), e1 = expf(v1-m), e2 = expf(v2-m), e3 = expf(v3-m);
        float s = e0+e1+e2+e3;
        for (int o = 16; o; o >>= 1) s += __shfl_xor_sync(0xffffffffu, s, o);
        float inv = 1.f/s;
        al[lane] = e0*inv; al[lane+32] = e1*inv; al[lane+64] = e2*inv; al[lane+96] = e3*inv;
    }
    __syncthreads();
    for (int d = tid; d < GH; d += 256) {
        float acc = 0.f;
        for (int p = 0; p < PL; p++) acc += al[p]*po[((size_t)b*PL + p)*GH + d];
        din2[(size_t)b*KC + d] = acc;
    }
    if (tid < NT) {
        float s = 0.f;
        const float* u = ubg + ((size_t)b*NT + tid)*HID;
        for (int j = 0; j < HID; j++) s += vb_w[j]*tanhf(wbh[j] + u[j]);
        dls[tid] = s + vb_b[0];
    }
    __syncthreads();
    if (wid == 0) {
        float a0 = (lane < NT) ? dls[lane] : -1e30f;
        float a1 = (lane+32 < NT) ? dls[lane+32] : -1e30f;
        float m = fmaxf(a0, a1);
        for (int o = 16; o; o >>= 1) m = fmaxf(m, __shfl_xor_sync(0xffffffffu, m, o));
        float e0 = (lane < NT) ? expf(a0-m) : 0.f;
        float e1 = (lane+32 < NT) ? expf(a1-m) : 0.f;
        float s = e0 + e1;
        for (int o = 16; o; o >>= 1) s += __shfl_xor_sync(0xffffffffu, s, o);
        float inv = 1.f/s;
        if (lane < NT)    { das[lane] = e0*inv;    da[(size_t)b*NT + lane] = e0*inv; }
        if (lane+32 < NT) { das[lane+32] = e1*inv; da[(size_t)b*NT + lane+32] = e1*inv; }
    }
    __syncthreads();
    float* zrow = Z + ((size_t)t*B + b)*KD;
    for (int d = tid; d < 200; d += 256) {
        float s = 0.f;
        for (int n = 0; n < NT; n++) s += das[n]*sg[((size_t)b*NT + n)*200 + d];
        din2[(size_t)b*KC + 512 + d] = s;
        zrow[512 + d] = s;
    }
}

// ---------------- triple attention: partial over n-chunks, fp16 tef ----------------
__global__ void __launch_bounds__(256) dec_tv_part(
        const __half* __restrict__ tef16, const float* __restrict__ q,
        const float* __restrict__ da, float* __restrict__ tvp) {
    int b = blockIdx.x, ch = blockIdx.y;
    int tid = threadIdx.x, lane = tid & 31, wid = tid >> 5;
    __shared__ float qs[300];
    __shared__ float sw[10*NP];
    __shared__ float dal[10];
    for (int i = tid; i < 300; i += 256) qs[i] = q[(size_t)b*300 + i];
    if (tid < 10) dal[tid] = da[(size_t)b*NT + ch*10 + tid];
    __syncthreads();
    const __half* tb = tef16 + ((size_t)b*NT + ch*10)*NP*300;
    #pragma unroll
    for (int it = 0; it < 25; it++) {
        int pair = wid + 8*it;
        const __half* row = tb + (size_t)pair*300;
        float s = 0.f;
        for (int k2 = lane; k2 < 150; k2 += 32) {
            __half2 hv = *reinterpret_cast<const __half2*>(row + 2*k2);
            float2 fv = __half22float2(hv);
            s += fv.x*qs[2*k2] + fv.y*qs[2*k2+1];
        }
        #pragma unroll
        for (int o = 16; o; o >>= 1) s += __shfl_down_sync(0xffffffffu, s, o);
        if (lane == 0) sw[pair] = s;
    }
    __syncthreads();
    for (int n = wid; n < 10; n += 8) {
        float v = (lane < NP) ? sw[n*NP + lane] : -1e30f;
        float m = v;
        for (int o = 16; o; o >>= 1) m = fmaxf(m, __shfl_xor_sync(0xffffffffu, m, o));
        float e = (lane < NP) ? expf(v - m) : 0.f;
        float su = e;
        for (int o = 16; o; o >>= 1) su += __shfl_xor_sync(0xffffffffu, su, o);
        if (lane < NP) sw[n*NP + lane] = e * dal[n] / su;
    }
    __syncthreads();
    for (int d = tid; d < 300; d += 256) {
        float acc = 0.f;
        #pragma unroll 8
        for (int r = 0; r < 200; r++) acc += sw[r]*__half2float(tb[(size_t)r*300 + d]);
        tvp[((size_t)b*NCH + ch)*300 + d] = acc;
    }
}

__global__ void dec_tvsum(const float* __restrict__ tvp, float* __restrict__ din2,
                          float* __restrict__ Z, int t) {
    int b = blockIdx.x, d = threadIdx.x;
    float s = 0.f;
    #pragma unroll
    for (int ch = 0; ch < NCH; ch++) s += tvp[((size_t)b*NCH + ch)*300 + d];
    din2[(size_t)b*KC + 712 + d] = s;
    Z[((size_t)t*B + b)*KD + 712 + d] = s;
}

// final gates for last decoder step
__global__ void dec_gates2(const float* __restrict__ cp, const float* __restrict__ gxrv_t,
                           const float* __restrict__ bhh, float* __restrict__ din2,
                           float* __restrict__ Z, int t) {
    int idx = blockIdx.x*blockDim.x + threadIdx.x;
    if (idx >= B*GH) return;
    int b = idx / GH, j = idx % GH;
    float cr = 0.f, cz = 0.f, cxn = 0.f, chn = 0.f;
    #pragma unroll
    for (int z = 0; z < 8; z++) {
        const float* p = cp + ((size_t)z*B + b)*G4;
        cr += p[j]; cz += p[512+j]; cxn += p[1024+j]; chn += p[1536+j];
    }
    const float* gr = gxrv_t + (size_t)b*G3;
    float r  = sigmoidf_(cr + gr[j] + bhh[j]);
    float zz = sigmoidf_(cz + gr[GH+j] + bhh[GH+j]);
    float n  = tanhf(cxn + gr[2*GH+j] + r*(chn + bhh[2*GH+j]));
    float hold = din2[(size_t)b*KC + 1012 + j];
    float hn = (1.f - zz)*n + zz*hold;
    din2[(size_t)b*KC + 1012 + j] = hn;
    Z[((size_t)t*B + b)*KD + j] = hn;
}

// ---------------- fp16 split prep ----------------
// W: [bh] only (deduped), KW cols
__global__ void k_split_W(const float* __restrict__ W, __half* __restrict__ Ws) {
    size_t i = (size_t)blockIdx.x*blockDim.x + threadIdx.x;
    size_t total = (size_t)VW*(KW/8);
    if (i >= total) return;
    int cg = (int)(i % (KW/8));
    size_t r = i / (KW/8);
    int c0 = cg*8;
    __half o[8];
    #pragma unroll
    for (int e = 0; e < 8; e++) {
        int c = c0 + e;
        o[e] = (c < KSEG) ? __float2half(W[r*KSEG + c]) : __float2half(0.f);
    }
    *reinterpret_cast<uint4*>(Ws + r*KW + c0) = *reinterpret_cast<uint4*>(o);
}

// A: [ah(KW) | al(KW)] from fp32 Z
__global__ void k_split_Z(const float* __restrict__ Z, __half* __restrict__ As_) {
    size_t i = (size_t)blockIdx.x*blockDim.x + threadIdx.x;
    size_t total = (size_t)MP*(KPA/8);
    if (i >= total) return;
    int cg = (int)(i % (KPA/8));
    int m = (int)(i / (KPA/8));
    int b = m / TDEC, t = m - b*TDEC;
    int c0 = cg*8;
    __half o[8];
    #pragma unroll
    for (int e = 0; e < 8; e++) {
        int c = c0 + e;
        int lo = (c >= KW);
        int kc = lo ? (c - KW) : c;
        __half v = __float2half(0.f);
        if (b < B && kc < KSEG) {
            float zv = Z[((size_t)t*B + b)*KD + kc];
            __half hh = __float2half(zv);
            if (lo) v = __float2half(zv - __half2float(hh));
            else v = hh;
        }
        o[e] = v;
    }
    *reinterpret_cast<uint4*>(As_ + (size_t)m*KPA + c0) = *reinterpret_cast<uint4*>(o);
}

// ---------------- mma.sync fp16 vocab GEMM: 256x128 tile, B deduped, 3-stage --------
__global__ void __launch_bounds__(256) vocab_mma(
        const __half* __restrict__ Ag, const __half* __restrict__ Wg,
        const float* __restrict__ bout, float* __restrict__ out) {
    extern __shared__ __align__(16) char sraw[];
    const int tid = threadIdx.x;
    const int wid = tid >> 5, lane = tid & 31;
    const int m0 = blockIdx.x * VTM, n0 = blockIdx.y * VTN;
    const int wm = (wid >> 1) * 64, wn = (wid & 1) * 64;
    const int g = lane >> 2, tg = lane & 3;
    const uint32_t sb = smem_u32(sraw);

    float acc[4][8][4];
    #pragma unroll
    for (int i = 0; i < 4; i++)
    #pragma unroll
    for (int j = 0; j < 8; j++) { acc[i][j][0]=0.f; acc[i][j][1]=0.f; acc[i][j][2]=0.f; acc[i][j][3]=0.f; }

    auto load_stage = [&](int s, int k0) {
        uint32_t base = sb + (uint32_t)s*VSTAGE;
        #pragma unroll
        for (int i = 0; i < 10; i++) {
            int c = i*256 + tid;                  // 0..2559: A0 1024, A1 1024, B 512
            uint32_t roff; const __half* src;
            if (c < 1024) {
                int row = c >> 2, ch = c & 3;
                roff = (uint32_t)row*(SSTRIDE*2) + (uint32_t)ch*16u;
                src = Ag + (size_t)(m0+row)*KPA + k0 + ch*8;
            } else if (c < 2048) {
                int cc = c - 1024; int row = cc >> 2, ch = cc & 3;
                roff = VA_HALF + (uint32_t)row*(SSTRIDE*2) + (uint32_t)ch*16u;
                src = Ag + (size_t)(m0+row)*KPA + KW + k0 + ch*8;
            } else {
                int cc = c - 2048; int row = cc >> 2, ch = cc & 3;
                roff = 2*VA_HALF + (uint32_t)row*(SSTRIDE*2) + (uint32_t)ch*16u;
                src = Wg + (size_t)(n0+row)*KW + k0 + ch*8;
            }
            asm volatile("cp.async.cg.shared.global [%0], [%1], 16;" :: "r"(base + roff), "l"(src));
        }
        asm volatile("cp.async.commit_group;" ::: "memory");
    };

    load_stage(0, 0); load_stage(1, 32); load_stage(2, 64);

    const int a_row = lane & 15;
    const int a_k8  = (lane >> 4) << 3;
    const int b_row = lane & 7;
    const int b_k8  = ((lane >> 3) & 1) << 3;
    const int b_ni  = lane >> 4;

    const int NIT = KW/32;                 // 51
    for (int kt = 0; kt < NIT; kt++) {
        if (kt + 3 < NIT) { asm volatile("cp.async.wait_group 2;" ::: "memory"); }
        else              { asm volatile("cp.async.wait_group 0;" ::: "memory"); }
        __syncthreads();
        int s = kt % 3;
        uint32_t baseA0 = sb + (uint32_t)s*VSTAGE;
        uint32_t baseB  = baseA0 + 2*VA_HALF;
        #pragma unroll
        for (int kk = 0; kk < 2; kk++) {
            uint32_t bfr[8][2];
            #pragma unroll
            for (int ni = 0; ni < 8; ni += 2) {
                uint32_t bd = baseB + ((uint32_t)(wn + (ni + b_ni)*8 + b_row)*SSTRIDE
                                       + (uint32_t)(kk*16 + b_k8))*2u;
                asm volatile("ldmatrix.sync.aligned.m8n8.x4.shared.b16 {%0,%1,%2,%3}, [%4];"
                    : "=r"(bfr[ni][0]),"=r"(bfr[ni][1]),"=r"(bfr[ni+1][0]),"=r"(bfr[ni+1][1])
                    : "r"(bd));
            }
            #pragma unroll
            for (int half = 0; half < 2; half++) {
                uint32_t baseA = baseA0 + (uint32_t)half*VA_HALF;
                uint32_t afr[4][4];
                #pragma unroll
                for (int mi = 0; mi < 4; mi++) {
                    uint32_t ad = baseA + ((uint32_t)(wm + mi*16 + a_row)*SSTRIDE
                                           + (uint32_t)(kk*16 + a_k8))*2u;
                    asm volatile("ldmatrix.sync.aligned.m8n8.x4.shared.b16 {%0,%1,%2,%3}, [%4];"
                        : "=r"(afr[mi][0]),"=r"(afr[mi][1]),"=r"(afr[mi][2]),"=r"(afr[mi][3])
                        : "r"(ad));
                }
                #pragma unroll
                for (int mi = 0; mi < 4; mi++)
                #pragma unroll
                for (int ni = 0; ni < 8; ni++) {
                    asm volatile(
                      "mma.sync.aligned.m16n8k16.row.col.f32.f16.f16.f32 "
                      "{%0,%1,%2,%3},{%4,%5,%6,%7},{%8,%9},{%0,%1,%2,%3};"
                      : "+f"(acc[mi][ni][0]), "+f"(acc[mi][ni][1]),
                        "+f"(acc[mi][ni][2]), "+f"(acc[mi][ni][3])
                      : "r"(afr[mi][0]),"r"(afr[mi][1]),"r"(afr[mi][2]),"r"(afr[mi][3]),
                        "r"(bfr[ni][0]),"r"(bfr[ni][1]));
                }
            }
        }
        __syncthreads();
        if (kt + 3 < NIT) load_stage(s, (kt+3)*32);
    }
    __syncthreads();

    float* Ds = (float*)sraw;
    #pragma unroll
    for (int h = 0; h < 2; h++) {
        if ((wid >> 2) == h) {
            int mbase = wm - h*128;
            #pragma unroll
            for (int mi = 0; mi < 4; mi++) {
                int mA = mbase + mi*16 + g;
                #pragma unroll
                for (int ni = 0; ni < 8; ni++) {
                    int nn = wn + ni*8 + tg*2;
                    Ds[mA*129 + nn]         = acc[mi][ni][0];
                    Ds[mA*129 + nn + 1]     = acc[mi][ni][1];
                    Ds[(mA+8)*129 + nn]     = acc[mi][ni][2];
                    Ds[(mA+8)*129 + nn + 1] = acc[mi][ni][3];
                }
            }
        }
        __syncthreads();
        for (int idx = tid; idx < VTN*128; idx += 256) {
            int n = idx >> 7, m = idx & 127;
            int mg = m0 + h*128 + m;
            if (mg < B*TDEC) {
                int bb = mg / TDEC, tt = mg - bb*TDEC;
                int ng = n0 + n;
                out[(size_t)bb*VW*TDEC + (size_t)ng*TDEC + tt] = Ds[m*129 + n] + __ldg(bout + ng);
            }
        }
        __syncthreads();
    }
}

// ---------------- launch ----------------
extern "C" void kernel_launch(void* const* d_in, const int* in_sizes, int n_in,
                              void* d_out, int out_size) {
    const float* word_emb   = (const float*)d_in[0];
    const float* transe_emb = (const float*)d_in[1];
    const float* wh_w = (const float*)d_in[2];  const float* wh_b = (const float*)d_in[3];
    const float* wr_w = (const float*)d_in[4];  const float* wr_b = (const float*)d_in[5];
    const float* wt_w = (const float*)d_in[6];  const float* wt_b = (const float*)d_in[7];
    const float* wb_w = (const float*)d_in[8];  const float* wb_b = (const float*)d_in[9];
    const float* ub_w = (const float*)d_in[10]; const float* ub_b = (const float*)d_in[11];
    const float* vb_w = (const float*)d_in[12]; const float* vb_b = (const float*)d_in[13];
    const float* wc_w = (const float*)d_in[14]; const float* wc_b = (const float*)d_in[15];
    const float* Wih_e = (const float*)d_in[16]; const float* Whh_e = (const float*)d_in[17];
    const float* bih_e = (const float*)d_in[18]; const float* bhh_e = (const float*)d_in[19];
    const float* Wih_d = (const float*)d_in[20]; const float* Whh_d = (const float*)d_in[21];
    const float* bih_d = (const float*)d_in[22]; const float* bhh_d = (const float*)d_in[23];
    const float* out_w = (const float*)d_in[24]; const float* out_b = (const float*)d_in[25];
    const int* post          = (const int*)d_in[26];
    const int* post_length   = (const int*)d_in[27];
    const int* response      = (const int*)d_in[28];
    const int* resp_triple   = (const int*)d_in[29];
    const int* post_triple   = (const int*)d_in[30];
    const int* triple        = (const int*)d_in[31];
    float* out = (float*)d_out;

    void* basep = nullptr; cudaGetSymbolAddress(&basep, g_buf);
    float* base = (float*)basep;
    void* wsp = nullptr; cudaGetSymbolAddress(&wsp, g_Ws);
    void* asp = nullptr; cudaGetSymbolAddress(&asp, g_As);
    void* t16p = nullptr; cudaGetSymbolAddress(&t16p, g_tef16);
    __half* Ws = (__half*)wsp;
    __half* As = (__half*)asp;
    __half* tef16 = (__half*)t16p;

    float* tef  = base + OFF_TEF;
    float* sl   = base + OFF_SL;
    float* sg   = base + OFF_SG;
    float* ubg  = base + OFF_UBG;
    float* pin  = base + OFF_PIN;
    float* gxe  = base + OFF_GXE;
    float* po   = base + OFF_PO;
    float* h    = base + OFF_H;
    float* rv   = base + OFF_RV;
    float* Z    = base + OFF_Z;
    float* din2 = base + OFF_DIN2;
    float* q    = base + OFF_Q;
    float* da   = base + OFF_DA;
    float* cp   = base + OFF_CP;
    float* ghp  = base + OFF_GHP;
    float* gxrv = base + OFF_GXRV;
    float* Wcb  = base + OFF_WCB;
    float* Wrv  = base + OFF_WRV;
    float* tvp  = base + OFF_TVP;

    cudaFuncSetAttribute(vocab_mma, cudaFuncAttributeMaxDynamicSharedMemorySize, VSMEM);

    // ---- phase A ----
    k_zero<<<(unsigned)((SZ_H + 255)/256), 256>>>(h, SZ_H);
    {
        size_t n4 = (size_t)B*NT*NP*3*25;
        k_gather_tef<<<(unsigned)((n4 + 255)/256), 256>>>(transe_emb, triple, tef, tef16);
    }
    {
        size_t n4 = (size_t)TDEC*B*150;
        k_gather_rv<<<(unsigned)((n4 + 255)/256), 256>>>(word_emb, transe_emb, response, resp_triple, rv, Z);
    }
    {
        size_t nsp = (size_t)VW*(KW/8);
        k_split_W<<<(unsigned)((nsp + 255)/256), 256>>>(out_w, Ws);
    }
    {
        size_t n = (size_t)G4*KC;
        k_build_wcomb<<<(unsigned)((n + 255)/256), 256>>>(Wih_d, Whh_d, Wcb);
    }
    {
        size_t n = (size_t)G3*600;
        k_build_wrv<<<(unsigned)((n + 255)/256), 256>>>(Wih_d, Wrv);
    }
    k_triple_score<<<B*NT*NP, 128>>>(tef, triple, wh_w, wh_b, wr_w, wr_b, wt_w, wt_b, sl);
    k_graph_softmax<<<B*NT, 64>>>(sl, tef, sg);
    k_ubg<<<B*NT, 128>>>(sg, ub_w, ub_b, ubg);
    {
        size_t n4 = (size_t)B*PL*125;
        k_post_in<<<(unsigned)((n4 + 255)/256), 256>>>(word_emb, sg, post, post_triple, pin);
    }
    gemm_bias<<<dim3((B*PL)/64, G3/64), 256>>>(pin, Wih_e, bih_e, gxe, B*PL, G3, KE);
    gemm_bias<<<dim3((TDEC*B)/64, G3/64), 256>>>(rv, Wrv, bih_d, gxrv, TDEC*B, G3, 600);

    // ---- phase B: encoder recurrence (proven R11 structure) ----
    for (int t = 0; t < PL; t++) {
        gemm_splitk<<<dim3(G3/64, 4), 256>>>(h, Whh_e, ghp, B, G3, GH, 128);
        enc_gates<<<(B*GH)/256, 256>>>(gxe, ghp, bhh_e, h, po, post_length, t);
    }
    k_h2din2<<<(B*GH)/256, 256>>>(h, din2);

    // ---- phase C: decoder recurrence (proven R11 structure) ----
    for (int t = 0; t < TDEC; t++) {
        const float* gxrv_prev = (t > 0) ? (gxrv + (size_t)(t-1)*B*G3) : gxrv;
        dec_am<<<B, 256>>>(din2, po, cp, gxrv_prev, bhh_d,
                           wb_w, wb_b, wc_w, wc_b, vb_w, vb_b,
                           ubg, sg, q, da, Z, t, t > 0 ? 1 : 0);
        dec_tv_part<<<dim3(B, NCH), 256>>>(tef16, q, da, tvp);
        dec_tvsum<<<B, 300>>>(tvp, din2, Z, t);
        gemm_splitk<<<dim3(G4/64, 8), 256>>>(din2, Wcb, cp, B, G4, KC, 192);
    }
    dec_gates2<<<(B*GH)/256, 256>>>(cp, gxrv + (size_t)(TDEC-1)*B*G3, bhh_d, din2, Z, TDEC-1);

    // ---- phase D: split Z + vocab projection (B-deduped) ----
    {
        size_t nsp = (size_t)MP*(KPA/8);
        k_split_Z<<<(unsigned)((nsp + 255)/256), 256>>>(Z, As);
    }
    vocab_mma<<<dim3(MP/VTM, VW/VTN), 256, VSMEM>>>(As, Ws, out_b, out);
}

// round 14
// speedup vs baseline: 1.4245x; 1.0550x over previous
#include <cuda_runtime.h>
#include <cuda_fp16.h>
#include <cstdint>
#include <math.h>

// ---------------- problem dims ----------------
#define B    64
#define PL   128
#define RL   64
#define TDEC 63
#define NT   50
#define NP   20
#define TE   100
#define HID  100
#define GH   512
#define G3   1536
#define G4   2048        // 4 gate-row groups for combined decoder GEMM
#define DE   300
#define VW   32000
#define KE   500
#define KD   1612        // logits input dim [hn,dg,tv,rv]
#define KC   1524        // combined decoder GEMM K = 1012 (cv,dg,tv) + 512 (h)
#define NEGV -1000000000.0f
#define NCH  5           // tv n-chunks (10 triples each)

// ---- fp16 2-term split vocab GEMM: A=[ah|al] (KPA), B=[bh] (KW, deduped) ----
#define KSEG 1612
#define KW   1632        // unique K (1612 padded to 32)
#define KPA  3264        // A row: [ah(1632) | al(1632)]
#define MP   4096
#define SSTRIDE 40       // smem row stride in fp16 (32 data + 8 pad)
#define VTM  256
#define VTN  128
#define VA_HALF (256*SSTRIDE*2)           // 20480 per A half
#define VB_SZ   (128*SSTRIDE*2)           // 10240
#define VSTAGE  (2*VA_HALF + VB_SZ)       // 51200
#define VSMEM   (3*VSTAGE)                // 153600

// ---- generic fp16 2-term prep GEMM (128x128 tile) ----
#define GSTAGE  (2*128*SSTRIDE*2)         // A(10240)+B(10240) = 20480

// ---------------- scratch ----------------
constexpr size_t SZ_TEF = (size_t)B*NT*NP*300;
constexpr size_t SZ_SL  = (size_t)B*NT*NP;
constexpr size_t SZ_SG  = (size_t)B*NT*200;
constexpr size_t SZ_UBG = (size_t)B*NT*100;
constexpr size_t SZ_PIN = (size_t)B*PL*KE;
constexpr size_t SZ_GXE = (size_t)B*PL*G3;
constexpr size_t SZ_PO  = (size_t)B*PL*GH;
constexpr size_t SZ_H   = (size_t)B*GH;
constexpr size_t SZ_RV  = (size_t)TDEC*B*600;
constexpr size_t SZ_Z   = (size_t)TDEC*B*KD;
constexpr size_t SZ_DIN2= (size_t)B*KC;
constexpr size_t SZ_Q   = (size_t)B*300;
constexpr size_t SZ_DA  = (size_t)B*NT;
constexpr size_t SZ_CP  = (size_t)8*B*G4;
constexpr size_t SZ_GHP = (size_t)4*B*G3;
constexpr size_t SZ_GXRV= (size_t)TDEC*B*G3;
constexpr size_t SZ_WCB = (size_t)G4*KC;
constexpr size_t SZ_TVP = (size_t)B*NCH*300;

constexpr size_t OFF_TEF = 0;
constexpr size_t OFF_SL  = OFF_TEF + SZ_TEF;
constexpr size_t OFF_SG  = OFF_SL  + SZ_SL;
constexpr size_t OFF_UBG = OFF_SG  + SZ_SG;
constexpr size_t OFF_PIN = OFF_UBG + SZ_UBG;
constexpr size_t OFF_GXE = OFF_PIN + SZ_PIN;
constexpr size_t OFF_PO  = OFF_GXE + SZ_GXE;
constexpr size_t OFF_H   = OFF_PO  + SZ_PO;
constexpr size_t OFF_RV  = OFF_H   + SZ_H;
constexpr size_t OFF_Z   = OFF_RV  + SZ_RV;
constexpr size_t OFF_DIN2= OFF_Z   + SZ_Z;
constexpr size_t OFF_Q   = OFF_DIN2+ SZ_DIN2;
constexpr size_t OFF_DA  = OFF_Q   + SZ_Q;
constexpr size_t OFF_CP  = OFF_DA  + SZ_DA;
constexpr size_t OFF_GHP = OFF_CP  + SZ_CP;
constexpr size_t OFF_GXRV= OFF_GHP + SZ_GHP;
constexpr size_t OFF_WCB = OFF_GXRV+ SZ_GXRV;
constexpr size_t OFF_TVP = OFF_WCB + SZ_WCB;
constexpr size_t SZ_TOTAL = OFF_TVP + SZ_TVP;

__device__ float g_buf[SZ_TOTAL];
__device__ __align__(16) __half g_Ws[(size_t)VW * KW];
__device__ __align__(16) __half g_As[(size_t)MP * KPA];   // also reused as prep-GEMM A scratch
__device__ __align__(16) __half g_W2[(size_t)G3 * 1216];  // prep-GEMM W scratch (max K2=1216)
__device__ __align__(16) __half g_tef16[SZ_TEF];

__device__ __forceinline__ float sigmoidf_(float x) { return 1.0f / (1.0f + expf(-x)); }
__device__ __forceinline__ uint32_t smem_u32(const void* p) {
    uint32_t a;
    asm("{ .reg .u64 t; cvta.to.shared.u64 t, %1; cvt.u32.u64 %0, t; }" : "=r"(a) : "l"(p));
    return a;
}

// ---------------- small utility kernels ----------------
__global__ void k_zero(float* p, size_t n) {
    size_t i = (size_t)blockIdx.x*blockDim.x + threadIdx.x;
    if (i < n) p[i] = 0.f;
}

__global__ void k_gather_tef(const float* __restrict__ te, const int* __restrict__ triple,
                             float* __restrict__ tef, __half* __restrict__ tef16) {
    size_t i = (size_t)blockIdx.x*blockDim.x + threadIdx.x;
    size_t total = (size_t)B*NT*NP*3*25;
    if (i >= total) return;
    size_t ent = i / 25; int off = (int)(i % 25) * 4;
    size_t tri = ent / 3; int e = (int)(ent % 3);
    int idx = triple[ent];
    float4 v = *reinterpret_cast<const float4*>(te + (size_t)idx*TE + off);
    size_t dst = tri*300 + e*100 + off;
    *reinterpret_cast<float4*>(tef + dst) = v;
    __half h4[4];
    h4[0] = __float2half(v.x); h4[1] = __float2half(v.y);
    h4[2] = __float2half(v.z); h4[3] = __float2half(v.w);
    *reinterpret_cast<uint2*>(tef16 + dst) = *reinterpret_cast<uint2*>(h4);
}

__global__ void k_gather_rv(const float* __restrict__ we, const float* __restrict__ te,
                            const int* __restrict__ resp, const int* __restrict__ rtrip,
                            float* __restrict__ rv, float* __restrict__ Z) {
    size_t i = (size_t)blockIdx.x*blockDim.x + threadIdx.x;
    size_t total = (size_t)TDEC*B*150;
    if (i >= total) return;
    size_t tb = i / 150; int f = (int)(i % 150);
    int t = (int)(tb / B), b = (int)(tb % B);
    float4 v;
    if (f < 75) {
        int w = resp[b*RL + t];
        v = *reinterpret_cast<const float4*>(we + (size_t)w*DE + f*4);
    } else {
        int f2 = f - 75; int e = f2 / 25; int off = (f2 % 25) * 4;
        int idx = rtrip[((size_t)b*RL + t)*3 + e];
        v = *reinterpret_cast<const float4*>(te + (size_t)idx*TE + off);
    }
    *reinterpret_cast<float4*>(rv + tb*600 + f*4) = v;
    *reinterpret_cast<float4*>(Z + tb*KD + 1012 + f*4) = v;
}

__global__ void k_triple_score(const float* __restrict__ tef, const int* __restrict__ triple,
                               const float* __restrict__ wh_w, const float* __restrict__ wh_b,
                               const float* __restrict__ wr_w, const float* __restrict__ wr_b,
                               const float* __restrict__ wt_w, const float* __restrict__ wt_b,
                               float* __restrict__ sl) {
    int g = blockIdx.x;
    const float* tb = tef + (size_t)g*300;
    __shared__ float e[300];
    __shared__ float red[128];
    int tid = threadIdx.x;
    for (int i = tid; i < 300; i += 128) e[i] = tb[i];
    __syncthreads();
    float contrib = 0.f;
    if (tid < HID) {
        int j = tid;
        float a = wh_b[j] + wt_b[j];
        float r = wr_b[j];
        const float* whr = wh_w + (size_t)j*TE;
        const float* wtr = wt_w + (size_t)j*TE;
        const float* wrr = wr_w + (size_t)j*TE;
        #pragma unroll 4
        for (int k = 0; k < TE; k++) {
            a += e[k]*whr[k] + e[200+k]*wtr[k];
            r += e[100+k]*wrr[k];
        }
        contrib = r * tanhf(a);
    }
    red[tid] = contrib; __syncthreads();
    for (int s = 64; s; s >>= 1) { if (tid < s) red[tid] += red[tid+s]; __syncthreads(); }
    if (tid == 0)
        sl[g] = (triple[(size_t)g*3] == 0) ? NEGV : red[0];
}

__global__ void k_graph_softmax(const float* __restrict__ sl, const float* __restrict__ tef,
                                float* __restrict__ sg) {
    int g = blockIdx.x;
    int tid = threadIdx.x;
    __shared__ float sa[NP];
    if (tid == 0) {
        float m = -1e30f;
        for (int p = 0; p < NP; p++) m = fmaxf(m, sl[(size_t)g*NP + p]);
        float sum = 0.f;
        for (int p = 0; p < NP; p++) { float ev = expf(sl[(size_t)g*NP + p] - m); sa[p] = ev; sum += ev; }
        float inv = 1.f / sum;
        for (int p = 0; p < NP; p++) sa[p] *= inv;
    }
    __syncthreads();
    const float* tb = tef + (size_t)g*NP*300;
    for (int d = tid; d < 200; d += 64) {
        int dd = (d < 100) ? d : d + 100;
        float s = 0.f;
        #pragma unroll
        for (int p = 0; p < NP; p++) s += sa[p]*tb[(size_t)p*300 + dd];
        sg[(size_t)g*200 + d] = s;
    }
}

__global__ void k_ubg(const float* __restrict__ sg, const float* __restrict__ ub_w,
                      const float* __restrict__ ub_b, float* __restrict__ ubg) {
    int g = blockIdx.x;
    int tid = threadIdx.x;
    __shared__ float s[200];
    for (int i = tid; i < 200; i += 128) s[i] = sg[(size_t)g*200 + i];
    __syncthreads();
    if (tid < HID) {
        float acc = ub_b[tid];
        const float* w = ub_w + (size_t)tid*200;
        #pragma unroll 4
        for (int k = 0; k < 200; k++) acc += s[k]*w[k];
        ubg[(size_t)g*HID + tid] = acc;
    }
}

__global__ void k_post_in(const float* __restrict__ we, const float* __restrict__ sg,
                          const int* __restrict__ post, const int* __restrict__ ptrip,
                          float* __restrict__ pin) {
    size_t i = (size_t)blockIdx.x*blockDim.x + threadIdx.x;
    size_t total = (size_t)B*PL*125;
    if (i >= total) return;
    size_t bt = i / 125; int f = (int)(i % 125);
    float4 v;
    if (f < 75) {
        v = *reinterpret_cast<const float4*>(we + (size_t)post[bt]*DE + f*4);
    } else {
        int b = (int)(bt / PL);
        int n = ptrip[bt];
        v = *reinterpret_cast<const float4*>(sg + ((size_t)b*NT + n)*200 + (f-75)*4);
    }
    *reinterpret_cast<float4*>(pin + bt*KE + f*4) = v;
}

__global__ void k_build_wcomb(const float* __restrict__ Wih, const float* __restrict__ Whh,
                              float* __restrict__ Wc) {
    size_t i = (size_t)blockIdx.x*blockDim.x + threadIdx.x;
    if (i >= (size_t)G4*KC) return;
    int c = (int)(i % KC);
    int r = (int)(i / KC);
    float v = 0.f;
    if (r < 1024) {
        v = (c < 1012) ? Wih[(size_t)r*KD + c] : Whh[(size_t)r*GH + (c - 1012)];
    } else if (r < 1536) {
        if (c < 1012) v = Wih[(size_t)r*KD + c];
    } else {
        if (c >= 1012) v = Whh[(size_t)(r - 512)*GH + (c - 1012)];
    }
    Wc[i] = v;
}

__global__ void k_h2din2(const float* __restrict__ h, float* __restrict__ din2) {
    int i = blockIdx.x*blockDim.x + threadIdx.x;
    if (i >= B*GH) return;
    int b = i / GH, j = i % GH;
    din2[(size_t)b*KC + 1012 + j] = h[i];
}

// ---------------- fp16 2-term prep for generic GEMM ----------------
// A2 row: [ah(Kp) | al(Kp)], rows padded to Mp with zeros
__global__ void k_prep_h2A(const float* __restrict__ src, __half* __restrict__ dst,
                           int M, int Mp, int K, int Kp, int srcStride) {
    int vpr = (2*Kp) >> 3;
    size_t i = (size_t)blockIdx.x*blockDim.x + threadIdx.x;
    size_t total = (size_t)Mp * vpr;
    if (i >= total) return;
    int cg = (int)(i % vpr);
    int row = (int)(i / vpr);
    int c0 = cg*8;
    __half o[8];
    #pragma unroll
    for (int e = 0; e < 8; e++) {
        int c = c0 + e;
        int lo = (c >= Kp);
        int kc = lo ? (c - Kp) : c;
        __half v = __float2half(0.f);
        if (row < M && kc < K) {
            float x = src[(size_t)row*srcStride + kc];
            __half hh = __float2half(x);
            v = lo ? __float2half(x - __half2float(hh)) : hh;
        }
        o[e] = v;
    }
    *reinterpret_cast<uint4*>(dst + (size_t)row*(2*Kp) + c0) = *reinterpret_cast<uint4*>(o);
}

// W2 row: [wh(Kp) | wh(Kp)] from W[r*srcStride + co + k]
__global__ void k_prep_h2W(const float* __restrict__ W, __half* __restrict__ dst,
                           int N, int K, int Kp, int srcStride, int co) {
    int vpr = (2*Kp) >> 3;
    size_t i = (size_t)blockIdx.x*blockDim.x + threadIdx.x;
    size_t total = (size_t)N * vpr;
    if (i >= total) return;
    int cg = (int)(i % vpr);
    int r = (int)(i / vpr);
    int c0 = cg*8;
    __half o[8];
    #pragma unroll
    for (int e = 0; e < 8; e++) {
        int c = c0 + e;
        int kc = (c >= Kp) ? (c - Kp) : c;
        o[e] = (kc < K) ? __float2half(W[(size_t)r*srcStride + co + kc]) : __float2half(0.f);
    }
    *reinterpret_cast<uint4*>(dst + (size_t)r*(2*Kp) + c0) = *reinterpret_cast<uint4*>(o);
}

// ---------------- generic fp16 mma GEMM: C[M,N] = A2[Mp,K2] @ W2[N,K2]^T + bias ----
// 128x128 tile, 8 warps (2m x 4n), BK=32, 2-stage cp.async.  K2 = 2*Kp, mult of 64.
__global__ void __launch_bounds__(256) gemm_h16(
        const __half* __restrict__ A2, const __half* __restrict__ W2,
        const float* __restrict__ bias, float* __restrict__ C,
        int M, int N, int K2) {
    __shared__ __align__(16) char gsm[2*GSTAGE];
    const int tid = threadIdx.x;
    const int wid = tid >> 5, lane = tid & 31;
    const int m0 = blockIdx.x * 128, n0 = blockIdx.y * 128;
    const int wm = (wid >> 2) * 64, wn = (wid & 3) * 32;
    const int g = lane >> 2, tg = lane & 3;
    const uint32_t sb = smem_u32(gsm);

    float acc[4][4][4];
    #pragma unroll
    for (int i = 0; i < 4; i++)
    #pragma unroll
    for (int j = 0; j < 4; j++) { acc[i][j][0]=0.f; acc[i][j][1]=0.f; acc[i][j][2]=0.f; acc[i][j][3]=0.f; }

    auto load_stage = [&](int s, int k0) {
        uint32_t base = sb + (uint32_t)s*GSTAGE;
        #pragma unroll
        for (int i = 0; i < 4; i++) {
            int c = i*256 + tid;               // 0..1023: A 512, B 512
            int isB = (c >= 512); int cc = c & 511;
            int row = cc >> 2, ch = cc & 3;
            uint32_t dst = base + (isB ? (uint32_t)(128*SSTRIDE*2) : 0u)
                         + (uint32_t)row*(SSTRIDE*2) + (uint32_t)ch*16u;
            const __half* src = isB ? (W2 + (size_t)(n0+row)*K2 + k0 + ch*8)
                                    : (A2 + (size_t)(m0+row)*K2 + k0 + ch*8);
            asm volatile("cp.async.cg.shared.global [%0], [%1], 16;" :: "r"(dst), "l"(src));
        }
        asm volatile("cp.async.commit_group;" ::: "memory");
    };

    load_stage(0, 0); load_stage(1, 32);

    const int a_row = lane & 15;
    const int a_k8  = (lane >> 4) << 3;
    const int b_row = lane & 7;
    const int b_k8  = ((lane >> 3) & 1) << 3;
    const int b_ni  = lane >> 4;

    const int NIT = K2/32;
    for (int kt = 0; kt < NIT; kt++) {
        if (kt + 2 < NIT) { asm volatile("cp.async.wait_group 1;" ::: "memory"); }
        else              { asm volatile("cp.async.wait_group 0;" ::: "memory"); }
        __syncthreads();
        int s = kt & 1;
        uint32_t baseA = sb + (uint32_t)s*GSTAGE;
        uint32_t baseB = baseA + (uint32_t)(128*SSTRIDE*2);
        #pragma unroll
        for (int kk = 0; kk < 2; kk++) {
            uint32_t afr[4][4];
            #pragma unroll
            for (int mi = 0; mi < 4; mi++) {
                uint32_t ad = baseA + ((uint32_t)(wm + mi*16 + a_row)*SSTRIDE
                                       + (uint32_t)(kk*16 + a_k8))*2u;
                asm volatile("ldmatrix.sync.aligned.m8n8.x4.shared.b16 {%0,%1,%2,%3}, [%4];"
                    : "=r"(afr[mi][0]),"=r"(afr[mi][1]),"=r"(afr[mi][2]),"=r"(afr[mi][3])
                    : "r"(ad));
            }
            uint32_t bfr[4][2];
            #pragma unroll
            for (int ni = 0; ni < 4; ni += 2) {
                uint32_t bd = baseB + ((uint32_t)(wn + (ni + b_ni)*8 + b_row)*SSTRIDE
                                       + (uint32_t)(kk*16 + b_k8))*2u;
                asm volatile("ldmatrix.sync.aligned.m8n8.x4.shared.b16 {%0,%1,%2,%3}, [%4];"
                    : "=r"(bfr[ni][0]),"=r"(bfr[ni][1]),"=r"(bfr[ni+1][0]),"=r"(bfr[ni+1][1])
                    : "r"(bd));
            }
            #pragma unroll
            for (int mi = 0; mi < 4; mi++)
            #pragma unroll
            for (int ni = 0; ni < 4; ni++) {
                asm volatile(
                  "mma.sync.aligned.m16n8k16.row.col.f32.f16.f16.f32 "
                  "{%0,%1,%2,%3},{%4,%5,%6,%7},{%8,%9},{%0,%1,%2,%3};"
                  : "+f"(acc[mi][ni][0]), "+f"(acc[mi][ni][1]),
                    "+f"(acc[mi][ni][2]), "+f"(acc[mi][ni][3])
                  : "r"(afr[mi][0]),"r"(afr[mi][1]),"r"(afr[mi][2]),"r"(afr[mi][3]),
                    "r"(bfr[ni][0]),"r"(bfr[ni][1]));
            }
        }
        __syncthreads();
        if (kt + 2 < NIT) load_stage(s, (kt+2)*32);
    }

    #pragma unroll
    for (int mi = 0; mi < 4; mi++) {
        int gm = m0 + wm + mi*16 + g;
        #pragma unroll
        for (int ni = 0; ni < 4; ni++) {
            int gn = n0 + wn + ni*8 + tg*2;
            float b0 = bias[gn], b1 = bias[gn+1];
            if (gm < M) {
                C[(size_t)gm*N + gn]     = acc[mi][ni][0] + b0;
                C[(size_t)gm*N + gn + 1] = acc[mi][ni][1] + b1;
            }
            if (gm + 8 < M) {
                C[(size_t)(gm+8)*N + gn]     = acc[mi][ni][2] + b0;
                C[(size_t)(gm+8)*N + gn + 1] = acc[mi][ni][3] + b1;
            }
        }
    }
}

// ---------------- fp32 split-K GEMM (recurrent steps) ----------------
__global__ void gemm_splitk(const float* __restrict__ A, const float* __restrict__ W,
                            float* __restrict__ Cp, int M, int N, int K, int kchunk) {
    __shared__ float As[16][64];
    __shared__ float Ws[16][64];
    int z = blockIdx.y;
    int ks = z * kchunk;
    int ke = min(K, ks + kchunk);
    int bn = blockIdx.x * 64;
    int tid = threadIdx.x;
    int tx = tid & 15, ty = tid >> 4;
    float acc[4][4] = {};
    int r  = tid >> 2;
    int kk = (tid & 3) * 4;
    for (int k0 = ks; k0 < ke; k0 += 16) {
        int gk = k0 + kk;
        float4 va = make_float4(0,0,0,0);
        if (r < M) {
            if (gk + 3 < ke) va = *reinterpret_cast<const float4*>(A + (size_t)r*K + gk);
            else { float t0=0,t1=0,t2=0,t3=0;
                   if (gk+0<ke) t0=A[(size_t)r*K+gk+0]; if (gk+1<ke) t1=A[(size_t)r*K+gk+1];
                   if (gk+2<ke) t2=A[(size_t)r*K+gk+2]; if (gk+3<ke) t3=A[(size_t)r*K+gk+3];
                   va = make_float4(t0,t1,t2,t3); }
        }
        As[kk+0][r]=va.x; As[kk+1][r]=va.y; As[kk+2][r]=va.z; As[kk+3][r]=va.w;
        float4 vw = make_float4(0,0,0,0);
        int gn = bn + r;
        if (gn < N) {
            if (gk + 3 < ke) vw = *reinterpret_cast<const float4*>(W + (size_t)gn*K + gk);
            else { float t0=0,t1=0,t2=0,t3=0;
                   if (gk+0<ke) t0=W[(size_t)gn*K+gk+0]; if (gk+1<ke) t1=W[(size_t)gn*K+gk+1];
                   if (gk+2<ke) t2=W[(size_t)gn*K+gk+2]; if (gk+3<ke) t3=W[(size_t)gn*K+gk+3];
                   vw = make_float4(t0,t1,t2,t3); }
        }
        Ws[kk+0][r]=vw.x; Ws[kk+1][r]=vw.y; Ws[kk+2][r]=vw.z; Ws[kk+3][r]=vw.w;
        __syncthreads();
        #pragma unroll
        for (int k = 0; k < 16; k++) {
            float4 a = *reinterpret_cast<const float4*>(&As[k][ty*4]);
            float4 b = *reinterpret_cast<const float4*>(&Ws[k][tx*4]);
            acc[0][0]+=a.x*b.x; acc[0][1]+=a.x*b.y; acc[0][2]+=a.x*b.z; acc[0][3]+=a.x*b.w;
            acc[1][0]+=a.y*b.x; acc[1][1]+=a.y*b.y; acc[1][2]+=a.y*b.z; acc[1][3]+=a.y*b.w;
            acc[2][0]+=a.z*b.x; acc[2][1]+=a.z*b.y; acc[2][2]+=a.z*b.z; acc[2][3]+=a.z*b.w;
            acc[3][0]+=a.w*b.x; acc[3][1]+=a.w*b.y; acc[3][2]+=a.w*b.z; acc[3][3]+=a.w*b.w;
        }
        __syncthreads();
    }
    float* Cz = Cp + (size_t)z*M*N;
    #pragma unroll
    for (int i = 0; i < 4; i++) {
        int gm = ty*4 + i; if (gm >= M) continue;
        #pragma unroll
        for (int j = 0; j < 4; j++) {
            int gn = bn + tx*4 + j; if (gn >= N) continue;
            Cz[(size_t)gm*N + gn] = acc[i][j];
        }
    }
}

// ---------------- encoder step gates ----------------
__global__ void enc_gates(const float* __restrict__ gxe, const float* __restrict__ ghp,
                          const float* __restrict__ bhh, float* __restrict__ h,
                          float* __restrict__ po, const int* __restrict__ post_length, int t) {
    int idx = blockIdx.x*blockDim.x + threadIdx.x;
    if (idx >= B*GH) return;
    int b = idx / GH, j = idx % GH;
    const float* gx = gxe + ((size_t)b*PL + t)*G3;
    float ghr = bhh[j], ghz = bhh[GH+j], ghn = bhh[2*GH+j];
    #pragma unroll
    for (int s = 0; s < 4; s++) {
        const float* p = ghp + ((size_t)s*B + b)*G3;
        ghr += p[j]; ghz += p[GH+j]; ghn += p[2*GH+j];
    }
    float r = sigmoidf_(gx[j] + ghr);
    float z = sigmoidf_(gx[GH+j] + ghz);
    float n = tanhf(gx[2*GH+j] + r*ghn);
    float hold = h[idx];
    float hn = (1.f - z)*n + z*hold;
    bool valid = t < post_length[b];
    h[idx] = valid ? hn : hold;
    po[((size_t)b*PL + t)*GH + j] = valid ? hn : 0.f;
}

// ---------------- decoder: prev-gates + attention + misc (one block per b) ---------
__global__ void __launch_bounds__(256) dec_am(
        float* __restrict__ din2, const float* __restrict__ po,
        const float* __restrict__ cp, const float* __restrict__ gxrv_prev,
        const float* __restrict__ bhh,
        const float* __restrict__ wb_w, const float* __restrict__ wb_b,
        const float* __restrict__ wc_w, const float* __restrict__ wc_b,
        const float* __restrict__ vb_w, const float* __restrict__ vb_b,
        const float* __restrict__ ubg, const float* __restrict__ sg,
        float* __restrict__ q, float* __restrict__ da,
        float* __restrict__ Z, int t, int do_gates) {
    int b = blockIdx.x, tid = threadIdx.x;
    int lane = tid & 31, wid = tid >> 5;
    __shared__ float hs[GH];
    __shared__ float sc2[256];
    __shared__ float sc[PL];
    __shared__ float al[PL];
    __shared__ float wbh[HID];
    __shared__ float dls[NT];
    __shared__ float das[NT];
    if (do_gates) {
        #pragma unroll
        for (int jj = 0; jj < 2; jj++) {
            int j = jj*256 + tid;
            float cr = 0.f, cz = 0.f, cxn = 0.f, chn = 0.f;
            #pragma unroll
            for (int z = 0; z < 8; z++) {
                const float* p = cp + ((size_t)z*B + b)*G4;
                cr += p[j]; cz += p[512+j]; cxn += p[1024+j]; chn += p[1536+j];
            }
            const float* gr = gxrv_prev + (size_t)b*G3;
            float r  = sigmoidf_(cr + gr[j] + bhh[j]);
            float zz = sigmoidf_(cz + gr[GH+j] + bhh[GH+j]);
            float n  = tanhf(cxn + gr[2*GH+j] + r*(chn + bhh[2*GH+j]));
            float hold = din2[(size_t)b*KC + 1012 + j];
            float hn = (1.f - zz)*n + zz*hold;
            din2[(size_t)b*KC + 1012 + j] = hn;
            Z[((size_t)(t-1)*B + b)*KD + j] = hn;
            hs[j] = hn;
        }
        __syncthreads();
    } else {
        for (int i = tid; i < GH; i += 256) hs[i] = din2[(size_t)b*KC + 1012 + i];
        __syncthreads();
    }
    {
        int p = tid >> 1, hf = tid & 1;
        const float* row = po + ((size_t)b*PL + p)*GH + hf*256;
        const float* h2 = hs + hf*256;
        float s = 0.f;
        for (int k = 0; k < 256; k += 4) {
            float4 v = *reinterpret_cast<const float4*>(row + k);
            s += v.x*h2[k] + v.y*h2[k+1] + v.z*h2[k+2] + v.w*h2[k+3];
        }
        sc2[tid] = s;
    }
    __syncthreads();
    if (tid < PL) sc[tid] = sc2[2*tid] + sc2[2*tid+1];
    __syncthreads();
    for (int j = tid; j < 400; j += 256) {
        const float* w;
        float acc;
        if (j < 300) { acc = wc_b[j]; w = wc_w + (size_t)j*GH; }
        else         { acc = wb_b[j-300]; w = wb_w + (size_t)(j-300)*GH; }
        for (int k = 0; k < GH; k += 4) {
            float4 v = *reinterpret_cast<const float4*>(w + k);
            acc += v.x*hs[k] + v.y*hs[k+1] + v.z*hs[k+2] + v.w*hs[k+3];
        }
        if (j < 300) q[(size_t)b*300 + j] = acc;
        else wbh[j-300] = acc;
    }
    if (wid == 0) {
        float v0 = sc[lane], v1 = sc[lane+32], v2 = sc[lane+64], v3 = sc[lane+96];
        float m = fmaxf(fmaxf(v0, v1), fmaxf(v2, v3));
        for (int o = 16; o; o >>= 1) m = fmaxf(m, __shfl_xor_sync(0xffffffffu, m, o));
        float e0 = expf(v0-m), e1 = expf(v1-m), e2 = expf(v2-m), e3 = expf(v3-m);
        float s = e0+e1+e2+e3;
        for (int o = 16; o; o >>= 1) s += __shfl_xor_sync(0xffffffffu, s, o);
        float inv = 1.f/s;
        al[lane] = e0*inv; al[lane+32] = e1*inv; al[lane+64] = e2*inv; al[lane+96] = e3*inv;
    }
    __syncthreads();
    for (int d = tid; d < GH; d += 256) {
        float acc = 0.f;
        for (int p = 0; p < PL; p++) acc += al[p]*po[((size_t)b*PL + p)*GH + d];
        din2[(size_t)b*KC + d] = acc;
    }
    if (tid < NT) {
        float s = 0.f;
        const float* u = ubg + ((size_t)b*NT + tid)*HID;
        for (int j = 0; j < HID; j++) s += vb_w[j]*tanhf(wbh[j] + u[j]);
        dls[tid] = s + vb_b[0];
    }
    __syncthreads();
    if (wid == 0) {
        float a0 = (lane < NT) ? dls[lane] : -1e30f;
        float a1 = (lane+32 < NT) ? dls[lane+32] : -1e30f;
        float m = fmaxf(a0, a1);
        for (int o = 16; o; o >>= 1) m = fmaxf(m, __shfl_xor_sync(0xffffffffu, m, o));
        float e0 = (lane < NT) ? expf(a0-m) : 0.f;
        float e1 = (lane+32 < NT) ? expf(a1-m) : 0.f;
        float s = e0 + e1;
        for (int o = 16; o; o >>= 1) s += __shfl_xor_sync(0xffffffffu, s, o);
        float inv = 1.f/s;
        if (lane < NT)    { das[lane] = e0*inv;    da[(size_t)b*NT + lane] = e0*inv; }
        if (lane+32 < NT) { das[lane+32] = e1*inv; da[(size_t)b*NT + lane+32] = e1*inv; }
    }
    __syncthreads();
    float* zrow = Z + ((size_t)t*B + b)*KD;
    for (int d = tid; d < 200; d += 256) {
        float s = 0.f;
        for (int n = 0; n < NT; n++) s += das[n]*sg[((size_t)b*NT + n)*200 + d];
        din2[(size_t)b*KC + 512 + d] = s;
        zrow[512 + d] = s;
    }
}

// ---------------- triple attention: partial over n-chunks, fp16 tef ----------------
__global__ void __launch_bounds__(256) dec_tv_part(
        const __half* __restrict__ tef16, const float* __restrict__ q,
        const float* __restrict__ da, float* __restrict__ tvp) {
    int b = blockIdx.x, ch = blockIdx.y;
    int tid = threadIdx.x, lane = tid & 31, wid = tid >> 5;
    __shared__ float qs[300];
    __shared__ float sw[10*NP];
    __shared__ float dal[10];
    for (int i = tid; i < 300; i += 256) qs[i] = q[(size_t)b*300 + i];
    if (tid < 10) dal[tid] = da[(size_t)b*NT + ch*10 + tid];
    __syncthreads();
    const __half* tb = tef16 + ((size_t)b*NT + ch*10)*NP*300;
    #pragma unroll
    for (int it = 0; it < 25; it++) {
        int pair = wid + 8*it;
        const __half* row = tb + (size_t)pair*300;
        float s = 0.f;
        for (int k2 = lane; k2 < 150; k2 += 32) {
            __half2 hv = *reinterpret_cast<const __half2*>(row + 2*k2);
            float2 fv = __half22float2(hv);
            s += fv.x*qs[2*k2] + fv.y*qs[2*k2+1];
        }
        #pragma unroll
        for (int o = 16; o; o >>= 1) s += __shfl_down_sync(0xffffffffu, s, o);
        if (lane == 0) sw[pair] = s;
    }
    __syncthreads();
    for (int n = wid; n < 10; n += 8) {
        float v = (lane < NP) ? sw[n*NP + lane] : -1e30f;
        float m = v;
        for (int o = 16; o; o >>= 1) m = fmaxf(m, __shfl_xor_sync(0xffffffffu, m, o));
        float e = (lane < NP) ? expf(v - m) : 0.f;
        float su = e;
        for (int o = 16; o; o >>= 1) su += __shfl_xor_sync(0xffffffffu, su, o);
        if (lane < NP) sw[n*NP + lane] = e * dal[n] / su;
    }
    __syncthreads();
    for (int d = tid; d < 300; d += 256) {
        float acc = 0.f;
        #pragma unroll 8
        for (int r = 0; r < 200; r++) acc += sw[r]*__half2float(tb[(size_t)r*300 + d]);
        tvp[((size_t)b*NCH + ch)*300 + d] = acc;
    }
}

__global__ void dec_tvsum(const float* __restrict__ tvp, float* __restrict__ din2,
                          float* __restrict__ Z, int t) {
    int b = blockIdx.x, d = threadIdx.x;
    float s = 0.f;
    #pragma unroll
    for (int ch = 0; ch < NCH; ch++) s += tvp[((size_t)b*NCH + ch)*300 + d];
    din2[(size_t)b*KC + 712 + d] = s;
    Z[((size_t)t*B + b)*KD + 712 + d] = s;
}

// final gates for last decoder step
__global__ void dec_gates2(const float* __restrict__ cp, const float* __restrict__ gxrv_t,
                           const float* __restrict__ bhh, float* __restrict__ din2,
                           float* __restrict__ Z, int t) {
    int idx = blockIdx.x*blockDim.x + threadIdx.x;
    if (idx >= B*GH) return;
    int b = idx / GH, j = idx % GH;
    float cr = 0.f, cz = 0.f, cxn = 0.f, chn = 0.f;
    #pragma unroll
    for (int z = 0; z < 8; z++) {
        const float* p = cp + ((size_t)z*B + b)*G4;
        cr += p[j]; cz += p[512+j]; cxn += p[1024+j]; chn += p[1536+j];
    }
    const float* gr = gxrv_t + (size_t)b*G3;
    float r  = sigmoidf_(cr + gr[j] + bhh[j]);
    float zz = sigmoidf_(cz + gr[GH+j] + bhh[GH+j]);
    float n  = tanhf(cxn + gr[2*GH+j] + r*(chn + bhh[2*GH+j]));
    float hold = din2[(size_t)b*KC + 1012 + j];
    float hn = (1.f - zz)*n + zz*hold;
    din2[(size_t)b*KC + 1012 + j] = hn;
    Z[((size_t)t*B + b)*KD + j] = hn;
}

// ---------------- fp16 split prep (vocab) ----------------
__global__ void k_split_W(const float* __restrict__ W, __half* __restrict__ Ws) {
    size_t i = (size_t)blockIdx.x*blockDim.x + threadIdx.x;
    size_t total = (size_t)VW*(KW/8);
    if (i >= total) return;
    int cg = (int)(i % (KW/8));
    size_t r = i / (KW/8);
    int c0 = cg*8;
    __half o[8];
    #pragma unroll
    for (int e = 0; e < 8; e++) {
        int c = c0 + e;
        o[e] = (c < KSEG) ? __float2half(W[r*KSEG + c]) : __float2half(0.f);
    }
    *reinterpret_cast<uint4*>(Ws + r*KW + c0) = *reinterpret_cast<uint4*>(o);
}

__global__ void k_split_Z(const float* __restrict__ Z, __half* __restrict__ As_) {
    size_t i = (size_t)blockIdx.x*blockDim.x + threadIdx.x;
    size_t total = (size_t)MP*(KPA/8);
    if (i >= total) return;
    int cg = (int)(i % (KPA/8));
    int m = (int)(i / (KPA/8));
    int b = m / TDEC, t = m - b*TDEC;
    int c0 = cg*8;
    __half o[8];
    #pragma unroll
    for (int e = 0; e < 8; e++) {
        int c = c0 + e;
        int lo = (c >= KW);
        int kc = lo ? (c - KW) : c;
        __half v = __float2half(0.f);
        if (b < B && kc < KSEG) {
            float zv = Z[((size_t)t*B + b)*KD + kc];
            __half hh = __float2half(zv);
            if (lo) v = __float2half(zv - __half2float(hh));
            else v = hh;
        }
        o[e] = v;
    }
    *reinterpret_cast<uint4*>(As_ + (size_t)m*KPA + c0) = *reinterpret_cast<uint4*>(o);
}

// ---------------- mma.sync fp16 vocab GEMM: 256x128 tile, B deduped, 3-stage --------
__global__ void __launch_bounds__(256) vocab_mma(
        const __half* __restrict__ Ag, const __half* __restrict__ Wg,
        const float* __restrict__ bout, float* __restrict__ out) {
    extern __shared__ __align__(16) char sraw[];
    const int tid = threadIdx.x;
    const int wid = tid >> 5, lane = tid & 31;
    const int m0 = blockIdx.x * VTM, n0 = blockIdx.y * VTN;
    const int wm = (wid >> 1) * 64, wn = (wid & 1) * 64;
    const int g = lane >> 2, tg = lane & 3;
    const uint32_t sb = smem_u32(sraw);

    float acc[4][8][4];
    #pragma unroll
    for (int i = 0; i < 4; i++)
    #pragma unroll
    for (int j = 0; j < 8; j++) { acc[i][j][0]=0.f; acc[i][j][1]=0.f; acc[i][j][2]=0.f; acc[i][j][3]=0.f; }

    auto load_stage = [&](int s, int k0) {
        uint32_t base = sb + (uint32_t)s*VSTAGE;
        #pragma unroll
        for (int i = 0; i < 10; i++) {
            int c = i*256 + tid;                  // 0..2559: A0 1024, A1 1024, B 512
            uint32_t roff; const __half* src;
            if (c < 1024) {
                int row = c >> 2, ch = c & 3;
                roff = (uint32_t)row*(SSTRIDE*2) + (uint32_t)ch*16u;
                src = Ag + (size_t)(m0+row)*KPA + k0 + ch*8;
            } else if (c < 2048) {
                int cc = c - 1024; int row = cc >> 2, ch = cc & 3;
                roff = VA_HALF + (uint32_t)row*(SSTRIDE*2) + (uint32_t)ch*16u;
                src = Ag + (size_t)(m0+row)*KPA + KW + k0 + ch*8;
            } else {
                int cc = c - 2048; int row = cc >> 2, ch = cc & 3;
                roff = 2*VA_HALF + (uint32_t)row*(SSTRIDE*2) + (uint32_t)ch*16u;
                src = Wg + (size_t)(n0+row)*KW + k0 + ch*8;
            }
            asm volatile("cp.async.cg.shared.global [%0], [%1], 16;" :: "r"(base + roff), "l"(src));
        }
        asm volatile("cp.async.commit_group;" ::: "memory");
    };

    load_stage(0, 0); load_stage(1, 32); load_stage(2, 64);

    const int a_row = lane & 15;
    const int a_k8  = (lane >> 4) << 3;
    const int b_row = lane & 7;
    const int b_k8  = ((lane >> 3) & 1) << 3;
    const int b_ni  = lane >> 4;

    const int NIT = KW/32;                 // 51
    for (int kt = 0; kt < NIT; kt++) {
        if (kt + 3 < NIT) { asm volatile("cp.async.wait_group 2;" ::: "memory"); }
        else              { asm volatile("cp.async.wait_group 0;" ::: "memory"); }
        __syncthreads();
        int s = kt % 3;
        uint32_t baseA0 = sb + (uint32_t)s*VSTAGE;
        uint32_t baseB  = baseA0 + 2*VA_HALF;
        #pragma unroll
        for (int kk = 0; kk < 2; kk++) {
            uint32_t bfr[8][2];
            #pragma unroll
            for (int ni = 0; ni < 8; ni += 2) {
                uint32_t bd = baseB + ((uint32_t)(wn + (ni + b_ni)*8 + b_row)*SSTRIDE
                                       + (uint32_t)(kk*16 + b_k8))*2u;
                asm volatile("ldmatrix.sync.aligned.m8n8.x4.shared.b16 {%0,%1,%2,%3}, [%4];"
                    : "=r"(bfr[ni][0]),"=r"(bfr[ni][1]),"=r"(bfr[ni+1][0]),"=r"(bfr[ni+1][1])
                    : "r"(bd));
            }
            #pragma unroll
            for (int half = 0; half < 2; half++) {
                uint32_t baseA = baseA0 + (uint32_t)half*VA_HALF;
                uint32_t afr[4][4];
                #pragma unroll
                for (int mi = 0; mi < 4; mi++) {
                    uint32_t ad = baseA + ((uint32_t)(wm + mi*16 + a_row)*SSTRIDE
                                           + (uint32_t)(kk*16 + a_k8))*2u;
                    asm volatile("ldmatrix.sync.aligned.m8n8.x4.shared.b16 {%0,%1,%2,%3}, [%4];"
                        : "=r"(afr[mi][0]),"=r"(afr[mi][1]),"=r"(afr[mi][2]),"=r"(afr[mi][3])
                        : "r"(ad));
                }
                #pragma unroll
                for (int mi = 0; mi < 4; mi++)
                #pragma unroll
                for (int ni = 0; ni < 8; ni++) {
                    asm volatile(
                      "mma.sync.aligned.m16n8k16.row.col.f32.f16.f16.f32 "
                      "{%0,%1,%2,%3},{%4,%5,%6,%7},{%8,%9},{%0,%1,%2,%3};"
                      : "+f"(acc[mi][ni][0]), "+f"(acc[mi][ni][1]),
                        "+f"(acc[mi][ni][2]), "+f"(acc[mi][ni][3])
                      : "r"(afr[mi][0]),"r"(afr[mi][1]),"r"(afr[mi][2]),"r"(afr[mi][3]),
                        "r"(bfr[ni][0]),"r"(bfr[ni][1]));
                }
            }
        }
        __syncthreads();
        if (kt + 3 < NIT) load_stage(s, (kt+3)*32);
    }
    __syncthreads();

    float* Ds = (float*)sraw;
    #pragma unroll
    for (int h = 0; h < 2; h++) {
        if ((wid >> 2) == h) {
            int mbase = wm - h*128;
            #pragma unroll
            for (int mi = 0; mi < 4; mi++) {
                int mA = mbase + mi*16 + g;
                #pragma unroll
                for (int ni = 0; ni < 8; ni++) {
                    int nn = wn + ni*8 + tg*2;
                    Ds[mA*129 + nn]         = acc[mi][ni][0];
                    Ds[mA*129 + nn + 1]     = acc[mi][ni][1];
                    Ds[(mA+8)*129 + nn]     = acc[mi][ni][2];
                    Ds[(mA+8)*129 + nn + 1] = acc[mi][ni][3];
                }
            }
        }
        __syncthreads();
        for (int idx = tid; idx < VTN*128; idx += 256) {
            int n = idx >> 7, m = idx & 127;
            int mg = m0 + h*128 + m;
            if (mg < B*TDEC) {
                int bb = mg / TDEC, tt = mg - bb*TDEC;
                int ng = n0 + n;
                out[(size_t)bb*VW*TDEC + (size_t)ng*TDEC + tt] = Ds[m*129 + n] + __ldg(bout + ng);
            }
        }
        __syncthreads();
    }
}

// ---------------- launch ----------------
extern "C" void kernel_launch(void* const* d_in, const int* in_sizes, int n_in,
                              void* d_out, int out_size) {
    const float* word_emb   = (const float*)d_in[0];
    const float* transe_emb = (const float*)d_in[1];
    const float* wh_w = (const float*)d_in[2];  const float* wh_b = (const float*)d_in[3];
    const float* wr_w = (const float*)d_in[4];  const float* wr_b = (const float*)d_in[5];
    const float* wt_w = (const float*)d_in[6];  const float* wt_b = (const float*)d_in[7];
    const float* wb_w = (const float*)d_in[8];  const float* wb_b = (const float*)d_in[9];
    const float* ub_w = (const float*)d_in[10]; const float* ub_b = (const float*)d_in[11];
    const float* vb_w = (const float*)d_in[12]; const float* vb_b = (const float*)d_in[13];
    const float* wc_w = (const float*)d_in[14]; const float* wc_b = (const float*)d_in[15];
    const float* Wih_e = (const float*)d_in[16]; const float* Whh_e = (const float*)d_in[17];
    const float* bih_e = (const float*)d_in[18]; const float* bhh_e = (const float*)d_in[19];
    const float* Wih_d = (const float*)d_in[20]; const float* Whh_d = (const float*)d_in[21];
    const float* bih_d = (const float*)d_in[22]; const float* bhh_d = (const float*)d_in[23];
    const float* out_w = (const float*)d_in[24]; const float* out_b = (const float*)d_in[25];
    const int* post          = (const int*)d_in[26];
    const int* post_length   = (const int*)d_in[27];
    const int* response      = (const int*)d_in[28];
    const int* resp_triple   = (const int*)d_in[29];
    const int* post_triple   = (const int*)d_in[30];
    const int* triple        = (const int*)d_in[31];
    float* out = (float*)d_out;

    void* basep = nullptr; cudaGetSymbolAddress(&basep, g_buf);
    float* base = (float*)basep;
    void* wsp = nullptr; cudaGetSymbolAddress(&wsp, g_Ws);
    void* asp = nullptr; cudaGetSymbolAddress(&asp, g_As);
    void* w2p = nullptr; cudaGetSymbolAddress(&w2p, g_W2);
    void* t16p = nullptr; cudaGetSymbolAddress(&t16p, g_tef16);
    __half* Ws = (__half*)wsp;
    __half* As = (__half*)asp;
    __half* W2 = (__half*)w2p;
    __half* tef16 = (__half*)t16p;

    float* tef  = base + OFF_TEF;
    float* sl   = base + OFF_SL;
    float* sg   = base + OFF_SG;
    float* ubg  = base + OFF_UBG;
    float* pin  = base + OFF_PIN;
    float* gxe  = base + OFF_GXE;
    float* po   = base + OFF_PO;
    float* h    = base + OFF_H;
    float* rv   = base + OFF_RV;
    float* Z    = base + OFF_Z;
    float* din2 = base + OFF_DIN2;
    float* q    = base + OFF_Q;
    float* da   = base + OFF_DA;
    float* cp   = base + OFF_CP;
    float* ghp  = base + OFF_GHP;
    float* gxrv = base + OFF_GXRV;
    float* Wcb  = base + OFF_WCB;
    float* tvp  = base + OFF_TVP;

    cudaFuncSetAttribute(vocab_mma, cudaFuncAttributeMaxDynamicSharedMemorySize, VSMEM);

    // ---- phase A ----
    k_zero<<<(unsigned)((SZ_H + 255)/256), 256>>>(h, SZ_H);
    {
        size_t n4 = (size_t)B*NT*NP*3*25;
        k_gather_tef<<<(unsigned)((n4 + 255)/256), 256>>>(transe_emb, triple, tef, tef16);
    }
    {
        size_t n4 = (size_t)TDEC*B*150;
        k_gather_rv<<<(unsigned)((n4 + 255)/256), 256>>>(word_emb, transe_emb, response, resp_triple, rv, Z);
    }
    {
        size_t nsp = (size_t)VW*(KW/8);
        k_split_W<<<(unsigned)((nsp + 255)/256), 256>>>(out_w, Ws);
    }
    {
        size_t n = (size_t)G4*KC;
        k_build_wcomb<<<(unsigned)((n + 255)/256), 256>>>(Wih_d, Whh_d, Wcb);
    }
    k_triple_score<<<B*NT*NP, 128>>>(tef, triple, wh_w, wh_b, wr_w, wr_b, wt_w, wt_b, sl);
    k_graph_softmax<<<B*NT, 64>>>(sl, tef, sg);
    k_ubg<<<B*NT, 128>>>(sg, ub_w, ub_b, ubg);
    {
        size_t n4 = (size_t)B*PL*125;
        k_post_in<<<(unsigned)((n4 + 255)/256), 256>>>(word_emb, sg, post, post_triple, pin);
    }
    // gxe = pin @ Wih_e^T + bih_e  (fp16 2-term split mma): K=500, Kp=512, K2=1024
    {
        size_t nA = (size_t)(B*PL) * (1024/8);
        k_prep_h2A<<<(unsigned)((nA + 255)/256), 256>>>(pin, As, B*PL, B*PL, KE, 512, KE);
        size_t nW = (size_t)G3 * (1024/8);
        k_prep_h2W<<<(unsigned)((nW + 255)/256), 256>>>(Wih_e, W2, G3, KE, 512, KE, 0);
        gemm_h16<<<dim3((B*PL)/128, G3/128), 256>>>(As, W2, bih_e, gxe, B*PL, G3, 1024);
    }
    // gxrv = rv @ Wih_d[:,1012:]^T + bih_d : K=600, Kp=608, K2=1216, M=4032 pad 4096
    {
        size_t nA = (size_t)4096 * (1216/8);
        k_prep_h2A<<<(unsigned)((nA + 255)/256), 256>>>(rv, As, TDEC*B, 4096, 600, 608, 600);
        size_t nW = (size_t)G3 * (1216/8);
        k_prep_h2W<<<(unsigned)((nW + 255)/256), 256>>>(Wih_d, W2, G3, 600, 608, KD, 1012);
        gemm_h16<<<dim3(4096/128, G3/128), 256>>>(As, W2, bih_d, gxrv, TDEC*B, G3, 1216);
    }

    // ---- phase B: encoder recurrence ----
    for (int t = 0; t < PL; t++) {
        gemm_splitk<<<dim3(G3/64, 4), 256>>>(h, Whh_e, ghp, B, G3, GH, 128);
        enc_gates<<<(B*GH)/256, 256>>>(gxe, ghp, bhh_e, h, po, post_length, t);
    }
    k_h2din2<<<(B*GH)/256, 256>>>(h, din2);

    // ---- phase C: decoder recurrence ----
    for (int t = 0; t < TDEC; t++) {
        const float* gxrv_prev = (t > 0) ? (gxrv + (size_t)(t-1)*B*G3) : gxrv;
        dec_am<<<B, 256>>>(din2, po, cp, gxrv_prev, bhh_d,
                           wb_w, wb_b, wc_w, wc_b, vb_w, vb_b,
                           ubg, sg, q, da, Z, t, t > 0 ? 1 : 0);
        dec_tv_part<<<dim3(B, NCH), 256>>>(tef16, q, da, tvp);
        dec_tvsum<<<B, 300>>>(tvp, din2, Z, t);
        gemm_splitk<<<dim3(G4/64, 8), 256>>>(din2, Wcb, cp, B, G4, KC, 192);
    }
    dec_gates2<<<(B*GH)/256, 256>>>(cp, gxrv + (size_t)(TDEC-1)*B*G3, bhh_d, din2, Z, TDEC-1);

    // ---- phase D: split Z + vocab projection ----
    {
        size_t nsp = (size_t)MP*(KPA/8);
        k_split_Z<<<(unsigned)((nsp + 255)/256), 256>>>(Z, As);
    }
    vocab_mma<<<dim3(MP/VTM, VW/VTN), 256, VSMEM>>>(As, Ws, out_b, out);
}

// round 15
// speedup vs baseline: 1.5373x; 1.0791x over previous
#include <cuda_runtime.h>
#include <cuda_fp16.h>
#include <cstdint>
#include <math.h>

// ---------------- problem dims ----------------
#define B    64
#define PL   128
#define RL   64
#define TDEC 63
#define NT   50
#define NP   20
#define TE   100
#define HID  100
#define GH   512
#define G3   1536
#define G4   2048
#define DE   300
#define VW   32000
#define KE   500
#define KD   1612
#define KC   1524
#define NEGV -1000000000.0f
#define NCH  5

// ---- fp16 2-term split vocab GEMM ----
#define KSEG 1612
#define KW   1632
#define KPA  3264
#define MP   4096
#define SSTRIDE 40
#define VTM  256
#define VTN  128
#define VA_HALF (256*SSTRIDE*2)
#define VB_SZ   (128*SSTRIDE*2)
#define VSTAGE  (2*VA_HALF + VB_SZ)
#define VSMEM   (3*VSTAGE)

#define GSTAGE  (2*128*SSTRIDE*2)
#define HSTAGE  (2*64*SSTRIDE*2 + 128*SSTRIDE*2)   // 20480

// ---------------- scratch ----------------
constexpr size_t SZ_TEF = (size_t)B*NT*NP*300;
constexpr size_t SZ_SL  = (size_t)B*NT*NP;
constexpr size_t SZ_SG  = (size_t)B*NT*200;
constexpr size_t SZ_UBG = (size_t)B*NT*100;
constexpr size_t SZ_PIN = (size_t)B*PL*KE;
constexpr size_t SZ_GXE = (size_t)B*PL*G3;
constexpr size_t SZ_PO  = (size_t)B*PL*GH;
constexpr size_t SZ_H   = (size_t)B*GH;
constexpr size_t SZ_RV  = (size_t)TDEC*B*600;
constexpr size_t SZ_Z   = (size_t)TDEC*B*KD;
constexpr size_t SZ_DIN2= (size_t)B*KC;
constexpr size_t SZ_Q   = (size_t)B*300;
constexpr size_t SZ_DA  = (size_t)B*NT;
constexpr size_t SZ_CP  = (size_t)8*B*G4;
constexpr size_t SZ_GHP = (size_t)4*B*G3;
constexpr size_t SZ_GXRV= (size_t)TDEC*B*G3;
constexpr size_t SZ_WCB = (size_t)G4*KC;
constexpr size_t SZ_TVP = (size_t)B*NCH*300;

constexpr size_t OFF_TEF = 0;
constexpr size_t OFF_SL  = OFF_TEF + SZ_TEF;
constexpr size_t OFF_SG  = OFF_SL  + SZ_SL;
constexpr size_t OFF_UBG = OFF_SG  + SZ_SG;
constexpr size_t OFF_PIN = OFF_UBG + SZ_UBG;
constexpr size_t OFF_GXE = OFF_PIN + SZ_PIN;
constexpr size_t OFF_PO  = OFF_GXE + SZ_GXE;
constexpr size_t OFF_H   = OFF_PO  + SZ_PO;
constexpr size_t OFF_RV  = OFF_H   + SZ_H;
constexpr size_t OFF_Z   = OFF_RV  + SZ_RV;
constexpr size_t OFF_DIN2= OFF_Z   + SZ_Z;
constexpr size_t OFF_Q   = OFF_DIN2+ SZ_DIN2;
constexpr size_t OFF_DA  = OFF_Q   + SZ_Q;
constexpr size_t OFF_CP  = OFF_DA  + SZ_DA;
constexpr size_t OFF_GHP = OFF_CP  + SZ_CP;
constexpr size_t OFF_GXRV= OFF_GHP + SZ_GHP;
constexpr size_t OFF_WCB = OFF_GXRV+ SZ_GXRV;
constexpr size_t OFF_TVP = OFF_WCB + SZ_WCB;
constexpr size_t SZ_TOTAL = OFF_TVP + SZ_TVP;

__device__ float g_buf[SZ_TOTAL];
__device__ __align__(16) __half g_Ws[(size_t)VW * KW];
__device__ __align__(16) __half g_As[(size_t)MP * KPA];
__device__ __align__(16) __half g_W2[(size_t)G3 * 1216];
__device__ __align__(16) __half g_tef16[SZ_TEF];
__device__ __align__(16) __half g_h16[(size_t)B * 1024];      // enc h split [ah(512)|al(512)]
__device__ __align__(16) __half g_din16[(size_t)B * 3072];    // dec din split [ah(1536)|al(1536)]
__device__ __align__(16) __half g_Whe16[(size_t)G3 * 512];
__device__ __align__(16) __half g_Wcb16[(size_t)G4 * 1536];

__device__ __forceinline__ float sigmoidf_(float x) { return 1.0f / (1.0f + expf(-x)); }
__device__ __forceinline__ uint32_t smem_u32(const void* p) {
    uint32_t a;
    asm("{ .reg .u64 t; cvta.to.shared.u64 t, %1; cvt.u32.u64 %0, t; }" : "=r"(a) : "l"(p));
    return a;
}
__device__ __forceinline__ void split16(__half* base, size_t hi_idx, int Kp, float v) {
    __half hh = __float2half(v);
    base[hi_idx] = hh;
    base[hi_idx + Kp] = __float2half(v - __half2float(hh));
}

// ---------------- small utility kernels ----------------
__global__ void k_zero(float* p, size_t n) {
    size_t i = (size_t)blockIdx.x*blockDim.x + threadIdx.x;
    if (i < n) p[i] = 0.f;
}
__global__ void k_zeroh(__half* p, size_t n) {
    size_t i = (size_t)blockIdx.x*blockDim.x + threadIdx.x;
    if (i < n) p[i] = __float2half(0.f);
}

__global__ void k_gather_tef(const float* __restrict__ te, const int* __restrict__ triple,
                             float* __restrict__ tef, __half* __restrict__ tef16) {
    size_t i = (size_t)blockIdx.x*blockDim.x + threadIdx.x;
    size_t total = (size_t)B*NT*NP*3*25;
    if (i >= total) return;
    size_t ent = i / 25; int off = (int)(i % 25) * 4;
    size_t tri = ent / 3; int e = (int)(ent % 3);
    int idx = triple[ent];
    float4 v = *reinterpret_cast<const float4*>(te + (size_t)idx*TE + off);
    size_t dst = tri*300 + e*100 + off;
    *reinterpret_cast<float4*>(tef + dst) = v;
    __half h4[4];
    h4[0] = __float2half(v.x); h4[1] = __float2half(v.y);
    h4[2] = __float2half(v.z); h4[3] = __float2half(v.w);
    *reinterpret_cast<uint2*>(tef16 + dst) = *reinterpret_cast<uint2*>(h4);
}

__global__ void k_gather_rv(const float* __restrict__ we, const float* __restrict__ te,
                            const int* __restrict__ resp, const int* __restrict__ rtrip,
                            float* __restrict__ rv, float* __restrict__ Z) {
    size_t i = (size_t)blockIdx.x*blockDim.x + threadIdx.x;
    size_t total = (size_t)TDEC*B*150;
    if (i >= total) return;
    size_t tb = i / 150; int f = (int)(i % 150);
    int t = (int)(tb / B), b = (int)(tb % B);
    float4 v;
    if (f < 75) {
        int w = resp[b*RL + t];
        v = *reinterpret_cast<const float4*>(we + (size_t)w*DE + f*4);
    } else {
        int f2 = f - 75; int e = f2 / 25; int off = (f2 % 25) * 4;
        int idx = rtrip[((size_t)b*RL + t)*3 + e];
        v = *reinterpret_cast<const float4*>(te + (size_t)idx*TE + off);
    }
    *reinterpret_cast<float4*>(rv + tb*600 + f*4) = v;
    *reinterpret_cast<float4*>(Z + tb*KD + 1012 + f*4) = v;
}

__global__ void k_triple_score(const float* __restrict__ tef, const int* __restrict__ triple,
                               const float* __restrict__ wh_w, const float* __restrict__ wh_b,
                               const float* __restrict__ wr_w, const float* __restrict__ wr_b,
                               const float* __restrict__ wt_w, const float* __restrict__ wt_b,
                               float* __restrict__ sl) {
    int g = blockIdx.x;
    const float* tb = tef + (size_t)g*300;
    __shared__ float e[300];
    __shared__ float red[128];
    int tid = threadIdx.x;
    for (int i = tid; i < 300; i += 128) e[i] = tb[i];
    __syncthreads();
    float contrib = 0.f;
    if (tid < HID) {
        int j = tid;
        float a = wh_b[j] + wt_b[j];
        float r = wr_b[j];
        const float* whr = wh_w + (size_t)j*TE;
        const float* wtr = wt_w + (size_t)j*TE;
        const float* wrr = wr_w + (size_t)j*TE;
        #pragma unroll 4
        for (int k = 0; k < TE; k++) {
            a += e[k]*whr[k] + e[200+k]*wtr[k];
            r += e[100+k]*wrr[k];
        }
        contrib = r * tanhf(a);
    }
    red[tid] = contrib; __syncthreads();
    for (int s = 64; s; s >>= 1) { if (tid < s) red[tid] += red[tid+s]; __syncthreads(); }
    if (tid == 0)
        sl[g] = (triple[(size_t)g*3] == 0) ? NEGV : red[0];
}

__global__ void k_graph_softmax(const float* __restrict__ sl, const float* __restrict__ tef,
                                float* __restrict__ sg) {
    int g = blockIdx.x;
    int tid = threadIdx.x;
    __shared__ float sa[NP];
    if (tid == 0) {
        float m = -1e30f;
        for (int p = 0; p < NP; p++) m = fmaxf(m, sl[(size_t)g*NP + p]);
        float sum = 0.f;
        for (int p = 0; p < NP; p++) { float ev = expf(sl[(size_t)g*NP + p] - m); sa[p] = ev; sum += ev; }
        float inv = 1.f / sum;
        for (int p = 0; p < NP; p++) sa[p] *= inv;
    }
    __syncthreads();
    const float* tb = tef + (size_t)g*NP*300;
    for (int d = tid; d < 200; d += 64) {
        int dd = (d < 100) ? d : d + 100;
        float s = 0.f;
        #pragma unroll
        for (int p = 0; p < NP; p++) s += sa[p]*tb[(size_t)p*300 + dd];
        sg[(size_t)g*200 + d] = s;
    }
}

__global__ void k_ubg(const float* __restrict__ sg, const float* __restrict__ ub_w,
                      const float* __restrict__ ub_b, float* __restrict__ ubg) {
    int g = blockIdx.x;
    int tid = threadIdx.x;
    __shared__ float s[200];
    for (int i = tid; i < 200; i += 128) s[i] = sg[(size_t)g*200 + i];
    __syncthreads();
    if (tid < HID) {
        float acc = ub_b[tid];
        const float* w = ub_w + (size_t)tid*200;
        #pragma unroll 4
        for (int k = 0; k < 200; k++) acc += s[k]*w[k];
        ubg[(size_t)g*HID + tid] = acc;
    }
}

__global__ void k_post_in(const float* __restrict__ we, const float* __restrict__ sg,
                          const int* __restrict__ post, const int* __restrict__ ptrip,
                          float* __restrict__ pin) {
    size_t i = (size_t)blockIdx.x*blockDim.x + threadIdx.x;
    size_t total = (size_t)B*PL*125;
    if (i >= total) return;
    size_t bt = i / 125; int f = (int)(i % 125);
    float4 v;
    if (f < 75) {
        v = *reinterpret_cast<const float4*>(we + (size_t)post[bt]*DE + f*4);
    } else {
        int b = (int)(bt / PL);
        int n = ptrip[bt];
        v = *reinterpret_cast<const float4*>(sg + ((size_t)b*NT + n)*200 + (f-75)*4);
    }
    *reinterpret_cast<float4*>(pin + bt*KE + f*4) = v;
}

__global__ void k_build_wcomb(const float* __restrict__ Wih, const float* __restrict__ Whh,
                              float* __restrict__ Wc) {
    size_t i = (size_t)blockIdx.x*blockDim.x + threadIdx.x;
    if (i >= (size_t)G4*KC) return;
    int c = (int)(i % KC);
    int r = (int)(i / KC);
    float v = 0.f;
    if (r < 1024) {
        v = (c < 1012) ? Wih[(size_t)r*KD + c] : Whh[(size_t)r*GH + (c - 1012)];
    } else if (r < 1536) {
        if (c < 1012) v = Wih[(size_t)r*KD + c];
    } else {
        if (c >= 1012) v = Whh[(size_t)(r - 512)*GH + (c - 1012)];
    }
    Wc[i] = v;
}

// fp32 -> fp16 W conversion with K padding
__global__ void k_conv16(const float* __restrict__ W, __half* __restrict__ dst,
                         int N, int K, int Kp, int stride) {
    int vpr = Kp >> 3;
    size_t i = (size_t)blockIdx.x*blockDim.x + threadIdx.x;
    size_t total = (size_t)N * vpr;
    if (i >= total) return;
    int cg = (int)(i % vpr);
    int r = (int)(i / vpr);
    int c0 = cg*8;
    __half o[8];
    #pragma unroll
    for (int e = 0; e < 8; e++) {
        int kc = c0 + e;
        o[e] = (kc < K) ? __float2half(W[(size_t)r*stride + kc]) : __float2half(0.f);
    }
    *reinterpret_cast<uint4*>(dst + (size_t)r*Kp + c0) = *reinterpret_cast<uint4*>(o);
}

__global__ void k_h2din2(const float* __restrict__ h, float* __restrict__ din2,
                         __half* __restrict__ din16) {
    int i = blockIdx.x*blockDim.x + threadIdx.x;
    if (i >= B*GH) return;
    int b = i / GH, j = i % GH;
    float v = h[i];
    din2[(size_t)b*KC + 1012 + j] = v;
    split16(din16, (size_t)b*3072 + 1012 + j, 1536, v);
}

// ---------------- fp16 2-term prep for generic GEMM ----------------
__global__ void k_prep_h2A(const float* __restrict__ src, __half* __restrict__ dst,
                           int M, int Mp, int K, int Kp, int srcStride) {
    int vpr = (2*Kp) >> 3;
    size_t i = (size_t)blockIdx.x*blockDim.x + threadIdx.x;
    size_t total = (size_t)Mp * vpr;
    if (i >= total) return;
    int cg = (int)(i % vpr);
    int row = (int)(i / vpr);
    int c0 = cg*8;
    __half o[8];
    #pragma unroll
    for (int e = 0; e < 8; e++) {
        int c = c0 + e;
        int lo = (c >= Kp);
        int kc = lo ? (c - Kp) : c;
        __half v = __float2half(0.f);
        if (row < M && kc < K) {
            float x = src[(size_t)row*srcStride + kc];
            __half hh = __float2half(x);
            v = lo ? __float2half(x - __half2float(hh)) : hh;
        }
        o[e] = v;
    }
    *reinterpret_cast<uint4*>(dst + (size_t)row*(2*Kp) + c0) = *reinterpret_cast<uint4*>(o);
}

__global__ void k_prep_h2W(const float* __restrict__ W, __half* __restrict__ dst,
                           int N, int K, int Kp, int srcStride, int co) {
    int vpr = (2*Kp) >> 3;
    size_t i = (size_t)blockIdx.x*blockDim.x + threadIdx.x;
    size_t total = (size_t)N * vpr;
    if (i >= total) return;
    int cg = (int)(i % vpr);
    int r = (int)(i / vpr);
    int c0 = cg*8;
    __half o[8];
    #pragma unroll
    for (int e = 0; e < 8; e++) {
        int c = c0 + e;
        int kc = (c >= Kp) ? (c - Kp) : c;
        o[e] = (kc < K) ? __float2half(W[(size_t)r*srcStride + co + kc]) : __float2half(0.f);
    }
    *reinterpret_cast<uint4*>(dst + (size_t)r*(2*Kp) + c0) = *reinterpret_cast<uint4*>(o);
}

// ---------------- generic fp16 mma GEMM (batch prep): 128x128 tile ---------------
__global__ void __launch_bounds__(256) gemm_h16(
        const __half* __restrict__ A2, const __half* __restrict__ W2,
        const float* __restrict__ bias, float* __restrict__ C,
        int M, int N, int K2) {
    __shared__ __align__(16) char gsm[2*GSTAGE];
    const int tid = threadIdx.x;
    const int wid = tid >> 5, lane = tid & 31;
    const int m0 = blockIdx.x * 128, n0 = blockIdx.y * 128;
    const int wm = (wid >> 2) * 64, wn = (wid & 3) * 32;
    const int g = lane >> 2, tg = lane & 3;
    const uint32_t sb = smem_u32(gsm);

    float acc[4][4][4];
    #pragma unroll
    for (int i = 0; i < 4; i++)
    #pragma unroll
    for (int j = 0; j < 4; j++) { acc[i][j][0]=0.f; acc[i][j][1]=0.f; acc[i][j][2]=0.f; acc[i][j][3]=0.f; }

    auto load_stage = [&](int s, int k0) {
        uint32_t base = sb + (uint32_t)s*GSTAGE;
        #pragma unroll
        for (int i = 0; i < 4; i++) {
            int c = i*256 + tid;
            int isB = (c >= 512); int cc = c & 511;
            int row = cc >> 2, ch = cc & 3;
            uint32_t dst = base + (isB ? (uint32_t)(128*SSTRIDE*2) : 0u)
                         + (uint32_t)row*(SSTRIDE*2) + (uint32_t)ch*16u;
            const __half* src = isB ? (W2 + (size_t)(n0+row)*K2 + k0 + ch*8)
                                    : (A2 + (size_t)(m0+row)*K2 + k0 + ch*8);
            asm volatile("cp.async.cg.shared.global [%0], [%1], 16;" :: "r"(dst), "l"(src));
        }
        asm volatile("cp.async.commit_group;" ::: "memory");
    };

    load_stage(0, 0); load_stage(1, 32);

    const int a_row = lane & 15;
    const int a_k8  = (lane >> 4) << 3;
    const int b_row = lane & 7;
    const int b_k8  = ((lane >> 3) & 1) << 3;
    const int b_ni  = lane >> 4;

    const int NIT = K2/32;
    for (int kt = 0; kt < NIT; kt++) {
        if (kt + 2 < NIT) { asm volatile("cp.async.wait_group 1;" ::: "memory"); }
        else              { asm volatile("cp.async.wait_group 0;" ::: "memory"); }
        __syncthreads();
        int s = kt & 1;
        uint32_t baseA = sb + (uint32_t)s*GSTAGE;
        uint32_t baseB = baseA + (uint32_t)(128*SSTRIDE*2);
        #pragma unroll
        for (int kk = 0; kk < 2; kk++) {
            uint32_t afr[4][4];
            #pragma unroll
            for (int mi = 0; mi < 4; mi++) {
                uint32_t ad = baseA + ((uint32_t)(wm + mi*16 + a_row)*SSTRIDE
                                       + (uint32_t)(kk*16 + a_k8))*2u;
                asm volatile("ldmatrix.sync.aligned.m8n8.x4.shared.b16 {%0,%1,%2,%3}, [%4];"
                    : "=r"(afr[mi][0]),"=r"(afr[mi][1]),"=r"(afr[mi][2]),"=r"(afr[mi][3])
                    : "r"(ad));
            }
            uint32_t bfr[4][2];
            #pragma unroll
            for (int ni = 0; ni < 4; ni += 2) {
                uint32_t bd = baseB + ((uint32_t)(wn + (ni + b_ni)*8 + b_row)*SSTRIDE
                                       + (uint32_t)(kk*16 + b_k8))*2u;
                asm volatile("ldmatrix.sync.aligned.m8n8.x4.shared.b16 {%0,%1,%2,%3}, [%4];"
                    : "=r"(bfr[ni][0]),"=r"(bfr[ni][1]),"=r"(bfr[ni+1][0]),"=r"(bfr[ni+1][1])
                    : "r"(bd));
            }
            #pragma unroll
            for (int mi = 0; mi < 4; mi++)
            #pragma unroll
            for (int ni = 0; ni < 4; ni++) {
                asm volatile(
                  "mma.sync.aligned.m16n8k16.row.col.f32.f16.f16.f32 "
                  "{%0,%1,%2,%3},{%4,%5,%6,%7},{%8,%9},{%0,%1,%2,%3};"
                  : "+f"(acc[mi][ni][0]), "+f"(acc[mi][ni][1]),
                    "+f"(acc[mi][ni][2]), "+f"(acc[mi][ni][3])
                  : "r"(afr[mi][0]),"r"(afr[mi][1]),"r"(afr[mi][2]),"r"(afr[mi][3]),
                    "r"(bfr[ni][0]),"r"(bfr[ni][1]));
            }
        }
        __syncthreads();
        if (kt + 2 < NIT) load_stage(s, (kt+2)*32);
    }

    #pragma unroll
    for (int mi = 0; mi < 4; mi++) {
        int gm = m0 + wm + mi*16 + g;
        #pragma unroll
        for (int ni = 0; ni < 4; ni++) {
            int gn = n0 + wn + ni*8 + tg*2;
            float b0 = bias[gn], b1 = bias[gn+1];
            if (gm < M) {
                C[(size_t)gm*N + gn]     = acc[mi][ni][0] + b0;
                C[(size_t)gm*N + gn + 1] = acc[mi][ni][1] + b1;
            }
            if (gm + 8 < M) {
                C[(size_t)(gm+8)*N + gn]     = acc[mi][ni][2] + b0;
                C[(size_t)(gm+8)*N + gn + 1] = acc[mi][ni][3] + b1;
            }
        }
    }
}

// ---------------- split-K fp16 mma GEMM for recurrent steps -----------------------
// Cp[z][64][N] partials; A16[64][2*Kp]=[ah|al]; W16[N][Kp]; 64x128 tile, BK=32
__global__ void __launch_bounds__(256) gemm_h16_sk(
        const __half* __restrict__ A16, const __half* __restrict__ W16,
        float* __restrict__ Cp, int N, int Kp, int kchunk) {
    __shared__ __align__(16) char hsm[2*HSTAGE];
    const int tid = threadIdx.x;
    const int wid = tid >> 5, lane = tid & 31;
    const int n0 = blockIdx.x * 128;
    const int z = blockIdx.y;
    const int ks = z * kchunk;
    const int wm = (wid >> 2) * 32, wn = (wid & 3) * 32;
    const int g = lane >> 2, tg = lane & 3;
    const uint32_t sb = smem_u32(hsm);

    float acc[2][4][4];
    #pragma unroll
    for (int i = 0; i < 2; i++)
    #pragma unroll
    for (int j = 0; j < 4; j++) { acc[i][j][0]=0.f; acc[i][j][1]=0.f; acc[i][j][2]=0.f; acc[i][j][3]=0.f; }

    auto load_stage = [&](int s, int k0) {       // k0 is global K offset
        uint32_t base = sb + (uint32_t)s*HSTAGE;
        #pragma unroll
        for (int i = 0; i < 4; i++) {
            int c = i*256 + tid;                 // 0..1023: A0 256, A1 256, W 512
            uint32_t dst; const __half* src;
            if (c < 256) {
                int row = c >> 2, ch = c & 3;
                dst = base + (uint32_t)row*(SSTRIDE*2) + (uint32_t)ch*16u;
                src = A16 + (size_t)row*(2*Kp) + k0 + ch*8;
            } else if (c < 512) {
                int cc = c - 256; int row = cc >> 2, ch = cc & 3;
                dst = base + (uint32_t)(64*SSTRIDE*2) + (uint32_t)row*(SSTRIDE*2) + (uint32_t)ch*16u;
                src = A16 + (size_t)row*(2*Kp) + Kp + k0 + ch*8;
            } else {
                int cc = c - 512; int row = cc >> 2, ch = cc & 3;
                dst = base + (uint32_t)(128*SSTRIDE*2) + (uint32_t)row*(SSTRIDE*2) + (uint32_t)ch*16u;
                src = W16 + (size_t)(n0 + row)*Kp + k0 + ch*8;
            }
            asm volatile("cp.async.cg.shared.global [%0], [%1], 16;" :: "r"(dst), "l"(src));
        }
        asm volatile("cp.async.commit_group;" ::: "memory");
    };

    load_stage(0, ks); load_stage(1, ks + 32);

    const int a_row = lane & 15;
    const int a_k8  = (lane >> 4) << 3;
    const int b_row = lane & 7;
    const int b_k8  = ((lane >> 3) & 1) << 3;
    const int b_ni  = lane >> 4;

    const int NIT = kchunk/32;
    for (int kt = 0; kt < NIT; kt++) {
        if (kt + 2 < NIT) { asm volatile("cp.async.wait_group 1;" ::: "memory"); }
        else              { asm volatile("cp.async.wait_group 0;" ::: "memory"); }
        __syncthreads();
        int s = kt & 1;
        uint32_t baseA0 = sb + (uint32_t)s*HSTAGE;
        uint32_t baseA1 = baseA0 + (uint32_t)(64*SSTRIDE*2);
        uint32_t baseW  = baseA0 + (uint32_t)(128*SSTRIDE*2);
        #pragma unroll
        for (int kk = 0; kk < 2; kk++) {
            uint32_t bfr[4][2];
            #pragma unroll
            for (int ni = 0; ni < 4; ni += 2) {
                uint32_t bd = baseW + ((uint32_t)(wn + (ni + b_ni)*8 + b_row)*SSTRIDE
                                       + (uint32_t)(kk*16 + b_k8))*2u;
                asm volatile("ldmatrix.sync.aligned.m8n8.x4.shared.b16 {%0,%1,%2,%3}, [%4];"
                    : "=r"(bfr[ni][0]),"=r"(bfr[ni][1]),"=r"(bfr[ni+1][0]),"=r"(bfr[ni+1][1])
                    : "r"(bd));
            }
            #pragma unroll
            for (int half = 0; half < 2; half++) {
                uint32_t baseA = half ? baseA1 : baseA0;
                uint32_t afr[2][4];
                #pragma unroll
                for (int mi = 0; mi < 2; mi++) {
                    uint32_t ad = baseA + ((uint32_t)(wm + mi*16 + a_row)*SSTRIDE
                                           + (uint32_t)(kk*16 + a_k8))*2u;
                    asm volatile("ldmatrix.sync.aligned.m8n8.x4.shared.b16 {%0,%1,%2,%3}, [%4];"
                        : "=r"(afr[mi][0]),"=r"(afr[mi][1]),"=r"(afr[mi][2]),"=r"(afr[mi][3])
                        : "r"(ad));
                }
                #pragma unroll
                for (int mi = 0; mi < 2; mi++)
                #pragma unroll
                for (int ni = 0; ni < 4; ni++) {
                    asm volatile(
                      "mma.sync.aligned.m16n8k16.row.col.f32.f16.f16.f32 "
                      "{%0,%1,%2,%3},{%4,%5,%6,%7},{%8,%9},{%0,%1,%2,%3};"
                      : "+f"(acc[mi][ni][0]), "+f"(acc[mi][ni][1]),
                        "+f"(acc[mi][ni][2]), "+f"(acc[mi][ni][3])
                      : "r"(afr[mi][0]),"r"(afr[mi][1]),"r"(afr[mi][2]),"r"(afr[mi][3]),
                        "r"(bfr[ni][0]),"r"(bfr[ni][1]));
                }
            }
        }
        __syncthreads();
        if (kt + 2 < NIT) load_stage(s, ks + (kt+2)*32);
    }

    float* Cz = Cp + (size_t)z*64*N;
    #pragma unroll
    for (int mi = 0; mi < 2; mi++) {
        int gm = wm + mi*16 + g;
        #pragma unroll
        for (int ni = 0; ni < 4; ni++) {
            int gn = n0 + wn + ni*8 + tg*2;
            Cz[(size_t)gm*N + gn]         = acc[mi][ni][0];
            Cz[(size_t)gm*N + gn + 1]     = acc[mi][ni][1];
            Cz[(size_t)(gm+8)*N + gn]     = acc[mi][ni][2];
            Cz[(size_t)(gm+8)*N + gn + 1] = acc[mi][ni][3];
        }
    }
}

// ---------------- encoder step gates ----------------
__global__ void enc_gates(const float* __restrict__ gxe, const float* __restrict__ ghp,
                          const float* __restrict__ bhh, float* __restrict__ h,
                          __half* __restrict__ h16,
                          float* __restrict__ po, const int* __restrict__ post_length, int t) {
    int idx = blockIdx.x*blockDim.x + threadIdx.x;
    if (idx >= B*GH) return;
    int b = idx / GH, j = idx % GH;
    const float* gx = gxe + ((size_t)b*PL + t)*G3;
    float ghr = bhh[j], ghz = bhh[GH+j], ghn = bhh[2*GH+j];
    #pragma unroll
    for (int s = 0; s < 4; s++) {
        const float* p = ghp + ((size_t)s*B + b)*G3;
        ghr += p[j]; ghz += p[GH+j]; ghn += p[2*GH+j];
    }
    float r = sigmoidf_(gx[j] + ghr);
    float z = sigmoidf_(gx[GH+j] + ghz);
    float n = tanhf(gx[2*GH+j] + r*ghn);
    float hold = h[idx];
    float hn = (1.f - z)*n + z*hold;
    bool valid = t < post_length[b];
    float hv = valid ? hn : hold;
    h[idx] = hv;
    split16(h16, (size_t)b*1024 + j, 512, hv);
    po[((size_t)b*PL + t)*GH + j] = valid ? hn : 0.f;
}

// ---------------- decoder: prev-gates + attention + misc ----------------
__global__ void __launch_bounds__(256) dec_am(
        float* __restrict__ din2, __half* __restrict__ din16,
        const float* __restrict__ po,
        const float* __restrict__ cp, const float* __restrict__ gxrv_prev,
        const float* __restrict__ bhh,
        const float* __restrict__ wb_w, const float* __restrict__ wb_b,
        const float* __restrict__ wc_w, const float* __restrict__ wc_b,
        const float* __restrict__ vb_w, const float* __restrict__ vb_b,
        const float* __restrict__ ubg, const float* __restrict__ sg,
        float* __restrict__ q, float* __restrict__ da,
        float* __restrict__ Z, int t, int do_gates) {
    int b = blockIdx.x, tid = threadIdx.x;
    int lane = tid & 31, wid = tid >> 5;
    __shared__ float hs[GH];
    __shared__ float sc2[256];
    __shared__ float sc[PL];
    __shared__ float al[PL];
    __shared__ float wbh[HID];
    __shared__ float dls[NT];
    __shared__ float das[NT];
    if (do_gates) {
        #pragma unroll
        for (int jj = 0; jj < 2; jj++) {
            int j = jj*256 + tid;
            float cr = 0.f, cz = 0.f, cxn = 0.f, chn = 0.f;
            #pragma unroll
            for (int z = 0; z < 8; z++) {
                const float* p = cp + ((size_t)z*B + b)*G4;
                cr += p[j]; cz += p[512+j]; cxn += p[1024+j]; chn += p[1536+j];
            }
            const float* gr = gxrv_prev + (size_t)b*G3;
            float r  = sigmoidf_(cr + gr[j] + bhh[j]);
            float zz = sigmoidf_(cz + gr[GH+j] + bhh[GH+j]);
            float n  = tanhf(cxn + gr[2*GH+j] + r*(chn + bhh[2*GH+j]));
            float hold = din2[(size_t)b*KC + 1012 + j];
            float hn = (1.f - zz)*n + zz*hold;
            din2[(size_t)b*KC + 1012 + j] = hn;
            split16(din16, (size_t)b*3072 + 1012 + j, 1536, hn);
            Z[((size_t)(t-1)*B + b)*KD + j] = hn;
            hs[j] = hn;
        }
        __syncthreads();
    } else {
        for (int i = tid; i < GH; i += 256) hs[i] = din2[(size_t)b*KC + 1012 + i];
        __syncthreads();
    }
    {
        int p = tid >> 1, hf = tid & 1;
        const float* row = po + ((size_t)b*PL + p)*GH + hf*256;
        const float* h2 = hs + hf*256;
        float s = 0.f;
        for (int k = 0; k < 256; k += 4) {
            float4 v = *reinterpret_cast<const float4*>(row + k);
            s += v.x*h2[k] + v.y*h2[k+1] + v.z*h2[k+2] + v.w*h2[k+3];
        }
        sc2[tid] = s;
    }
    __syncthreads();
    if (tid < PL) sc[tid] = sc2[2*tid] + sc2[2*tid+1];
    __syncthreads();
    for (int j = tid; j < 400; j += 256) {
        const float* w;
        float acc;
        if (j < 300) { acc = wc_b[j]; w = wc_w + (size_t)j*GH; }
        else         { acc = wb_b[j-300]; w = wb_w + (size_t)(j-300)*GH; }
        for (int k = 0; k < GH; k += 4) {
            float4 v = *reinterpret_cast<const float4*>(w + k);
            acc += v.x*hs[k] + v.y*hs[k+1] + v.z*hs[k+2] + v.w*hs[k+3];
        }
        if (j < 300) q[(size_t)b*300 + j] = acc;
        else wbh[j-300] = acc;
    }
    if (wid == 0) {
        float v0 = sc[lane], v1 = sc[lane+32], v2 = sc[lane+64], v3 = sc[lane+96];
        float m = fmaxf(fmaxf(v0, v1), fmaxf(v2, v3));
        for (int o = 16; o; o >>= 1) m = fmaxf(m, __shfl_xor_sync(0xffffffffu, m, o));
        float e0 = expf(v0-m), e1 = expf(v1-m), e2 = expf(v2-m), e3 = expf(v3-m);
        float s = e0+e1+e2+e3;
        for (int o = 16; o; o >>= 1) s += __shfl_xor_sync(0xffffffffu, s, o);
        float inv = 1.f/s;
        al[lane] = e0*inv; al[lane+32] = e1*inv; al[lane+64] = e2*inv; al[lane+96] = e3*inv;
    }
    __syncthreads();
    for (int d = tid; d < GH; d += 256) {
        float acc = 0.f;
        for (int p = 0; p < PL; p++) acc += al[p]*po[((size_t)b*PL + p)*GH + d];
        din2[(size_t)b*KC + d] = acc;
        split16(din16, (size_t)b*3072 + d, 1536, acc);
    }
    if (tid < NT) {
        float s = 0.f;
        const float* u = ubg + ((size_t)b*NT + tid)*HID;
        for (int j = 0; j < HID; j++) s += vb_w[j]*tanhf(wbh[j] + u[j]);
        dls[tid] = s + vb_b[0];
    }
    __syncthreads();
    if (wid == 0) {
        float a0 = (lane < NT) ? dls[lane] : -1e30f;
        float a1 = (lane+32 < NT) ? dls[lane+32] : -1e30f;
        float m = fmaxf(a0, a1);
        for (int o = 16; o; o >>= 1) m = fmaxf(m, __shfl_xor_sync(0xffffffffu, m, o));
        float e0 = (lane < NT) ? expf(a0-m) : 0.f;
        float e1 = (lane+32 < NT) ? expf(a1-m) : 0.f;
        float s = e0 + e1;
        for (int o = 16; o; o >>= 1) s += __shfl_xor_sync(0xffffffffu, s, o);
        float inv = 1.f/s;
        if (lane < NT)    { das[lane] = e0*inv;    da[(size_t)b*NT + lane] = e0*inv; }
        if (lane+32 < NT) { das[lane+32] = e1*inv; da[(size_t)b*NT + lane+32] = e1*inv; }
    }
    __syncthreads();
    float* zrow = Z + ((size_t)t*B + b)*KD;
    for (int d = tid; d < 200; d += 256) {
        float s = 0.f;
        for (int n = 0; n < NT; n++) s += das[n]*sg[((size_t)b*NT + n)*200 + d];
        din2[(size_t)b*KC + 512 + d] = s;
        split16(din16, (size_t)b*3072 + 512 + d, 1536, s);
        zrow[512 + d] = s;
    }
}

// ---------------- triple attention ----------------
__global__ void __launch_bounds__(256) dec_tv_part(
        const __half* __restrict__ tef16, const float* __restrict__ q,
        const float* __restrict__ da, float* __restrict__ tvp) {
    int b = blockIdx.x, ch = blockIdx.y;
    int tid = threadIdx.x, lane = tid & 31, wid = tid >> 5;
    __shared__ float qs[300];
    __shared__ float sw[10*NP];
    __shared__ float dal[10];
    for (int i = tid; i < 300; i += 256) qs[i] = q[(size_t)b*300 + i];
    if (tid < 10) dal[tid] = da[(size_t)b*NT + ch*10 + tid];
    __syncthreads();
    const __half* tb = tef16 + ((size_t)b*NT + ch*10)*NP*300;
    #pragma unroll
    for (int it = 0; it < 25; it++) {
        int pair = wid + 8*it;
        const __half* row = tb + (size_t)pair*300;
        float s = 0.f;
        for (int k2 = lane; k2 < 150; k2 += 32) {
            __half2 hv = *reinterpret_cast<const __half2*>(row + 2*k2);
            float2 fv = __half22float2(hv);
            s += fv.x*qs[2*k2] + fv.y*qs[2*k2+1];
        }
        #pragma unroll
        for (int o = 16; o; o >>= 1) s += __shfl_down_sync(0xffffffffu, s, o);
        if (lane == 0) sw[pair] = s;
    }
    __syncthreads();
    for (int n = wid; n < 10; n += 8) {
        float v = (lane < NP) ? sw[n*NP + lane] : -1e30f;
        float m = v;
        for (int o = 16; o; o >>= 1) m = fmaxf(m, __shfl_xor_sync(0xffffffffu, m, o));
        float e = (lane < NP) ? expf(v - m) : 0.f;
        float su = e;
        for (int o = 16; o; o >>= 1) su += __shfl_xor_sync(0xffffffffu, su, o);
        if (lane < NP) sw[n*NP + lane] = e * dal[n] / su;
    }
    __syncthreads();
    for (int d = tid; d < 300; d += 256) {
        float acc = 0.f;
        #pragma unroll 8
        for (int r = 0; r < 200; r++) acc += sw[r]*__half2float(tb[(size_t)r*300 + d]);
        tvp[((size_t)b*NCH + ch)*300 + d] = acc;
    }
}

__global__ void dec_tvsum(const float* __restrict__ tvp, float* __restrict__ din2,
                          __half* __restrict__ din16, float* __restrict__ Z, int t) {
    int b = blockIdx.x, d = threadIdx.x;
    float s = 0.f;
    #pragma unroll
    for (int ch = 0; ch < NCH; ch++) s += tvp[((size_t)b*NCH + ch)*300 + d];
    din2[(size_t)b*KC + 712 + d] = s;
    split16(din16, (size_t)b*3072 + 712 + d, 1536, s);
    Z[((size_t)t*B + b)*KD + 712 + d] = s;
}

// final gates for last decoder step (only Z matters afterward)
__global__ void dec_gates2(const float* __restrict__ cp, const float* __restrict__ gxrv_t,
                           const float* __restrict__ bhh, float* __restrict__ din2,
                           float* __restrict__ Z, int t) {
    int idx = blockIdx.x*blockDim.x + threadIdx.x;
    if (idx >= B*GH) return;
    int b = idx / GH, j = idx % GH;
    float cr = 0.f, cz = 0.f, cxn = 0.f, chn = 0.f;
    #pragma unroll
    for (int z = 0; z < 8; z++) {
        const float* p = cp + ((size_t)z*B + b)*G4;
        cr += p[j]; cz += p[512+j]; cxn += p[1024+j]; chn += p[1536+j];
    }
    const float* gr = gxrv_t + (size_t)b*G3;
    float r  = sigmoidf_(cr + gr[j] + bhh[j]);
    float zz = sigmoidf_(cz + gr[GH+j] + bhh[GH+j]);
    float n  = tanhf(cxn + gr[2*GH+j] + r*(chn + bhh[2*GH+j]));
    float hold = din2[(size_t)b*KC + 1012 + j];
    float hn = (1.f - zz)*n + zz*hold;
    din2[(size_t)b*KC + 1012 + j] = hn;
    Z[((size_t)t*B + b)*KD + j] = hn;
}

// ---------------- fp16 split prep (vocab) ----------------
__global__ void k_split_W(const float* __restrict__ W, __half* __restrict__ Ws) {
    size_t i = (size_t)blockIdx.x*blockDim.x + threadIdx.x;
    size_t total = (size_t)VW*(KW/8);
    if (i >= total) return;
    int cg = (int)(i % (KW/8));
    size_t r = i / (KW/8);
    int c0 = cg*8;
    __half o[8];
    #pragma unroll
    for (int e = 0; e < 8; e++) {
        int c = c0 + e;
        o[e] = (c < KSEG) ? __float2half(W[r*KSEG + c]) : __float2half(0.f);
    }
    *reinterpret_cast<uint4*>(Ws + r*KW + c0) = *reinterpret_cast<uint4*>(o);
}

__global__ void k_split_Z(const float* __restrict__ Z, __half* __restrict__ As_) {
    size_t i = (size_t)blockIdx.x*blockDim.x + threadIdx.x;
    size_t total = (size_t)MP*(KPA/8);
    if (i >= total) return;
    int cg = (int)(i % (KPA/8));
    int m = (int)(i / (KPA/8));
    int b = m / TDEC, t = m - b*TDEC;
    int c0 = cg*8;
    __half o[8];
    #pragma unroll
    for (int e = 0; e < 8; e++) {
        int c = c0 + e;
        int lo = (c >= KW);
        int kc = lo ? (c - KW) : c;
        __half v = __float2half(0.f);
        if (b < B && kc < KSEG) {
            float zv = Z[((size_t)t*B + b)*KD + kc];
            __half hh = __float2half(zv);
            if (lo) v = __float2half(zv - __half2float(hh));
            else v = hh;
        }
        o[e] = v;
    }
    *reinterpret_cast<uint4*>(As_ + (size_t)m*KPA + c0) = *reinterpret_cast<uint4*>(o);
}

// ---------------- mma.sync fp16 vocab GEMM: 256x128 tile, B deduped, 3-stage --------
__global__ void __launch_bounds__(256) vocab_mma(
        const __half* __restrict__ Ag, const __half* __restrict__ Wg,
        const float* __restrict__ bout, float* __restrict__ out) {
    extern __shared__ __align__(16) char sraw[];
    const int tid = threadIdx.x;
    const int wid = tid >> 5, lane = tid & 31;
    const int m0 = blockIdx.x * VTM, n0 = blockIdx.y * VTN;
    const int wm = (wid >> 1) * 64, wn = (wid & 1) * 64;
    const int g = lane >> 2, tg = lane & 3;
    const uint32_t sb = smem_u32(sraw);

    float acc[4][8][4];
    #pragma unroll
    for (int i = 0; i < 4; i++)
    #pragma unroll
    for (int j = 0; j < 8; j++) { acc[i][j][0]=0.f; acc[i][j][1]=0.f; acc[i][j][2]=0.f; acc[i][j][3]=0.f; }

    auto load_stage = [&](int s, int k0) {
        uint32_t base = sb + (uint32_t)s*VSTAGE;
        #pragma unroll
        for (int i = 0; i < 10; i++) {
            int c = i*256 + tid;
            uint32_t roff; const __half* src;
            if (c < 1024) {
                int row = c >> 2, ch = c & 3;
                roff = (uint32_t)row*(SSTRIDE*2) + (uint32_t)ch*16u;
                src = Ag + (size_t)(m0+row)*KPA + k0 + ch*8;
            } else if (c < 2048) {
                int cc = c - 1024; int row = cc >> 2, ch = cc & 3;
                roff = VA_HALF + (uint32_t)row*(SSTRIDE*2) + (uint32_t)ch*16u;
                src = Ag + (size_t)(m0+row)*KPA + KW + k0 + ch*8;
            } else {
                int cc = c - 2048; int row = cc >> 2, ch = cc & 3;
                roff = 2*VA_HALF + (uint32_t)row*(SSTRIDE*2) + (uint32_t)ch*16u;
                src = Wg + (size_t)(n0+row)*KW + k0 + ch*8;
            }
            asm volatile("cp.async.cg.shared.global [%0], [%1], 16;" :: "r"(base + roff), "l"(src));
        }
        asm volatile("cp.async.commit_group;" ::: "memory");
    };

    load_stage(0, 0); load_stage(1, 32); load_stage(2, 64);

    const int a_row = lane & 15;
    const int a_k8  = (lane >> 4) << 3;
    const int b_row = lane & 7;
    const int b_k8  = ((lane >> 3) & 1) << 3;
    const int b_ni  = lane >> 4;

    const int NIT = KW/32;
    for (int kt = 0; kt < NIT; kt++) {
        if (kt + 3 < NIT) { asm volatile("cp.async.wait_group 2;" ::: "memory"); }
        else              { asm volatile("cp.async.wait_group 0;" ::: "memory"); }
        __syncthreads();
        int s = kt % 3;
        uint32_t baseA0 = sb + (uint32_t)s*VSTAGE;
        uint32_t baseB  = baseA0 + 2*VA_HALF;
        #pragma unroll
        for (int kk = 0; kk < 2; kk++) {
            uint32_t bfr[8][2];
            #pragma unroll
            for (int ni = 0; ni < 8; ni += 2) {
                uint32_t bd = baseB + ((uint32_t)(wn + (ni + b_ni)*8 + b_row)*SSTRIDE
                                       + (uint32_t)(kk*16 + b_k8))*2u;
                asm volatile("ldmatrix.sync.aligned.m8n8.x4.shared.b16 {%0,%1,%2,%3}, [%4];"
                    : "=r"(bfr[ni][0]),"=r"(bfr[ni][1]),"=r"(bfr[ni+1][0]),"=r"(bfr[ni+1][1])
                    : "r"(bd));
            }
            #pragma unroll
            for (int half = 0; half < 2; half++) {
                uint32_t baseA = baseA0 + (uint32_t)half*VA_HALF;
                uint32_t afr[4][4];
                #pragma unroll
                for (int mi = 0; mi < 4; mi++) {
                    uint32_t ad = baseA + ((uint32_t)(wm + mi*16 + a_row)*SSTRIDE
                                           + (uint32_t)(kk*16 + a_k8))*2u;
                    asm volatile("ldmatrix.sync.aligned.m8n8.x4.shared.b16 {%0,%1,%2,%3}, [%4];"
                        : "=r"(afr[mi][0]),"=r"(afr[mi][1]),"=r"(afr[mi][2]),"=r"(afr[mi][3])
                        : "r"(ad));
                }
                #pragma unroll
                for (int mi = 0; mi < 4; mi++)
                #pragma unroll
                for (int ni = 0; ni < 8; ni++) {
                    asm volatile(
                      "mma.sync.aligned.m16n8k16.row.col.f32.f16.f16.f32 "
                      "{%0,%1,%2,%3},{%4,%5,%6,%7},{%8,%9},{%0,%1,%2,%3};"
                      : "+f"(acc[mi][ni][0]), "+f"(acc[mi][ni][1]),
                        "+f"(acc[mi][ni][2]), "+f"(acc[mi][ni][3])
                      : "r"(afr[mi][0]),"r"(afr[mi][1]),"r"(afr[mi][2]),"r"(afr[mi][3]),
                        "r"(bfr[ni][0]),"r"(bfr[ni][1]));
                }
            }
        }
        __syncthreads();
        if (kt + 3 < NIT) load_stage(s, (kt+3)*32);
    }
    __syncthreads();

    float* Ds = (float*)sraw;
    #pragma unroll
    for (int h = 0; h < 2; h++) {
        if ((wid >> 2) == h) {
            int mbase = wm - h*128;
            #pragma unroll
            for (int mi = 0; mi < 4; mi++) {
                int mA = mbase + mi*16 + g;
                #pragma unroll
                for (int ni = 0; ni < 8; ni++) {
                    int nn = wn + ni*8 + tg*2;
                    Ds[mA*129 + nn]         = acc[mi][ni][0];
                    Ds[mA*129 + nn + 1]     = acc[mi][ni][1];
                    Ds[(mA+8)*129 + nn]     = acc[mi][ni][2];
                    Ds[(mA+8)*129 + nn + 1] = acc[mi][ni][3];
                }
            }
        }
        __syncthreads();
        for (int idx = tid; idx < VTN*128; idx += 256) {
            int n = idx >> 7, m = idx & 127;
            int mg = m0 + h*128 + m;
            if (mg < B*TDEC) {
                int bb = mg / TDEC, tt = mg - bb*TDEC;
                int ng = n0 + n;
                out[(size_t)bb*VW*TDEC + (size_t)ng*TDEC + tt] = Ds[m*129 + n] + __ldg(bout + ng);
            }
        }
        __syncthreads();
    }
}

// ---------------- launch ----------------
extern "C" void kernel_launch(void* const* d_in, const int* in_sizes, int n_in,
                              void* d_out, int out_size) {
    const float* word_emb   = (const float*)d_in[0];
    const float* transe_emb = (const float*)d_in[1];
    const float* wh_w = (const float*)d_in[2];  const float* wh_b = (const float*)d_in[3];
    const float* wr_w = (const float*)d_in[4];  const float* wr_b = (const float*)d_in[5];
    const float* wt_w = (const float*)d_in[6];  const float* wt_b = (const float*)d_in[7];
    const float* wb_w = (const float*)d_in[8];  const float* wb_b = (const float*)d_in[9];
    const float* ub_w = (const float*)d_in[10]; const float* ub_b = (const float*)d_in[11];
    const float* vb_w = (const float*)d_in[12]; const float* vb_b = (const float*)d_in[13];
    const float* wc_w = (const float*)d_in[14]; const float* wc_b = (const float*)d_in[15];
    const float* Wih_e = (const float*)d_in[16]; const float* Whh_e = (const float*)d_in[17];
    const float* bih_e = (const float*)d_in[18]; const float* bhh_e = (const float*)d_in[19];
    const float* Wih_d = (const float*)d_in[20]; const float* Whh_d = (const float*)d_in[21];
    const float* bih_d = (const float*)d_in[22]; const float* bhh_d = (const float*)d_in[23];
    const float* out_w = (const float*)d_in[24]; const float* out_b = (const float*)d_in[25];
    const int* post          = (const int*)d_in[26];
    const int* post_length   = (const int*)d_in[27];
    const int* response      = (const int*)d_in[28];
    const int* resp_triple   = (const int*)d_in[29];
    const int* post_triple   = (const int*)d_in[30];
    const int* triple        = (const int*)d_in[31];
    float* out = (float*)d_out;

    void* basep = nullptr; cudaGetSymbolAddress(&basep, g_buf);
    float* base = (float*)basep;
    void* wsp = nullptr; cudaGetSymbolAddress(&wsp, g_Ws);
    void* asp = nullptr; cudaGetSymbolAddress(&asp, g_As);
    void* w2p = nullptr; cudaGetSymbolAddress(&w2p, g_W2);
    void* t16p = nullptr; cudaGetSymbolAddress(&t16p, g_tef16);
    void* h16p = nullptr; cudaGetSymbolAddress(&h16p, g_h16);
    void* d16p = nullptr; cudaGetSymbolAddress(&d16p, g_din16);
    void* whe16p = nullptr; cudaGetSymbolAddress(&whe16p, g_Whe16);
    void* wcb16p = nullptr; cudaGetSymbolAddress(&wcb16p, g_Wcb16);
    __half* Ws = (__half*)wsp;
    __half* As = (__half*)asp;
    __half* W2 = (__half*)w2p;
    __half* tef16 = (__half*)t16p;
    __half* h16 = (__half*)h16p;
    __half* din16 = (__half*)d16p;
    __half* Whe16 = (__half*)whe16p;
    __half* Wcb16 = (__half*)wcb16p;

    float* tef  = base + OFF_TEF;
    float* sl   = base + OFF_SL;
    float* sg   = base + OFF_SG;
    float* ubg  = base + OFF_UBG;
    float* pin  = base + OFF_PIN;
    float* gxe  = base + OFF_GXE;
    float* po   = base + OFF_PO;
    float* h    = base + OFF_H;
    float* rv   = base + OFF_RV;
    float* Z    = base + OFF_Z;
    float* din2 = base + OFF_DIN2;
    float* q    = base + OFF_Q;
    float* da   = base + OFF_DA;
    float* cp   = base + OFF_CP;
    float* ghp  = base + OFF_GHP;
    float* gxrv = base + OFF_GXRV;
    float* Wcb  = base + OFF_WCB;
    float* tvp  = base + OFF_TVP;

    cudaFuncSetAttribute(vocab_mma, cudaFuncAttributeMaxDynamicSharedMemorySize, VSMEM);

    // ---- phase A ----
    k_zero<<<(unsigned)((SZ_H + 255)/256), 256>>>(h, SZ_H);
    k_zeroh<<<(unsigned)((B*1024 + 255)/256), 256>>>(h16, (size_t)B*1024);
    k_zeroh<<<(unsigned)((B*3072 + 255)/256), 256>>>(din16, (size_t)B*3072);
    {
        size_t n4 = (size_t)B*NT*NP*3*25;
        k_gather_tef<<<(unsigned)((n4 + 255)/256), 256>>>(transe_emb, triple, tef, tef16);
    }
    {
        size_t n4 = (size_t)TDEC*B*150;
        k_gather_rv<<<(unsigned)((n4 + 255)/256), 256>>>(word_emb, transe_emb, response, resp_triple, rv, Z);
    }
    {
        size_t nsp = (size_t)VW*(KW/8);
        k_split_W<<<(unsigned)((nsp + 255)/256), 256>>>(out_w, Ws);
    }
    {
        size_t n = (size_t)G4*KC;
        k_build_wcomb<<<(unsigned)((n + 255)/256), 256>>>(Wih_d, Whh_d, Wcb);
    }
    {
        size_t n = (size_t)G3*(512/8);
        k_conv16<<<(unsigned)((n + 255)/256), 256>>>(Whh_e, Whe16, G3, 512, 512, GH);
    }
    {
        size_t n = (size_t)G4*(1536/8);
        k_conv16<<<(unsigned)((n + 255)/256), 256>>>(Wcb, Wcb16, G4, KC, 1536, KC);
    }
    k_triple_score<<<B*NT*NP, 128>>>(tef, triple, wh_w, wh_b, wr_w, wr_b, wt_w, wt_b, sl);
    k_graph_softmax<<<B*NT, 64>>>(sl, tef, sg);
    k_ubg<<<B*NT, 128>>>(sg, ub_w, ub_b, ubg);
    {
        size_t n4 = (size_t)B*PL*125;
        k_post_in<<<(unsigned)((n4 + 255)/256), 256>>>(word_emb, sg, post, post_triple, pin);
    }
    // gxe = pin @ Wih_e^T + bih_e (fp16 2-term split mma)
    {
        size_t nA = (size_t)(B*PL) * (1024/8);
        k_prep_h2A<<<(unsigned)((nA + 255)/256), 256>>>(pin, As, B*PL, B*PL, KE, 512, KE);
        size_t nW = (size_t)G3 * (1024/8);
        k_prep_h2W<<<(unsigned)((nW + 255)/256), 256>>>(Wih_e, W2, G3, KE, 512, KE, 0);
        gemm_h16<<<dim3((B*PL)/128, G3/128), 256>>>(As, W2, bih_e, gxe, B*PL, G3, 1024);
    }
    // gxrv = rv @ Wih_d[:,1012:]^T + bih_d
    {
        size_t nA = (size_t)4096 * (1216/8);
        k_prep_h2A<<<(unsigned)((nA + 255)/256), 256>>>(rv, As, TDEC*B, 4096, 600, 608, 600);
        size_t nW = (size_t)G3 * (1216/8);
        k_prep_h2W<<<(unsigned)((nW + 255)/256), 256>>>(Wih_d, W2, G3, 600, 608, KD, 1012);
        gemm_h16<<<dim3(4096/128, G3/128), 256>>>(As, W2, bih_d, gxrv, TDEC*B, G3, 1216);
    }

    // ---- phase B: encoder recurrence (fp16 mma split-K) ----
    for (int t = 0; t < PL; t++) {
        gemm_h16_sk<<<dim3(G3/128, 4), 256>>>(h16, Whe16, ghp, G3, 512, 128);
        enc_gates<<<(B*GH)/256, 256>>>(gxe, ghp, bhh_e, h, h16, po, post_length, t);
    }
    k_h2din2<<<(B*GH)/256, 256>>>(h, din2, din16);

    // ---- phase C: decoder recurrence (fp16 mma split-K) ----
    for (int t = 0; t < TDEC; t++) {
        const float* gxrv_prev = (t > 0) ? (gxrv + (size_t)(t-1)*B*G3) : gxrv;
        dec_am<<<B, 256>>>(din2, din16, po, cp, gxrv_prev, bhh_d,
                           wb_w, wb_b, wc_w, wc_b, vb_w, vb_b,
                           ubg, sg, q, da, Z, t, t > 0 ? 1 : 0);
        dec_tv_part<<<dim3(B, NCH), 256>>>(tef16, q, da, tvp);
        dec_tvsum<<<B, 300>>>(tvp, din2, din16, Z, t);
        gemm_h16_sk<<<dim3(G4/128, 8), 256>>>(din16, Wcb16, cp, G4, 1536, 192);
    }
    dec_gates2<<<(B*GH)/256, 256>>>(cp, gxrv + (size_t)(TDEC-1)*B*G3, bhh_d, din2, Z, TDEC-1);

    // ---- phase D: split Z + vocab projection ----
    {
        size_t nsp = (size_t)MP*(KPA/8);
        k_split_Z<<<(unsigned)((nsp + 255)/256), 256>>>(Z, As);
    }
    vocab_mma<<<dim3(MP/VTM, VW/VTN), 256, VSMEM>>>(As, Ws, out_b, out);
}

// round 16
// speedup vs baseline: 1.5617x; 1.0159x over previous
#include <cuda_runtime.h>
#include <cuda_fp16.h>
#include <cstdint>
#include <math.h>

// ---------------- problem dims ----------------
#define B    64
#define PL   128
#define RL   64
#define TDEC 63
#define NT   50
#define NP   20
#define TE   100
#define HID  100
#define GH   512
#define G3   1536
#define G4   2048
#define DE   300
#define VW   32000
#define KE   500
#define KD   1612
#define KC   1524
#define NEGV -1000000000.0f
#define NCH  5

// ---- fp16 2-term split vocab GEMM ----
#define KSEG 1612
#define KW   1632
#define KPA  3264
#define MP   4096
#define SSTRIDE 40
#define VTM  256
#define VTN  128
#define VA_HALF (256*SSTRIDE*2)
#define VB_SZ   (128*SSTRIDE*2)
#define VSTAGE  (2*VA_HALF + VB_SZ)
#define VSMEM   (3*VSTAGE)

#define GSTAGE  (2*128*SSTRIDE*2)
#define HSTAGE  (2*64*SSTRIDE*2 + 128*SSTRIDE*2)   // 20480

// ---------------- scratch ----------------
constexpr size_t SZ_TEF = (size_t)B*NT*NP*300;
constexpr size_t SZ_SL  = (size_t)B*NT*NP;
constexpr size_t SZ_SG  = (size_t)B*NT*200;
constexpr size_t SZ_UBG = (size_t)B*NT*100;
constexpr size_t SZ_PIN = (size_t)B*PL*KE;
constexpr size_t SZ_GXE = (size_t)B*PL*G3;
constexpr size_t SZ_PO  = (size_t)B*PL*GH;
constexpr size_t SZ_H   = (size_t)B*GH;
constexpr size_t SZ_RV  = (size_t)TDEC*B*600;
constexpr size_t SZ_Z   = (size_t)TDEC*B*KD;
constexpr size_t SZ_DIN2= (size_t)B*KC;
constexpr size_t SZ_Q   = (size_t)B*300;
constexpr size_t SZ_DA  = (size_t)B*NT;
constexpr size_t SZ_CP  = (size_t)8*B*G4;
constexpr size_t SZ_GHP = (size_t)4*B*G3;
constexpr size_t SZ_GXRV= (size_t)TDEC*B*G3;
constexpr size_t SZ_WCB = (size_t)G4*KC;
constexpr size_t SZ_TVP = (size_t)B*NCH*300;

constexpr size_t OFF_TEF = 0;
constexpr size_t OFF_SL  = OFF_TEF + SZ_TEF;
constexpr size_t OFF_SG  = OFF_SL  + SZ_SL;
constexpr size_t OFF_UBG = OFF_SG  + SZ_SG;
constexpr size_t OFF_PIN = OFF_UBG + SZ_UBG;
constexpr size_t OFF_GXE = OFF_PIN + SZ_PIN;
constexpr size_t OFF_PO  = OFF_GXE + SZ_GXE;
constexpr size_t OFF_H   = OFF_PO  + SZ_PO;
constexpr size_t OFF_RV  = OFF_H   + SZ_H;
constexpr size_t OFF_Z   = OFF_RV  + SZ_RV;
constexpr size_t OFF_DIN2= OFF_Z   + SZ_Z;
constexpr size_t OFF_Q   = OFF_DIN2+ SZ_DIN2;
constexpr size_t OFF_DA  = OFF_Q   + SZ_Q;
constexpr size_t OFF_CP  = OFF_DA  + SZ_DA;
constexpr size_t OFF_GHP = OFF_CP  + SZ_CP;
constexpr size_t OFF_GXRV= OFF_GHP + SZ_GHP;
constexpr size_t OFF_WCB = OFF_GXRV+ SZ_GXRV;
constexpr size_t OFF_TVP = OFF_WCB + SZ_WCB;
constexpr size_t SZ_TOTAL = OFF_TVP + SZ_TVP;

__device__ float g_buf[SZ_TOTAL];
__device__ __align__(16) __half g_Ws[(size_t)VW * KW];
__device__ __align__(16) __half g_As[(size_t)MP * KPA];
__device__ __align__(16) __half g_W2[(size_t)G3 * 1216];
__device__ __align__(16) __half g_tef16[SZ_TEF];
__device__ __align__(16) __half g_h16[(size_t)B * 1024];      // enc h split [ah(512)|al(512)]
__device__ __align__(16) __half g_din16[(size_t)B * 3072];    // dec din split [ah(1536)|al(1536)]
__device__ __align__(16) __half g_Whe16[(size_t)G3 * 512];
__device__ __align__(16) __half g_Wcb16[(size_t)G4 * 1536];

__device__ __forceinline__ float sigmoidf_(float x) { return 1.0f / (1.0f + expf(-x)); }
__device__ __forceinline__ uint32_t smem_u32(const void* p) {
    uint32_t a;
    asm("{ .reg .u64 t; cvta.to.shared.u64 t, %1; cvt.u32.u64 %0, t; }" : "=r"(a) : "l"(p));
    return a;
}
__device__ __forceinline__ void split16(__half* base, size_t hi_idx, int Kp, float v) {
    __half hh = __float2half(v);
    base[hi_idx] = hh;
    base[hi_idx + Kp] = __float2half(v - __half2float(hh));
}

// ---------------- small utility kernels ----------------
__global__ void k_zero(float* p, size_t n) {
    size_t i = (size_t)blockIdx.x*blockDim.x + threadIdx.x;
    if (i < n) p[i] = 0.f;
}
__global__ void k_zeroh(__half* p, size_t n) {
    size_t i = (size_t)blockIdx.x*blockDim.x + threadIdx.x;
    if (i < n) p[i] = __float2half(0.f);
}

__global__ void k_gather_tef(const float* __restrict__ te, const int* __restrict__ triple,
                             float* __restrict__ tef, __half* __restrict__ tef16) {
    size_t i = (size_t)blockIdx.x*blockDim.x + threadIdx.x;
    size_t total = (size_t)B*NT*NP*3*25;
    if (i >= total) return;
    size_t ent = i / 25; int off = (int)(i % 25) * 4;
    size_t tri = ent / 3; int e = (int)(ent % 3);
    int idx = triple[ent];
    float4 v = *reinterpret_cast<const float4*>(te + (size_t)idx*TE + off);
    size_t dst = tri*300 + e*100 + off;
    *reinterpret_cast<float4*>(tef + dst) = v;
    __half h4[4];
    h4[0] = __float2half(v.x); h4[1] = __float2half(v.y);
    h4[2] = __float2half(v.z); h4[3] = __float2half(v.w);
    *reinterpret_cast<uint2*>(tef16 + dst) = *reinterpret_cast<uint2*>(h4);
}

__global__ void k_gather_rv(const float* __restrict__ we, const float* __restrict__ te,
                            const int* __restrict__ resp, const int* __restrict__ rtrip,
                            float* __restrict__ rv, float* __restrict__ Z) {
    size_t i = (size_t)blockIdx.x*blockDim.x + threadIdx.x;
    size_t total = (size_t)TDEC*B*150;
    if (i >= total) return;
    size_t tb = i / 150; int f = (int)(i % 150);
    int t = (int)(tb / B), b = (int)(tb % B);
    float4 v;
    if (f < 75) {
        int w = resp[b*RL + t];
        v = *reinterpret_cast<const float4*>(we + (size_t)w*DE + f*4);
    } else {
        int f2 = f - 75; int e = f2 / 25; int off = (f2 % 25) * 4;
        int idx = rtrip[((size_t)b*RL + t)*3 + e];
        v = *reinterpret_cast<const float4*>(te + (size_t)idx*TE + off);
    }
    *reinterpret_cast<float4*>(rv + tb*600 + f*4) = v;
    *reinterpret_cast<float4*>(Z + tb*KD + 1012 + f*4) = v;
}

__global__ void k_triple_score(const float* __restrict__ tef, const int* __restrict__ triple,
                               const float* __restrict__ wh_w, const float* __restrict__ wh_b,
                               const float* __restrict__ wr_w, const float* __restrict__ wr_b,
                               const float* __restrict__ wt_w, const float* __restrict__ wt_b,
                               float* __restrict__ sl) {
    int g = blockIdx.x;
    const float* tb = tef + (size_t)g*300;
    __shared__ float e[300];
    __shared__ float red[128];
    int tid = threadIdx.x;
    for (int i = tid; i < 300; i += 128) e[i] = tb[i];
    __syncthreads();
    float contrib = 0.f;
    if (tid < HID) {
        int j = tid;
        float a = wh_b[j] + wt_b[j];
        float r = wr_b[j];
        const float* whr = wh_w + (size_t)j*TE;
        const float* wtr = wt_w + (size_t)j*TE;
        const float* wrr = wr_w + (size_t)j*TE;
        #pragma unroll 4
        for (int k = 0; k < TE; k++) {
            a += e[k]*whr[k] + e[200+k]*wtr[k];
            r += e[100+k]*wrr[k];
        }
        contrib = r * tanhf(a);
    }
    red[tid] = contrib; __syncthreads();
    for (int s = 64; s; s >>= 1) { if (tid < s) red[tid] += red[tid+s]; __syncthreads(); }
    if (tid == 0)
        sl[g] = (triple[(size_t)g*3] == 0) ? NEGV : red[0];
}

__global__ void k_graph_softmax(const float* __restrict__ sl, const float* __restrict__ tef,
                                float* __restrict__ sg) {
    int g = blockIdx.x;
    int tid = threadIdx.x;
    __shared__ float sa[NP];
    if (tid == 0) {
        float m = -1e30f;
        for (int p = 0; p < NP; p++) m = fmaxf(m, sl[(size_t)g*NP + p]);
        float sum = 0.f;
        for (int p = 0; p < NP; p++) { float ev = expf(sl[(size_t)g*NP + p] - m); sa[p] = ev; sum += ev; }
        float inv = 1.f / sum;
        for (int p = 0; p < NP; p++) sa[p] *= inv;
    }
    __syncthreads();
    const float* tb = tef + (size_t)g*NP*300;
    for (int d = tid; d < 200; d += 64) {
        int dd = (d < 100) ? d : d + 100;
        float s = 0.f;
        #pragma unroll
        for (int p = 0; p < NP; p++) s += sa[p]*tb[(size_t)p*300 + dd];
        sg[(size_t)g*200 + d] = s;
    }
}

__global__ void k_ubg(const float* __restrict__ sg, const float* __restrict__ ub_w,
                      const float* __restrict__ ub_b, float* __restrict__ ubg) {
    int g = blockIdx.x;
    int tid = threadIdx.x;
    __shared__ float s[200];
    for (int i = tid; i < 200; i += 128) s[i] = sg[(size_t)g*200 + i];
    __syncthreads();
    if (tid < HID) {
        float acc = ub_b[tid];
        const float* w = ub_w + (size_t)tid*200;
        #pragma unroll 4
        for (int k = 0; k < 200; k++) acc += s[k]*w[k];
        ubg[(size_t)g*HID + tid] = acc;
    }
}

__global__ void k_post_in(const float* __restrict__ we, const float* __restrict__ sg,
                          const int* __restrict__ post, const int* __restrict__ ptrip,
                          float* __restrict__ pin) {
    size_t i = (size_t)blockIdx.x*blockDim.x + threadIdx.x;
    size_t total = (size_t)B*PL*125;
    if (i >= total) return;
    size_t bt = i / 125; int f = (int)(i % 125);
    float4 v;
    if (f < 75) {
        v = *reinterpret_cast<const float4*>(we + (size_t)post[bt]*DE + f*4);
    } else {
        int b = (int)(bt / PL);
        int n = ptrip[bt];
        v = *reinterpret_cast<const float4*>(sg + ((size_t)b*NT + n)*200 + (f-75)*4);
    }
    *reinterpret_cast<float4*>(pin + bt*KE + f*4) = v;
}

__global__ void k_build_wcomb(const float* __restrict__ Wih, const float* __restrict__ Whh,
                              float* __restrict__ Wc) {
    size_t i = (size_t)blockIdx.x*blockDim.x + threadIdx.x;
    if (i >= (size_t)G4*KC) return;
    int c = (int)(i % KC);
    int r = (int)(i / KC);
    float v = 0.f;
    if (r < 1024) {
        v = (c < 1012) ? Wih[(size_t)r*KD + c] : Whh[(size_t)r*GH + (c - 1012)];
    } else if (r < 1536) {
        if (c < 1012) v = Wih[(size_t)r*KD + c];
    } else {
        if (c >= 1012) v = Whh[(size_t)(r - 512)*GH + (c - 1012)];
    }
    Wc[i] = v;
}

// fp32 -> fp16 W conversion with K padding
__global__ void k_conv16(const float* __restrict__ W, __half* __restrict__ dst,
                         int N, int K, int Kp, int stride) {
    int vpr = Kp >> 3;
    size_t i = (size_t)blockIdx.x*blockDim.x + threadIdx.x;
    size_t total = (size_t)N * vpr;
    if (i >= total) return;
    int cg = (int)(i % vpr);
    int r = (int)(i / vpr);
    int c0 = cg*8;
    __half o[8];
    #pragma unroll
    for (int e = 0; e < 8; e++) {
        int kc = c0 + e;
        o[e] = (kc < K) ? __float2half(W[(size_t)r*stride + kc]) : __float2half(0.f);
    }
    *reinterpret_cast<uint4*>(dst + (size_t)r*Kp + c0) = *reinterpret_cast<uint4*>(o);
}

__global__ void k_h2din2(const float* __restrict__ h, float* __restrict__ din2,
                         __half* __restrict__ din16) {
    int i = blockIdx.x*blockDim.x + threadIdx.x;
    if (i >= B*GH) return;
    int b = i / GH, j = i % GH;
    float v = h[i];
    din2[(size_t)b*KC + 1012 + j] = v;
    split16(din16, (size_t)b*3072 + 1012 + j, 1536, v);
}

// ---------------- fp16 2-term prep for generic GEMM ----------------
__global__ void k_prep_h2A(const float* __restrict__ src, __half* __restrict__ dst,
                           int M, int Mp, int K, int Kp, int srcStride) {
    int vpr = (2*Kp) >> 3;
    size_t i = (size_t)blockIdx.x*blockDim.x + threadIdx.x;
    size_t total = (size_t)Mp * vpr;
    if (i >= total) return;
    int cg = (int)(i % vpr);
    int row = (int)(i / vpr);
    int c0 = cg*8;
    __half o[8];
    #pragma unroll
    for (int e = 0; e < 8; e++) {
        int c = c0 + e;
        int lo = (c >= Kp);
        int kc = lo ? (c - Kp) : c;
        __half v = __float2half(0.f);
        if (row < M && kc < K) {
            float x = src[(size_t)row*srcStride + kc];
            __half hh = __float2half(x);
            v = lo ? __float2half(x - __half2float(hh)) : hh;
        }
        o[e] = v;
    }
    *reinterpret_cast<uint4*>(dst + (size_t)row*(2*Kp) + c0) = *reinterpret_cast<uint4*>(o);
}

__global__ void k_prep_h2W(const float* __restrict__ W, __half* __restrict__ dst,
                           int N, int K, int Kp, int srcStride, int co) {
    int vpr = (2*Kp) >> 3;
    size_t i = (size_t)blockIdx.x*blockDim.x + threadIdx.x;
    size_t total = (size_t)N * vpr;
    if (i >= total) return;
    int cg = (int)(i % vpr);
    int r = (int)(i / vpr);
    int c0 = cg*8;
    __half o[8];
    #pragma unroll
    for (int e = 0; e < 8; e++) {
        int c = c0 + e;
        int kc = (c >= Kp) ? (c - Kp) : c;
        o[e] = (kc < K) ? __float2half(W[(size_t)r*srcStride + co + kc]) : __float2half(0.f);
    }
    *reinterpret_cast<uint4*>(dst + (size_t)r*(2*Kp) + c0) = *reinterpret_cast<uint4*>(o);
}

// ---------------- generic fp16 mma GEMM (batch prep): 128x128 tile ---------------
__global__ void __launch_bounds__(256) gemm_h16(
        const __half* __restrict__ A2, const __half* __restrict__ W2,
        const float* __restrict__ bias, float* __restrict__ C,
        int M, int N, int K2) {
    __shared__ __align__(16) char gsm[2*GSTAGE];
    const int tid = threadIdx.x;
    const int wid = tid >> 5, lane = tid & 31;
    const int m0 = blockIdx.x * 128, n0 = blockIdx.y * 128;
    const int wm = (wid >> 2) * 64, wn = (wid & 3) * 32;
    const int g = lane >> 2, tg = lane & 3;
    const uint32_t sb = smem_u32(gsm);

    float acc[4][4][4];
    #pragma unroll
    for (int i = 0; i < 4; i++)
    #pragma unroll
    for (int j = 0; j < 4; j++) { acc[i][j][0]=0.f; acc[i][j][1]=0.f; acc[i][j][2]=0.f; acc[i][j][3]=0.f; }

    auto load_stage = [&](int s, int k0) {
        uint32_t base = sb + (uint32_t)s*GSTAGE;
        #pragma unroll
        for (int i = 0; i < 4; i++) {
            int c = i*256 + tid;
            int isB = (c >= 512); int cc = c & 511;
            int row = cc >> 2, ch = cc & 3;
            uint32_t dst = base + (isB ? (uint32_t)(128*SSTRIDE*2) : 0u)
                         + (uint32_t)row*(SSTRIDE*2) + (uint32_t)ch*16u;
            const __half* src = isB ? (W2 + (size_t)(n0+row)*K2 + k0 + ch*8)
                                    : (A2 + (size_t)(m0+row)*K2 + k0 + ch*8);
            asm volatile("cp.async.cg.shared.global [%0], [%1], 16;" :: "r"(dst), "l"(src));
        }
        asm volatile("cp.async.commit_group;" ::: "memory");
    };

    load_stage(0, 0); load_stage(1, 32);

    const int a_row = lane & 15;
    const int a_k8  = (lane >> 4) << 3;
    const int b_row = lane & 7;
    const int b_k8  = ((lane >> 3) & 1) << 3;
    const int b_ni  = lane >> 4;

    const int NIT = K2/32;
    for (int kt = 0; kt < NIT; kt++) {
        if (kt + 2 < NIT) { asm volatile("cp.async.wait_group 1;" ::: "memory"); }
        else              { asm volatile("cp.async.wait_group 0;" ::: "memory"); }
        __syncthreads();
        int s = kt & 1;
        uint32_t baseA = sb + (uint32_t)s*GSTAGE;
        uint32_t baseB = baseA + (uint32_t)(128*SSTRIDE*2);
        #pragma unroll
        for (int kk = 0; kk < 2; kk++) {
            uint32_t afr[4][4];
            #pragma unroll
            for (int mi = 0; mi < 4; mi++) {
                uint32_t ad = baseA + ((uint32_t)(wm + mi*16 + a_row)*SSTRIDE
                                       + (uint32_t)(kk*16 + a_k8))*2u;
                asm volatile("ldmatrix.sync.aligned.m8n8.x4.shared.b16 {%0,%1,%2,%3}, [%4];"
                    : "=r"(afr[mi][0]),"=r"(afr[mi][1]),"=r"(afr[mi][2]),"=r"(afr[mi][3])
                    : "r"(ad));
            }
            uint32_t bfr[4][2];
            #pragma unroll
            for (int ni = 0; ni < 4; ni += 2) {
                uint32_t bd = baseB + ((uint32_t)(wn + (ni + b_ni)*8 + b_row)*SSTRIDE
                                       + (uint32_t)(kk*16 + b_k8))*2u;
                asm volatile("ldmatrix.sync.aligned.m8n8.x4.shared.b16 {%0,%1,%2,%3}, [%4];"
                    : "=r"(bfr[ni][0]),"=r"(bfr[ni][1]),"=r"(bfr[ni+1][0]),"=r"(bfr[ni+1][1])
                    : "r"(bd));
            }
            #pragma unroll
            for (int mi = 0; mi < 4; mi++)
            #pragma unroll
            for (int ni = 0; ni < 4; ni++) {
                asm volatile(
                  "mma.sync.aligned.m16n8k16.row.col.f32.f16.f16.f32 "
                  "{%0,%1,%2,%3},{%4,%5,%6,%7},{%8,%9},{%0,%1,%2,%3};"
                  : "+f"(acc[mi][ni][0]), "+f"(acc[mi][ni][1]),
                    "+f"(acc[mi][ni][2]), "+f"(acc[mi][ni][3])
                  : "r"(afr[mi][0]),"r"(afr[mi][1]),"r"(afr[mi][2]),"r"(afr[mi][3]),
                    "r"(bfr[ni][0]),"r"(bfr[ni][1]));
            }
        }
        __syncthreads();
        if (kt + 2 < NIT) load_stage(s, (kt+2)*32);
    }

    #pragma unroll
    for (int mi = 0; mi < 4; mi++) {
        int gm = m0 + wm + mi*16 + g;
        #pragma unroll
        for (int ni = 0; ni < 4; ni++) {
            int gn = n0 + wn + ni*8 + tg*2;
            float b0 = bias[gn], b1 = bias[gn+1];
            if (gm < M) {
                C[(size_t)gm*N + gn]     = acc[mi][ni][0] + b0;
                C[(size_t)gm*N + gn + 1] = acc[mi][ni][1] + b1;
            }
            if (gm + 8 < M) {
                C[(size_t)(gm+8)*N + gn]     = acc[mi][ni][2] + b0;
                C[(size_t)(gm+8)*N + gn + 1] = acc[mi][ni][3] + b1;
            }
        }
    }
}

// ---------------- split-K fp16 mma GEMM for recurrent steps -----------------------
// Cp[z][64][N] partials; A16[64][2*Kp]=[ah|al]; W16[N][Kp]; 64x128 tile, BK=32
__global__ void __launch_bounds__(256) gemm_h16_sk(
        const __half* __restrict__ A16, const __half* __restrict__ W16,
        float* __restrict__ Cp, int N, int Kp, int kchunk) {
    __shared__ __align__(16) char hsm[2*HSTAGE];
    const int tid = threadIdx.x;
    const int wid = tid >> 5, lane = tid & 31;
    const int n0 = blockIdx.x * 128;
    const int z = blockIdx.y;
    const int ks = z * kchunk;
    const int wm = (wid >> 2) * 32, wn = (wid & 3) * 32;
    const int g = lane >> 2, tg = lane & 3;
    const uint32_t sb = smem_u32(hsm);

    float acc[2][4][4];
    #pragma unroll
    for (int i = 0; i < 2; i++)
    #pragma unroll
    for (int j = 0; j < 4; j++) { acc[i][j][0]=0.f; acc[i][j][1]=0.f; acc[i][j][2]=0.f; acc[i][j][3]=0.f; }

    auto load_stage = [&](int s, int k0) {       // k0 is global K offset
        uint32_t base = sb + (uint32_t)s*HSTAGE;
        #pragma unroll
        for (int i = 0; i < 4; i++) {
            int c = i*256 + tid;                 // 0..1023: A0 256, A1 256, W 512
            uint32_t dst; const __half* src;
            if (c < 256) {
                int row = c >> 2, ch = c & 3;
                dst = base + (uint32_t)row*(SSTRIDE*2) + (uint32_t)ch*16u;
                src = A16 + (size_t)row*(2*Kp) + k0 + ch*8;
            } else if (c < 512) {
                int cc = c - 256; int row = cc >> 2, ch = cc & 3;
                dst = base + (uint32_t)(64*SSTRIDE*2) + (uint32_t)row*(SSTRIDE*2) + (uint32_t)ch*16u;
                src = A16 + (size_t)row*(2*Kp) + Kp + k0 + ch*8;
            } else {
                int cc = c - 512; int row = cc >> 2, ch = cc & 3;
                dst = base + (uint32_t)(128*SSTRIDE*2) + (uint32_t)row*(SSTRIDE*2) + (uint32_t)ch*16u;
                src = W16 + (size_t)(n0 + row)*Kp + k0 + ch*8;
            }
            asm volatile("cp.async.cg.shared.global [%0], [%1], 16;" :: "r"(dst), "l"(src));
        }
        asm volatile("cp.async.commit_group;" ::: "memory");
    };

    load_stage(0, ks); load_stage(1, ks + 32);

    const int a_row = lane & 15;
    const int a_k8  = (lane >> 4) << 3;
    const int b_row = lane & 7;
    const int b_k8  = ((lane >> 3) & 1) << 3;
    const int b_ni  = lane >> 4;

    const int NIT = kchunk/32;
    for (int kt = 0; kt < NIT; kt++) {
        if (kt + 2 < NIT) { asm volatile("cp.async.wait_group 1;" ::: "memory"); }
        else              { asm volatile("cp.async.wait_group 0;" ::: "memory"); }
        __syncthreads();
        int s = kt & 1;
        uint32_t baseA0 = sb + (uint32_t)s*HSTAGE;
        uint32_t baseA1 = baseA0 + (uint32_t)(64*SSTRIDE*2);
        uint32_t baseW  = baseA0 + (uint32_t)(128*SSTRIDE*2);
        #pragma unroll
        for (int kk = 0; kk < 2; kk++) {
            uint32_t bfr[4][2];
            #pragma unroll
            for (int ni = 0; ni < 4; ni += 2) {
                uint32_t bd = baseW + ((uint32_t)(wn + (ni + b_ni)*8 + b_row)*SSTRIDE
                                       + (uint32_t)(kk*16 + b_k8))*2u;
                asm volatile("ldmatrix.sync.aligned.m8n8.x4.shared.b16 {%0,%1,%2,%3}, [%4];"
                    : "=r"(bfr[ni][0]),"=r"(bfr[ni][1]),"=r"(bfr[ni+1][0]),"=r"(bfr[ni+1][1])
                    : "r"(bd));
            }
            #pragma unroll
            for (int half = 0; half < 2; half++) {
                uint32_t baseA = half ? baseA1 : baseA0;
                uint32_t afr[2][4];
                #pragma unroll
                for (int mi = 0; mi < 2; mi++) {
                    uint32_t ad = baseA + ((uint32_t)(wm + mi*16 + a_row)*SSTRIDE
                                           + (uint32_t)(kk*16 + a_k8))*2u;
                    asm volatile("ldmatrix.sync.aligned.m8n8.x4.shared.b16 {%0,%1,%2,%3}, [%4];"
                        : "=r"(afr[mi][0]),"=r"(afr[mi][1]),"=r"(afr[mi][2]),"=r"(afr[mi][3])
                        : "r"(ad));
                }
                #pragma unroll
                for (int mi = 0; mi < 2; mi++)
                #pragma unroll
                for (int ni = 0; ni < 4; ni++) {
                    asm volatile(
                      "mma.sync.aligned.m16n8k16.row.col.f32.f16.f16.f32 "
                      "{%0,%1,%2,%3},{%4,%5,%6,%7},{%8,%9},{%0,%1,%2,%3};"
                      : "+f"(acc[mi][ni][0]), "+f"(acc[mi][ni][1]),
                        "+f"(acc[mi][ni][2]), "+f"(acc[mi][ni][3])
                      : "r"(afr[mi][0]),"r"(afr[mi][1]),"r"(afr[mi][2]),"r"(afr[mi][3]),
                        "r"(bfr[ni][0]),"r"(bfr[ni][1]));
                }
            }
        }
        __syncthreads();
        if (kt + 2 < NIT) load_stage(s, ks + (kt+2)*32);
    }

    float* Cz = Cp + (size_t)z*64*N;
    #pragma unroll
    for (int mi = 0; mi < 2; mi++) {
        int gm = wm + mi*16 + g;
        #pragma unroll
        for (int ni = 0; ni < 4; ni++) {
            int gn = n0 + wn + ni*8 + tg*2;
            Cz[(size_t)gm*N + gn]         = acc[mi][ni][0];
            Cz[(size_t)gm*N + gn + 1]     = acc[mi][ni][1];
            Cz[(size_t)(gm+8)*N + gn]     = acc[mi][ni][2];
            Cz[(size_t)(gm+8)*N + gn + 1] = acc[mi][ni][3];
        }
    }
}

// ---------------- encoder step gates ----------------
__global__ void enc_gates(const float* __restrict__ gxe, const float* __restrict__ ghp,
                          const float* __restrict__ bhh, float* __restrict__ h,
                          __half* __restrict__ h16,
                          float* __restrict__ po, const int* __restrict__ post_length, int t) {
    int idx = blockIdx.x*blockDim.x + threadIdx.x;
    if (idx >= B*GH) return;
    int b = idx / GH, j = idx % GH;
    const float* gx = gxe + ((size_t)b*PL + t)*G3;
    float ghr = bhh[j], ghz = bhh[GH+j], ghn = bhh[2*GH+j];
    #pragma unroll
    for (int s = 0; s < 4; s++) {
        const float* p = ghp + ((size_t)s*B + b)*G3;
        ghr += p[j]; ghz += p[GH+j]; ghn += p[2*GH+j];
    }
    float r = sigmoidf_(gx[j] + ghr);
    float z = sigmoidf_(gx[GH+j] + ghz);
    float n = tanhf(gx[2*GH+j] + r*ghn);
    float hold = h[idx];
    float hn = (1.f - z)*n + z*hold;
    bool valid = t < post_length[b];
    float hv = valid ? hn : hold;
    h[idx] = hv;
    split16(h16, (size_t)b*1024 + j, 512, hv);
    po[((size_t)b*PL + t)*GH + j] = valid ? hn : 0.f;
}

// ---------------- decoder: prev-gates + attention + misc ----------------
__global__ void __launch_bounds__(256) dec_am(
        float* __restrict__ din2, __half* __restrict__ din16,
        const float* __restrict__ po,
        const float* __restrict__ cp, const float* __restrict__ gxrv_prev,
        const float* __restrict__ bhh,
        const float* __restrict__ wb_w, const float* __restrict__ wb_b,
        const float* __restrict__ wc_w, const float* __restrict__ wc_b,
        const float* __restrict__ vb_w, const float* __restrict__ vb_b,
        const float* __restrict__ ubg, const float* __restrict__ sg,
        float* __restrict__ q, float* __restrict__ da,
        float* __restrict__ Z, int t, int do_gates) {
    int b = blockIdx.x, tid = threadIdx.x;
    int lane = tid & 31, wid = tid >> 5;
    __shared__ float hs[GH];
    __shared__ float sc2[256];
    __shared__ float sc[PL];
    __shared__ float al[PL];
    __shared__ float wbh[HID];
    __shared__ float dls[NT];
    __shared__ float das[NT];
    if (do_gates) {
        #pragma unroll
        for (int jj = 0; jj < 2; jj++) {
            int j = jj*256 + tid;
            float cr = 0.f, cz = 0.f, cxn = 0.f, chn = 0.f;
            #pragma unroll
            for (int z = 0; z < 8; z++) {
                const float* p = cp + ((size_t)z*B + b)*G4;
                cr += p[j]; cz += p[512+j]; cxn += p[1024+j]; chn += p[1536+j];
            }
            const float* gr = gxrv_prev + (size_t)b*G3;
            float r  = sigmoidf_(cr + gr[j] + bhh[j]);
            float zz = sigmoidf_(cz + gr[GH+j] + bhh[GH+j]);
            float n  = tanhf(cxn + gr[2*GH+j] + r*(chn + bhh[2*GH+j]));
            float hold = din2[(size_t)b*KC + 1012 + j];
            float hn = (1.f - zz)*n + zz*hold;
            din2[(size_t)b*KC + 1012 + j] = hn;
            split16(din16, (size_t)b*3072 + 1012 + j, 1536, hn);
            Z[((size_t)(t-1)*B + b)*KD + j] = hn;
            hs[j] = hn;
        }
        __syncthreads();
    } else {
        for (int i = tid; i < GH; i += 256) hs[i] = din2[(size_t)b*KC + 1012 + i];
        __syncthreads();
    }
    {
        int p = tid >> 1, hf = tid & 1;
        const float* row = po + ((size_t)b*PL + p)*GH + hf*256;
        const float* h2 = hs + hf*256;
        float s = 0.f;
        for (int k = 0; k < 256; k += 4) {
            float4 v = *reinterpret_cast<const float4*>(row + k);
            s += v.x*h2[k] + v.y*h2[k+1] + v.z*h2[k+2] + v.w*h2[k+3];
        }
        sc2[tid] = s;
    }
    __syncthreads();
    if (tid < PL) sc[tid] = sc2[2*tid] + sc2[2*tid+1];
    __syncthreads();
    for (int j = tid; j < 400; j += 256) {
        const float* w;
        float acc;
        if (j < 300) { acc = wc_b[j]; w = wc_w + (size_t)j*GH; }
        else         { acc = wb_b[j-300]; w = wb_w + (size_t)(j-300)*GH; }
        for (int k = 0; k < GH; k += 4) {
            float4 v = *reinterpret_cast<const float4*>(w + k);
            acc += v.x*hs[k] + v.y*hs[k+1] + v.z*hs[k+2] + v.w*hs[k+3];
        }
        if (j < 300) q[(size_t)b*300 + j] = acc;
        else wbh[j-300] = acc;
    }
    if (wid == 0) {
        float v0 = sc[lane], v1 = sc[lane+32], v2 = sc[lane+64], v3 = sc[lane+96];
        float m = fmaxf(fmaxf(v0, v1), fmaxf(v2, v3));
        for (int o = 16; o; o >>= 1) m = fmaxf(m, __shfl_xor_sync(0xffffffffu, m, o));
        float e0 = expf(v0-m), e1 = expf(v1-m), e2 = expf(v2-m), e3 = expf(v3-m);
        float s = e0+e1+e2+e3;
        for (int o = 16; o; o >>= 1) s += __shfl_xor_sync(0xffffffffu, s, o);
        float inv = 1.f/s;
        al[lane] = e0*inv; al[lane+32] = e1*inv; al[lane+64] = e2*inv; al[lane+96] = e3*inv;
    }
    __syncthreads();
    for (int d = tid; d < GH; d += 256) {
        float acc = 0.f;
        for (int p = 0; p < PL; p++) acc += al[p]*po[((size_t)b*PL + p)*GH + d];
        din2[(size_t)b*KC + d] = acc;
        split16(din16, (size_t)b*3072 + d, 1536, acc);
    }
    if (tid < NT) {
        float s = 0.f;
        const float* u = ubg + ((size_t)b*NT + tid)*HID;
        for (int j = 0; j < HID; j++) s += vb_w[j]*tanhf(wbh[j] + u[j]);
        dls[tid] = s + vb_b[0];
    }
    __syncthreads();
    if (wid == 0) {
        float a0 = (lane < NT) ? dls[lane] : -1e30f;
        float a1 = (lane+32 < NT) ? dls[lane+32] : -1e30f;
        float m = fmaxf(a0, a1);
        for (int o = 16; o; o >>= 1) m = fmaxf(m, __shfl_xor_sync(0xffffffffu, m, o));
        float e0 = (lane < NT) ? expf(a0-m) : 0.f;
        float e1 = (lane+32 < NT) ? expf(a1-m) : 0.f;
        float s = e0 + e1;
        for (int o = 16; o; o >>= 1) s += __shfl_xor_sync(0xffffffffu, s, o);
        float inv = 1.f/s;
        if (lane < NT)    { das[lane] = e0*inv;    da[(size_t)b*NT + lane] = e0*inv; }
        if (lane+32 < NT) { das[lane+32] = e1*inv; da[(size_t)b*NT + lane+32] = e1*inv; }
    }
    __syncthreads();
    float* zrow = Z + ((size_t)t*B + b)*KD;
    for (int d = tid; d < 200; d += 256) {
        float s = 0.f;
        for (int n = 0; n < NT; n++) s += das[n]*sg[((size_t)b*NT + n)*200 + d];
        din2[(size_t)b*KC + 512 + d] = s;
        split16(din16, (size_t)b*3072 + 512 + d, 1536, s);
        zrow[512 + d] = s;
    }
}

// ---------------- triple attention ----------------
__global__ void __launch_bounds__(256) dec_tv_part(
        const __half* __restrict__ tef16, const float* __restrict__ q,
        const float* __restrict__ da, float* __restrict__ tvp) {
    int b = blockIdx.x, ch = blockIdx.y;
    int tid = threadIdx.x, lane = tid & 31, wid = tid >> 5;
    __shared__ float qs[300];
    __shared__ float sw[10*NP];
    __shared__ float dal[10];
    for (int i = tid; i < 300; i += 256) qs[i] = q[(size_t)b*300 + i];
    if (tid < 10) dal[tid] = da[(size_t)b*NT + ch*10 + tid];
    __syncthreads();
    const __half* tb = tef16 + ((size_t)b*NT + ch*10)*NP*300;
    #pragma unroll
    for (int it = 0; it < 25; it++) {
        int pair = wid + 8*it;
        const __half* row = tb + (size_t)pair*300;
        float s = 0.f;
        for (int k2 = lane; k2 < 150; k2 += 32) {
            __half2 hv = *reinterpret_cast<const __half2*>(row + 2*k2);
            float2 fv = __half22float2(hv);
            s += fv.x*qs[2*k2] + fv.y*qs[2*k2+1];
        }
        #pragma unroll
        for (int o = 16; o; o >>= 1) s += __shfl_down_sync(0xffffffffu, s, o);
        if (lane == 0) sw[pair] = s;
    }
    __syncthreads();
    for (int n = wid; n < 10; n += 8) {
        float v = (lane < NP) ? sw[n*NP + lane] : -1e30f;
        float m = v;
        for (int o = 16; o; o >>= 1) m = fmaxf(m, __shfl_xor_sync(0xffffffffu, m, o));
        float e = (lane < NP) ? expf(v - m) : 0.f;
        float su = e;
        for (int o = 16; o; o >>= 1) su += __shfl_xor_sync(0xffffffffu, su, o);
        if (lane < NP) sw[n*NP + lane] = e * dal[n] / su;
    }
    __syncthreads();
    for (int d = tid; d < 300; d += 256) {
        float acc = 0.f;
        #pragma unroll 8
        for (int r = 0; r < 200; r++) acc += sw[r]*__half2float(tb[(size_t)r*300 + d]);
        tvp[((size_t)b*NCH + ch)*300 + d] = acc;
    }
}

__global__ void dec_tvsum(const float* __restrict__ tvp, float* __restrict__ din2,
                          __half* __restrict__ din16, float* __restrict__ Z, int t) {
    int b = blockIdx.x, d = threadIdx.x;
    float s = 0.f;
    #pragma unroll
    for (int ch = 0; ch < NCH; ch++) s += tvp[((size_t)b*NCH + ch)*300 + d];
    din2[(size_t)b*KC + 712 + d] = s;
    split16(din16, (size_t)b*3072 + 712 + d, 1536, s);
    Z[((size_t)t*B + b)*KD + 712 + d] = s;
}

// final gates for last decoder step (only Z matters afterward)
__global__ void dec_gates2(const float* __restrict__ cp, const float* __restrict__ gxrv_t,
                           const float* __restrict__ bhh, float* __restrict__ din2,
                           float* __restrict__ Z, int t) {
    int idx = blockIdx.x*blockDim.x + threadIdx.x;
    if (idx >= B*GH) return;
    int b = idx / GH, j = idx % GH;
    float cr = 0.f, cz = 0.f, cxn = 0.f, chn = 0.f;
    #pragma unroll
    for (int z = 0; z < 8; z++) {
        const float* p = cp + ((size_t)z*B + b)*G4;
        cr += p[j]; cz += p[512+j]; cxn += p[1024+j]; chn += p[1536+j];
    }
    const float* gr = gxrv_t + (size_t)b*G3;
    float r  = sigmoidf_(cr + gr[j] + bhh[j]);
    float zz = sigmoidf_(cz + gr[GH+j] + bhh[GH+j]);
    float n  = tanhf(cxn + gr[2*GH+j] + r*(chn + bhh[2*GH+j]));
    float hold = din2[(size_t)b*KC + 1012 + j];
    float hn = (1.f - zz)*n + zz*hold;
    din2[(size_t)b*KC + 1012 + j] = hn;
    Z[((size_t)t*B + b)*KD + j] = hn;
}

// ---------------- fp16 split prep (vocab) ----------------
__global__ void k_split_W(const float* __restrict__ W, __half* __restrict__ Ws) {
    size_t i = (size_t)blockIdx.x*blockDim.x + threadIdx.x;
    size_t total = (size_t)VW*(KW/8);
    if (i >= total) return;
    int cg = (int)(i % (KW/8));
    size_t r = i / (KW/8);
    int c0 = cg*8;
    __half o[8];
    #pragma unroll
    for (int e = 0; e < 8; e++) {
        int c = c0 + e;
        o[e] = (c < KSEG) ? __float2half(W[r*KSEG + c]) : __float2half(0.f);
    }
    *reinterpret_cast<uint4*>(Ws + r*KW + c0) = *reinterpret_cast<uint4*>(o);
}

__global__ void k_split_Z(const float* __restrict__ Z, __half* __restrict__ As_) {
    size_t i = (size_t)blockIdx.x*blockDim.x + threadIdx.x;
    size_t total = (size_t)MP*(KPA/8);
    if (i >= total) return;
    int cg = (int)(i % (KPA/8));
    int m = (int)(i / (KPA/8));
    int b = m / TDEC, t = m - b*TDEC;
    int c0 = cg*8;
    __half o[8];
    #pragma unroll
    for (int e = 0; e < 8; e++) {
        int c = c0 + e;
        int lo = (c >= KW);
        int kc = lo ? (c - KW) : c;
        __half v = __float2half(0.f);
        if (b < B && kc < KSEG) {
            float zv = Z[((size_t)t*B + b)*KD + kc];
            __half hh = __float2half(zv);
            if (lo) v = __float2half(zv - __half2float(hh));
            else v = hh;
        }
        o[e] = v;
    }
    *reinterpret_cast<uint4*>(As_ + (size_t)m*KPA + c0) = *reinterpret_cast<uint4*>(o);
}

// ---------------- mma.sync fp16 vocab GEMM: 256x128 tile, B deduped, 3-stage --------
__global__ void __launch_bounds__(256) vocab_mma(
        const __half* __restrict__ Ag, const __half* __restrict__ Wg,
        const float* __restrict__ bout, float* __restrict__ out) {
    extern __shared__ __align__(16) char sraw[];
    const int tid = threadIdx.x;
    const int wid = tid >> 5, lane = tid & 31;
    const int m0 = blockIdx.x * VTM, n0 = blockIdx.y * VTN;
    const int wm = (wid >> 1) * 64, wn = (wid & 1) * 64;
    const int g = lane >> 2, tg = lane & 3;
    const uint32_t sb = smem_u32(sraw);

    float acc[4][8][4];
    #pragma unroll
    for (int i = 0; i < 4; i++)
    #pragma unroll
    for (int j = 0; j < 8; j++) { acc[i][j][0]=0.f; acc[i][j][1]=0.f; acc[i][j][2]=0.f; acc[i][j][3]=0.f; }

    auto load_stage = [&](int s, int k0) {
        uint32_t base = sb + (uint32_t)s*VSTAGE;
        #pragma unroll
        for (int i = 0; i < 10; i++) {
            int c = i*256 + tid;
            uint32_t roff; const __half* src;
            if (c < 1024) {
                int row = c >> 2, ch = c & 3;
                roff = (uint32_t)row*(SSTRIDE*2) + (uint32_t)ch*16u;
                src = Ag + (size_t)(m0+row)*KPA + k0 + ch*8;
            } else if (c < 2048) {
                int cc = c - 1024; int row = cc >> 2, ch = cc & 3;
                roff = VA_HALF + (uint32_t)row*(SSTRIDE*2) + (uint32_t)ch*16u;
                src = Ag + (size_t)(m0+row)*KPA + KW + k0 + ch*8;
            } else {
                int cc = c - 2048; int row = cc >> 2, ch = cc & 3;
                roff = 2*VA_HALF + (uint32_t)row*(SSTRIDE*2) + (uint32_t)ch*16u;
                src = Wg + (size_t)(n0+row)*KW + k0 + ch*8;
            }
            asm volatile("cp.async.cg.shared.global [%0], [%1], 16;" :: "r"(base + roff), "l"(src));
        }
        asm volatile("cp.async.commit_group;" ::: "memory");
    };

    load_stage(0, 0); load_stage(1, 32); load_stage(2, 64);

    const int a_row = lane & 15;
    const int a_k8  = (lane >> 4) << 3;
    const int b_row = lane & 7;
    const int b_k8  = ((lane >> 3) & 1) << 3;
    const int b_ni  = lane >> 4;

    const int NIT = KW/32;
    for (int kt = 0; kt < NIT; kt++) {
        if (kt + 3 < NIT) { asm volatile("cp.async.wait_group 2;" ::: "memory"); }
        else              { asm volatile("cp.async.wait_group 0;" ::: "memory"); }
        __syncthreads();
        int s = kt % 3;
        uint32_t baseA0 = sb + (uint32_t)s*VSTAGE;
        uint32_t baseB  = baseA0 + 2*VA_HALF;
        #pragma unroll
        for (int kk = 0; kk < 2; kk++) {
            uint32_t bfr[8][2];
            #pragma unroll
            for (int ni = 0; ni < 8; ni += 2) {
                uint32_t bd = baseB + ((uint32_t)(wn + (ni + b_ni)*8 + b_row)*SSTRIDE
                                       + (uint32_t)(kk*16 + b_k8))*2u;
                asm volatile("ldmatrix.sync.aligned.m8n8.x4.shared.b16 {%0,%1,%2,%3}, [%4];"
                    : "=r"(bfr[ni][0]),"=r"(bfr[ni][1]),"=r"(bfr[ni+1][0]),"=r"(bfr[ni+1][1])
                    : "r"(bd));
            }
            #pragma unroll
            for (int half = 0; half < 2; half++) {
                uint32_t baseA = baseA0 + (uint32_t)half*VA_HALF;
                uint32_t afr[4][4];
                #pragma unroll
                for (int mi = 0; mi < 4; mi++) {
                    uint32_t ad = baseA + ((uint32_t)(wm + mi*16 + a_row)*SSTRIDE
                                           + (uint32_t)(kk*16 + a_k8))*2u;
                    asm volatile("ldmatrix.sync.aligned.m8n8.x4.shared.b16 {%0,%1,%2,%3}, [%4];"
                        : "=r"(afr[mi][0]),"=r"(afr[mi][1]),"=r"(afr[mi][2]),"=r"(afr[mi][3])
                        : "r"(ad));
                }
                #pragma unroll
                for (int mi = 0; mi < 4; mi++)
                #pragma unroll
                for (int ni = 0; ni < 8; ni++) {
                    asm volatile(
                      "mma.sync.aligned.m16n8k16.row.col.f32.f16.f16.f32 "
                      "{%0,%1,%2,%3},{%4,%5,%6,%7},{%8,%9},{%0,%1,%2,%3};"
                      : "+f"(acc[mi][ni][0]), "+f"(acc[mi][ni][1]),
                        "+f"(acc[mi][ni][2]), "+f"(acc[mi][ni][3])
                      : "r"(afr[mi][0]),"r"(afr[mi][1]),"r"(afr[mi][2]),"r"(afr[mi][3]),
                        "r"(bfr[ni][0]),"r"(bfr[ni][1]));
                }
            }
        }
        __syncthreads();
        if (kt + 3 < NIT) load_stage(s, (kt+3)*32);
    }
    __syncthreads();

    float* Ds = (float*)sraw;
    #pragma unroll
    for (int h = 0; h < 2; h++) {
        if ((wid >> 2) == h) {
            int mbase = wm - h*128;
            #pragma unroll
            for (int mi = 0; mi < 4; mi++) {
                int mA = mbase + mi*16 + g;
                #pragma unroll
                for (int ni = 0; ni < 8; ni++) {
                    int nn = wn + ni*8 + tg*2;
                    Ds[mA*129 + nn]         = acc[mi][ni][0];
                    Ds[mA*129 + nn + 1]     = acc[mi][ni][1];
                    Ds[(mA+8)*129 + nn]     = acc[mi][ni][2];
                    Ds[(mA+8)*129 + nn + 1] = acc[mi][ni][3];
                }
            }
        }
        __syncthreads();
        for (int idx = tid; idx < VTN*128; idx += 256) {
            int n = idx >> 7, m = idx & 127;
            int mg = m0 + h*128 + m;
            if (mg < B*TDEC) {
                int bb = mg / TDEC, tt = mg - bb*TDEC;
                int ng = n0 + n;
                out[(size_t)bb*VW*TDEC + (size_t)ng*TDEC + tt] = Ds[m*129 + n] + __ldg(bout + ng);
            }
        }
        __syncthreads();
    }
}

// ---------------- launch ----------------
extern "C" void kernel_launch(void* const* d_in, const int* in_sizes, int n_in,
                              void* d_out, int out_size) {
    const float* word_emb   = (const float*)d_in[0];
    const float* transe_emb = (const float*)d_in[1];
    const float* wh_w = (const float*)d_in[2];  const float* wh_b = (const float*)d_in[3];
    const float* wr_w = (const float*)d_in[4];  const float* wr_b = (const float*)d_in[5];
    const float* wt_w = (const float*)d_in[6];  const float* wt_b = (const float*)d_in[7];
    const float* wb_w = (const float*)d_in[8];  const float* wb_b = (const float*)d_in[9];
    const float* ub_w = (const float*)d_in[10]; const float* ub_b = (const float*)d_in[11];
    const float* vb_w = (const float*)d_in[12]; const float* vb_b = (const float*)d_in[13];
    const float* wc_w = (const float*)d_in[14]; const float* wc_b = (const float*)d_in[15];
    const float* Wih_e = (const float*)d_in[16]; const float* Whh_e = (const float*)d_in[17];
    const float* bih_e = (const float*)d_in[18]; const float* bhh_e = (const float*)d_in[19];
    const float* Wih_d = (const float*)d_in[20]; const float* Whh_d = (const float*)d_in[21];
    const float* bih_d = (const float*)d_in[22]; const float* bhh_d = (const float*)d_in[23];
    const float* out_w = (const float*)d_in[24]; const float* out_b = (const float*)d_in[25];
    const int* post          = (const int*)d_in[26];
    const int* post_length   = (const int*)d_in[27];
    const int* response      = (const int*)d_in[28];
    const int* resp_triple   = (const int*)d_in[29];
    const int* post_triple   = (const int*)d_in[30];
    const int* triple        = (const int*)d_in[31];
    float* out = (float*)d_out;

    void* basep = nullptr; cudaGetSymbolAddress(&basep, g_buf);
    float* base = (float*)basep;
    void* wsp = nullptr; cudaGetSymbolAddress(&wsp, g_Ws);
    void* asp = nullptr; cudaGetSymbolAddress(&asp, g_As);
    void* w2p = nullptr; cudaGetSymbolAddress(&w2p, g_W2);
    void* t16p = nullptr; cudaGetSymbolAddress(&t16p, g_tef16);
    void* h16p = nullptr; cudaGetSymbolAddress(&h16p, g_h16);
    void* d16p = nullptr; cudaGetSymbolAddress(&d16p, g_din16);
    void* whe16p = nullptr; cudaGetSymbolAddress(&whe16p, g_Whe16);
    void* wcb16p = nullptr; cudaGetSymbolAddress(&wcb16p, g_Wcb16);
    __half* Ws = (__half*)wsp;
    __half* As = (__half*)asp;
    __half* W2 = (__half*)w2p;
    __half* tef16 = (__half*)t16p;
    __half* h16 = (__half*)h16p;
    __half* din16 = (__half*)d16p;
    __half* Whe16 = (__half*)whe16p;
    __half* Wcb16 = (__half*)wcb16p;

    float* tef  = base + OFF_TEF;
    float* sl   = base + OFF_SL;
    float* sg   = base + OFF_SG;
    float* ubg  = base + OFF_UBG;
    float* pin  = base + OFF_PIN;
    float* gxe  = base + OFF_GXE;
    float* po   = base + OFF_PO;
    float* h    = base + OFF_H;
    float* rv   = base + OFF_RV;
    float* Z    = base + OFF_Z;
    float* din2 = base + OFF_DIN2;
    float* q    = base + OFF_Q;
    float* da   = base + OFF_DA;
    float* cp   = base + OFF_CP;
    float* ghp  = base + OFF_GHP;
    float* gxrv = base + OFF_GXRV;
    float* Wcb  = base + OFF_WCB;
    float* tvp  = base + OFF_TVP;

    cudaFuncSetAttribute(vocab_mma, cudaFuncAttributeMaxDynamicSharedMemorySize, VSMEM);

    // ---- phase A ----
    k_zero<<<(unsigned)((SZ_H + 255)/256), 256>>>(h, SZ_H);
    k_zeroh<<<(unsigned)((B*1024 + 255)/256), 256>>>(h16, (size_t)B*1024);
    k_zeroh<<<(unsigned)((B*3072 + 255)/256), 256>>>(din16, (size_t)B*3072);
    {
        size_t n4 = (size_t)B*NT*NP*3*25;
        k_gather_tef<<<(unsigned)((n4 + 255)/256), 256>>>(transe_emb, triple, tef, tef16);
    }
    {
        size_t n4 = (size_t)TDEC*B*150;
        k_gather_rv<<<(unsigned)((n4 + 255)/256), 256>>>(word_emb, transe_emb, response, resp_triple, rv, Z);
    }
    {
        size_t nsp = (size_t)VW*(KW/8);
        k_split_W<<<(unsigned)((nsp + 255)/256), 256>>>(out_w, Ws);
    }
    {
        size_t n = (size_t)G4*KC;
        k_build_wcomb<<<(unsigned)((n + 255)/256), 256>>>(Wih_d, Whh_d, Wcb);
    }
    {
        size_t n = (size_t)G3*(512/8);
        k_conv16<<<(unsigned)((n + 255)/256), 256>>>(Whh_e, Whe16, G3, 512, 512, GH);
    }
    {
        size_t n = (size_t)G4*(1536/8);
        k_conv16<<<(unsigned)((n + 255)/256), 256>>>(Wcb, Wcb16, G4, KC, 1536, KC);
    }
    k_triple_score<<<B*NT*NP, 128>>>(tef, triple, wh_w, wh_b, wr_w, wr_b, wt_w, wt_b, sl);
    k_graph_softmax<<<B*NT, 64>>>(sl, tef, sg);
    k_ubg<<<B*NT, 128>>>(sg, ub_w, ub_b, ubg);
    {
        size_t n4 = (size_t)B*PL*125;
        k_post_in<<<(unsigned)((n4 + 255)/256), 256>>>(word_emb, sg, post, post_triple, pin);
    }
    // gxe = pin @ Wih_e^T + bih_e (fp16 2-term split mma)
    {
        size_t nA = (size_t)(B*PL) * (1024/8);
        k_prep_h2A<<<(unsigned)((nA + 255)/256), 256>>>(pin, As, B*PL, B*PL, KE, 512, KE);
        size_t nW = (size_t)G3 * (1024/8);
        k_prep_h2W<<<(unsigned)((nW + 255)/256), 256>>>(Wih_e, W2, G3, KE, 512, KE, 0);
        gemm_h16<<<dim3((B*PL)/128, G3/128), 256>>>(As, W2, bih_e, gxe, B*PL, G3, 1024);
    }
    // gxrv = rv @ Wih_d[:,1012:]^T + bih_d
    {
        size_t nA = (size_t)4096 * (1216/8);
        k_prep_h2A<<<(unsigned)((nA + 255)/256), 256>>>(rv, As, TDEC*B, 4096, 600, 608, 600);
        size_t nW = (size_t)G3 * (1216/8);
        k_prep_h2W<<<(unsigned)((nW + 255)/256), 256>>>(Wih_d, W2, G3, 600, 608, KD, 1012);
        gemm_h16<<<dim3(4096/128, G3/128), 256>>>(As, W2, bih_d, gxrv, TDEC*B, G3, 1216);
    }

    // ---- phase B: encoder recurrence (fp16 mma split-K) ----
    for (int t = 0; t < PL; t++) {
        gemm_h16_sk<<<dim3(G3/128, 4), 256>>>(h16, Whe16, ghp, G3, 512, 128);
        enc_gates<<<(B*GH)/256, 256>>>(gxe, ghp, bhh_e, h, h16, po, post_length, t);
    }
    k_h2din2<<<(B*GH)/256, 256>>>(h, din2, din16);

    // ---- phase C: decoder recurrence (fp16 mma split-K) ----
    for (int t = 0; t < TDEC; t++) {
        const float* gxrv_prev = (t > 0) ? (gxrv + (size_t)(t-1)*B*G3) : gxrv;
        dec_am<<<B, 256>>>(din2, din16, po, cp, gxrv_prev, bhh_d,
                           wb_w, wb_b, wc_w, wc_b, vb_w, vb_b,
                           ubg, sg, q, da, Z, t, t > 0 ? 1 : 0);
        dec_tv_part<<<dim3(B, NCH), 256>>>(tef16, q, da, tvp);
        dec_tvsum<<<B, 300>>>(tvp, din2, din16, Z, t);
        gemm_h16_sk<<<dim3(G4/128, 8), 256>>>(din16, Wcb16, cp, G4, 1536, 192);
    }
    dec_gates2<<<(B*GH)/256, 256>>>(cp, gxrv + (size_t)(TDEC-1)*B*G3, bhh_d, din2, Z, TDEC-1);

    // ---- phase D: split Z + vocab projection ----
    {
        size_t nsp = (size_t)MP*(KPA/8);
        k_split_Z<<<(unsigned)((nsp + 255)/256), 256>>>(Z, As);
    }
    vocab_mma<<<dim3(MP/VTM, VW/VTN), 256, VSMEM>>>(As, Ws, out_b, out);
}